// round 1
// baseline (speedup 1.0000x reference)
#include <cuda_runtime.h>

// ---------------- problem constants ----------------
#define Nn 10000
#define Ee 160000
#define Tt 32
#define Hh 256
#define NFd 192            // T*6
#define TTEACH 24

// ---------------- device scratch (no allocations allowed) ----------------
static __device__ float g_h[Nn * Hh];            // hidden state
static __device__ float g_prev[Nn * 6];          // previous mu
static __device__ float g_fh[Nn * NFd];          // relu(h@Wf+bf)
static __device__ float g_AB[Nn * 1536];         // [A(768) | B(768)] per node
static __device__ float g_macc[Nn * Hh];         // message accumulator (scatter sum)
static __device__ float g_gh[Nn * 768];          // m @ Whh^T + bhh
static __device__ float g_W1ab[192 * 1536];      // packed [W1a | W1b]
static __device__ float g_biasab[1536];          // [b1 | 0]
static __device__ float g_WhhT[256 * 768];       // Whh transposed
static __device__ float g_invcnt[Nn];
static __device__ int   g_deg[Nn];
static __device__ int   g_src[Ee];
static __device__ int   g_dst[Ee];
static __device__ int   g_is32;                  // edge_index dtype flag

// ---------------- f32x2 packed-FMA helpers (Blackwell) ----------------
__device__ __forceinline__ unsigned long long f2pack(float lo, float hi) {
    unsigned long long r;
    asm("mov.b64 %0, {%1, %2};" : "=l"(r) : "f"(lo), "f"(hi));
    return r;
}
__device__ __forceinline__ unsigned long long f2dup(float v) {
    unsigned long long r;
    asm("mov.b64 %0, {%1, %1};" : "=l"(r) : "f"(v));
    return r;
}
__device__ __forceinline__ unsigned long long f2fma(unsigned long long a,
                                                    unsigned long long b,
                                                    unsigned long long c) {
    unsigned long long d;
    asm("fma.rn.f32x2 %0, %1, %2, %3;" : "=l"(d) : "l"(a), "l"(b), "l"(c));
    return d;
}
__device__ __forceinline__ void f2unpack(unsigned long long v, float& lo, float& hi) {
    asm("mov.b64 {%0, %1}, %2;" : "=f"(lo), "=f"(hi) : "l"(v));
}

// ---------------- setup kernels ----------------
__global__ void k_init() {
    int i = blockIdx.x * blockDim.x + threadIdx.x;
    int st = gridDim.x * blockDim.x;
    for (int j = i; j < Nn * Hh; j += st) { g_h[j] = 0.f; g_macc[j] = 0.f; }
    for (int j = i; j < Nn * 6; j += st) g_prev[j] = 0.f;
    for (int j = i; j < Nn; j += st) g_deg[j] = 0;
    if (i == 0) g_is32 = 0;
}

// If edge_index is int64 (values < 10000, nonneg) every odd 32-bit word of the
// first 2E words is zero. If it's int32, the odd words are random indices.
__global__ void k_detect(const int* __restrict__ w) {
    int i = blockIdx.x * blockDim.x + threadIdx.x;
    int st = gridDim.x * blockDim.x;
    for (int j = i; j < 2 * Ee; j += st) {
        if ((j & 1) && w[j] != 0) g_is32 = 1;
    }
}

__global__ void k_extract(const void* __restrict__ eiraw) {
    int e = blockIdx.x * blockDim.x + threadIdx.x;
    if (e >= Ee) return;
    if (g_is32) {
        const int* p = (const int*)eiraw;
        g_src[e] = p[e];
        g_dst[e] = p[Ee + e];
    } else {
        const long long* p = (const long long*)eiraw;
        g_src[e] = (int)p[e];
        g_dst[e] = (int)p[Ee + e];
    }
}

__global__ void k_hist() {
    int e = blockIdx.x * blockDim.x + threadIdx.x;
    if (e < Ee) atomicAdd(&g_deg[g_dst[e]], 1);
}

__global__ void k_cnt() {
    int n = blockIdx.x * blockDim.x + threadIdx.x;
    if (n < Nn) g_invcnt[n] = 1.f / fmaxf((float)g_deg[n], 1.f);
}

// Pack W1 [3,384,256] into W1ab [192, 1536]: col c<768 -> W1[k][row][j] (dst half),
// col c>=768 -> W1[k][row+192][j] (src half). bias: [b1 | 0].
__global__ void k_pack_w1(const float* __restrict__ W1, const float* __restrict__ b1) {
    int idx = blockIdx.x * blockDim.x + threadIdx.x;
    if (idx < 192 * 1536) {
        int row = idx / 1536, c = idx % 1536;
        float v;
        if (c < 768) {
            int k = c >> 8, j = c & 255;
            v = W1[k * 98304 + row * 256 + j];
        } else {
            int c2 = c - 768;
            int k = c2 >> 8, j = c2 & 255;
            v = W1[k * 98304 + (row + 192) * 256 + j];
        }
        g_W1ab[idx] = v;
    }
    if (idx < 1536) g_biasab[idx] = (idx < 768) ? b1[idx] : 0.f;
}

__global__ void k_pack_whh(const float* __restrict__ Whh) {
    int idx = blockIdx.x * blockDim.x + threadIdx.x;
    if (idx >= 256 * 768) return;
    int kk = idx / 768, g = idx % 768;
    g_WhhT[idx] = Whh[g * 256 + kk];
}

// ---------------- generic fp32 GEMM: C = act(rowscale(A) @ B + bias) ----------------
// A [M,Kd] row-major, B [Kd,Nd] row-major, Nd % 64 == 0, Kd % 16 == 0.
// BM=64 BN=64 BK=16, 256 threads, 4x4 per thread, f32x2 accumulation.
__global__ void __launch_bounds__(256) k_gemm(
    const float* __restrict__ A, const float* __restrict__ B,
    const float* __restrict__ bias, float* __restrict__ C,
    int M, int Kd, int Nd, const float* __restrict__ rowscale, int relu)
{
    __shared__ float As[16][68];
    __shared__ float Bs[16][64];
    int tid = threadIdx.x;
    int tx = tid & 15, ty = tid >> 4;
    int m0 = blockIdx.x * 64, n0 = blockIdx.y * 64;

    int arow = tid >> 2, akk = (tid & 3) * 4;
    int bkk = tid >> 4, bcol = (tid & 15) * 4;

    unsigned long long acc[4][2];
#pragma unroll
    for (int r = 0; r < 4; r++) { acc[r][0] = 0ull; acc[r][1] = 0ull; }

    int am = m0 + arow;
    bool avalid = am < M;
    float rs = 1.f;
    if (rowscale && avalid) rs = rowscale[am];
    const float* Aptr = A + (size_t)(avalid ? am : 0) * Kd + akk;

    for (int kt = 0; kt < Kd; kt += 16) {
        float4 af = make_float4(0.f, 0.f, 0.f, 0.f);
        if (avalid) af = *(const float4*)(Aptr + kt);
        As[akk + 0][arow] = af.x * rs;
        As[akk + 1][arow] = af.y * rs;
        As[akk + 2][arow] = af.z * rs;
        As[akk + 3][arow] = af.w * rs;

        float4 bf4 = *(const float4*)(B + (size_t)(kt + bkk) * Nd + n0 + bcol);
        *(float4*)&Bs[bkk][bcol] = bf4;
        __syncthreads();

#pragma unroll
        for (int kk = 0; kk < 16; kk++) {
            const float4 a4 = *(const float4*)&As[kk][ty * 4];
            const float4 b4 = *(const float4*)&Bs[kk][tx * 4];
            unsigned long long b01 = f2pack(b4.x, b4.y);
            unsigned long long b23 = f2pack(b4.z, b4.w);
            unsigned long long ad;
            ad = f2dup(a4.x); acc[0][0] = f2fma(ad, b01, acc[0][0]); acc[0][1] = f2fma(ad, b23, acc[0][1]);
            ad = f2dup(a4.y); acc[1][0] = f2fma(ad, b01, acc[1][0]); acc[1][1] = f2fma(ad, b23, acc[1][1]);
            ad = f2dup(a4.z); acc[2][0] = f2fma(ad, b01, acc[2][0]); acc[2][1] = f2fma(ad, b23, acc[2][1]);
            ad = f2dup(a4.w); acc[3][0] = f2fma(ad, b01, acc[3][0]); acc[3][1] = f2fma(ad, b23, acc[3][1]);
        }
        __syncthreads();
    }

    int nbase = n0 + tx * 4;
    float bv0 = bias[nbase + 0], bv1 = bias[nbase + 1], bv2 = bias[nbase + 2], bv3 = bias[nbase + 3];
#pragma unroll
    for (int r = 0; r < 4; r++) {
        int m = m0 + ty * 4 + r;
        if (m >= M) continue;
        float o0, o1, o2, o3;
        f2unpack(acc[r][0], o0, o1);
        f2unpack(acc[r][1], o2, o3);
        o0 += bv0; o1 += bv1; o2 += bv2; o3 += bv3;
        if (relu) {
            o0 = fmaxf(o0, 0.f); o1 = fmaxf(o1, 0.f);
            o2 = fmaxf(o2, 0.f); o3 = fmaxf(o3, 0.f);
        }
        *(float4*)(C + (size_t)m * Nd + nbase) = make_float4(o0, o1, o2, o3);
    }
}

// ---------------- edge GEMM + scatter ----------------
// For a tile of 64 edges: h1[e,c] = z[e,1+c/256] * relu(AB[dst[e],c] + AB[src[e],768+c]),
// msg[e,:] = h1[e,:768] @ W2[768,256] + sum_k z_k*b2[k,:], atomicAdd into g_macc[dst[e]].
__global__ void __launch_bounds__(256, 2) k_edge(
    const float* __restrict__ z, const float* __restrict__ W2,
    const float* __restrict__ b2)
{
    __shared__ float As[16][68];
    __shared__ float Bs[16][256];
    __shared__ int sdst[64], ssrc[64];
    __shared__ float sz[3][64];

    int tid = threadIdx.x;
    int e0 = blockIdx.x * 64;

    if (tid < 64) {
        sdst[tid] = g_dst[e0 + tid];
        ssrc[tid] = g_src[e0 + tid];
    }
    if (tid < 192) {
        int r = tid & 63, k = tid >> 6;
        sz[k][r] = z[(size_t)(e0 + r) * 4 + 1 + k];
    }
    __syncthreads();

    int tx = tid & 31, ty = tid >> 5;
    int arow = tid >> 2, akk = (tid & 3) * 4;
    int dstn = sdst[arow], srcn = ssrc[arow];
    const float* pa = g_AB + (size_t)dstn * 1536 + akk;
    const float* pb = g_AB + (size_t)srcn * 1536 + 768 + akk;

    unsigned long long acc[8][4];
#pragma unroll
    for (int r = 0; r < 8; r++)
#pragma unroll
        for (int p = 0; p < 4; p++) acc[r][p] = 0ull;

    for (int kt = 0; kt < 768; kt += 16) {
        // gather + relu + z-scale the A (h1) slice
        float4 fa = *(const float4*)(pa + kt);
        float4 fb = *(const float4*)(pb + kt);
        float zz = sz[kt >> 8][arow];
        As[akk + 0][arow] = fmaxf(fa.x + fb.x, 0.f) * zz;
        As[akk + 1][arow] = fmaxf(fa.y + fb.y, 0.f) * zz;
        As[akk + 2][arow] = fmaxf(fa.z + fb.z, 0.f) * zz;
        As[akk + 3][arow] = fmaxf(fa.w + fb.w, 0.f) * zz;

        // W2 slice [16,256]
#pragma unroll
        for (int i = 0; i < 4; i++) {
            int lin4 = tid + 256 * i;        // float4 index 0..1023
            int kk = lin4 >> 6;
            int c4 = (lin4 & 63) * 4;
            float4 w = *(const float4*)(W2 + (size_t)(kt + kk) * 256 + c4);
            *(float4*)&Bs[kk][c4] = w;
        }
        __syncthreads();

#pragma unroll
        for (int kk = 0; kk < 16; kk++) {
            const float4 aA = *(const float4*)&As[kk][ty * 8];
            const float4 aB = *(const float4*)&As[kk][ty * 8 + 4];
            const float4 bx = *(const float4*)&Bs[kk][tx * 8];
            const float4 by = *(const float4*)&Bs[kk][tx * 8 + 4];
            unsigned long long bp0 = f2pack(bx.x, bx.y);
            unsigned long long bp1 = f2pack(bx.z, bx.w);
            unsigned long long bp2 = f2pack(by.x, by.y);
            unsigned long long bp3 = f2pack(by.z, by.w);
            float av[8] = {aA.x, aA.y, aA.z, aA.w, aB.x, aB.y, aB.z, aB.w};
#pragma unroll
            for (int r = 0; r < 8; r++) {
                unsigned long long ad = f2dup(av[r]);
                acc[r][0] = f2fma(ad, bp0, acc[r][0]);
                acc[r][1] = f2fma(ad, bp1, acc[r][1]);
                acc[r][2] = f2fma(ad, bp2, acc[r][2]);
                acc[r][3] = f2fma(ad, bp3, acc[r][3]);
            }
        }
        __syncthreads();
    }

    // epilogue: + sum_k z_k*b2[k,col], scatter via atomics
    int col = tx * 8;
    float b2v0[8], b2v1[8], b2v2[8];
#pragma unroll
    for (int c = 0; c < 8; c++) {
        b2v0[c] = b2[col + c];
        b2v1[c] = b2[256 + col + c];
        b2v2[c] = b2[512 + col + c];
    }
#pragma unroll
    for (int r = 0; r < 8; r++) {
        int erow = ty * 8 + r;
        int node = sdst[erow];
        float z0 = sz[0][erow], z1 = sz[1][erow], z2 = sz[2][erow];
        float* base = g_macc + (size_t)node * 256 + col;
#pragma unroll
        for (int p = 0; p < 4; p++) {
            float lo, hi;
            f2unpack(acc[r][p], lo, hi);
            int c = p * 2;
            lo += z0 * b2v0[c] + z1 * b2v1[c] + z2 * b2v2[c];
            hi += z0 * b2v0[c + 1] + z1 * b2v1[c + 1] + z2 * b2v2[c + 1];
            atomicAdd(base + c, lo);
            atomicAdd(base + c + 1, hi);
        }
    }
}

// ---------------- GRU + output, zeroes macc for next step ----------------
__global__ void k_gru(int t, const float* __restrict__ x,
                      const float* __restrict__ Wih, const float* __restrict__ bih,
                      const float* __restrict__ Wo, const float* __restrict__ bo,
                      float* __restrict__ out)
{
    int n = blockIdx.x;
    int i = threadIdx.x;
    __shared__ float sin6[6];
    __shared__ float sred[6][8];

    if (i < 6) sin6[i] = (t < TTEACH) ? x[(size_t)n * NFd + t * 6 + i] : g_prev[n * 6 + i];
    __syncthreads();

    float ic = g_invcnt[n];
    float m = g_macc[(size_t)n * 256 + i] * ic;
    g_macc[(size_t)n * 256 + i] = 0.f;

    float gxr = bih[i], gxz = bih[256 + i], gxn = bih[512 + i];
#pragma unroll
    for (int j = 0; j < 6; j++) {
        float xv = sin6[j];
        gxr += Wih[i * 6 + j] * xv;
        gxz += Wih[(256 + i) * 6 + j] * xv;
        gxn += Wih[(512 + i) * 6 + j] * xv;
    }
    size_t gb = (size_t)n * 768;
    float ghr = g_gh[gb + i], ghz = g_gh[gb + 256 + i], ghn = g_gh[gb + 512 + i];

    float r = 1.f / (1.f + expf(-(gxr + ghr)));
    float zg = 1.f / (1.f + expf(-(gxz + ghz)));
    float nn = tanhf(gxn + r * ghn);
    float hn = (1.f - zg) * nn + zg * m;
    g_h[(size_t)n * 256 + i] = hn;

    // mu = inputs + relu(h_new @ Wo + bo)
#pragma unroll
    for (int j = 0; j < 6; j++) {
        float v = hn * Wo[i * 6 + j];
#pragma unroll
        for (int off = 16; off > 0; off >>= 1)
            v += __shfl_down_sync(0xffffffffu, v, off);
        if ((i & 31) == 0) sred[j][i >> 5] = v;
    }
    __syncthreads();
    if (i < 6) {
        float s = 0.f;
#pragma unroll
        for (int w = 0; w < 8; w++) s += sred[i][w];
        float mu = sin6[i] + fmaxf(s + bo[i], 0.f);
        out[(size_t)n * NFd + t * 6 + i] = mu;
        g_prev[n * 6 + i] = mu;
    }
}

// ---------------- launch ----------------
extern "C" void kernel_launch(void* const* d_in, const int* in_sizes, int n_in,
                              void* d_out, int out_size)
{
    const float* x   = (const float*)d_in[0];
    const void*  ei  = d_in[1];
    const float* z   = (const float*)d_in[2];
    const float* Wf  = (const float*)d_in[3];
    const float* bf  = (const float*)d_in[4];
    const float* W1  = (const float*)d_in[5];
    const float* b1  = (const float*)d_in[6];
    const float* W2  = (const float*)d_in[7];
    const float* b2  = (const float*)d_in[8];
    const float* Wih = (const float*)d_in[9];
    const float* bih = (const float*)d_in[10];
    const float* Whh = (const float*)d_in[11];
    const float* bhh = (const float*)d_in[12];
    const float* Wo  = (const float*)d_in[13];
    const float* bo  = (const float*)d_in[14];
    float* out = (float*)d_out;

    float *p_h, *p_fh, *p_AB, *p_macc, *p_gh, *p_W1ab, *p_biasab, *p_WhhT, *p_ic;
    cudaGetSymbolAddress((void**)&p_h, g_h);
    cudaGetSymbolAddress((void**)&p_fh, g_fh);
    cudaGetSymbolAddress((void**)&p_AB, g_AB);
    cudaGetSymbolAddress((void**)&p_macc, g_macc);
    cudaGetSymbolAddress((void**)&p_gh, g_gh);
    cudaGetSymbolAddress((void**)&p_W1ab, g_W1ab);
    cudaGetSymbolAddress((void**)&p_biasab, g_biasab);
    cudaGetSymbolAddress((void**)&p_WhhT, g_WhhT);
    cudaGetSymbolAddress((void**)&p_ic, g_invcnt);

    k_init<<<512, 256>>>();
    k_detect<<<512, 256>>>((const int*)ei);
    k_extract<<<(Ee + 255) / 256, 256>>>(ei);
    k_hist<<<(Ee + 255) / 256, 256>>>();
    k_cnt<<<(Nn + 255) / 256, 256>>>();
    k_pack_w1<<<(192 * 1536 + 255) / 256, 256>>>(W1, b1);
    k_pack_whh<<<(256 * 768 + 255) / 256, 256>>>(Whh);

    dim3 gfh((Nn + 63) / 64, NFd / 64);     // 157 x 3
    dim3 gab((Nn + 63) / 64, 1536 / 64);    // 157 x 24
    dim3 ggh((Nn + 63) / 64, 768 / 64);     // 157 x 12
    int  gedge = Ee / 64;                   // 2500

    for (int t = 0; t < Tt; t++) {
        // fh = relu(h @ Wf + bf)
        k_gemm<<<gfh, 256>>>(p_h, Wf, bf, p_fh, Nn, 256, NFd, nullptr, 1);
        // AB = fh @ [W1a|W1b] + [b1|0]
        k_gemm<<<gab, 256>>>(p_fh, p_W1ab, p_biasab, p_AB, Nn, 192, 1536, nullptr, 0);
        // per-edge MLP2 + z-sum + scatter
        k_edge<<<gedge, 256>>>(z, W2, b2);
        // gh = (macc/cnt) @ Whh^T + bhh
        k_gemm<<<ggh, 256>>>(p_macc, p_WhhT, bhh, p_gh, Nn, 256, 768, p_ic, 0);
        // GRU + output head (also zeroes macc)
        k_gru<<<Nn, 256>>>(t, x, Wih, bih, Wo, bo, out);
    }
}

// round 3
// speedup vs baseline: 1.3410x; 1.3410x over previous
#include <cuda_runtime.h>
#include <cuda_bf16.h>
#include <cstdint>

// ---------------- problem constants ----------------
#define Nn 10000
#define Ee 160000
#define Tt 32
#define Hh 256
#define NFd 192            // T*6
#define TTEACH 24

// edge-GEMM tiling (mma.sync path)
#define EM 128             // edges per CTA
#define ENH 128            // N columns per CTA (one of 2 halves)
#define EK 768             // reduced K
#define ECH 64             // K chunk
#define NCHUNK (EK/ECH)    // 12

// dynamic SMEM layout (bytes): four 16KB tiles
#define SM_AHI 0
#define SM_ALO 16384
#define SM_BHI 32768
#define SM_BLO 49152
#define SM_EDGE_TOTAL 65536

// ---------------- device scratch ----------------
static __device__ float g_h[Nn * Hh];
static __device__ float g_prev[Nn * 6];
static __device__ float g_fh[Nn * NFd];
static __device__ float g_AB[Nn * 1536];
static __device__ float g_macc[Nn * Hh];
static __device__ float g_gh[Nn * 768];
static __device__ float g_W1ab[192 * 1536];
static __device__ float g_biasab[1536];
static __device__ float g_WhhT[256 * 768];
static __device__ float g_invcnt[Nn];
static __device__ int   g_deg[Nn];
static __device__ int   g_src[Ee];
static __device__ int   g_dst[Ee];
static __device__ int   g_is32;
// W2^T split to bf16 hi/lo, pre-swizzled per (chunk, nhalf): tiles of [128 n][64 k]
static __device__ __nv_bfloat16 g_Bpk_hi[NCHUNK * 2 * ENH * ECH];
static __device__ __nv_bfloat16 g_Bpk_lo[NCHUNK * 2 * ENH * ECH];

// ---------------- f32x2 packed-FMA helpers ----------------
__device__ __forceinline__ unsigned long long f2pack(float lo, float hi) {
    unsigned long long r;
    asm("mov.b64 %0, {%1, %2};" : "=l"(r) : "f"(lo), "f"(hi));
    return r;
}
__device__ __forceinline__ unsigned long long f2dup(float v) {
    unsigned long long r;
    asm("mov.b64 %0, {%1, %1};" : "=l"(r) : "f"(v));
    return r;
}
__device__ __forceinline__ unsigned long long f2fma(unsigned long long a,
                                                    unsigned long long b,
                                                    unsigned long long c) {
    unsigned long long d;
    asm("fma.rn.f32x2 %0, %1, %2, %3;" : "=l"(d) : "l"(a), "l"(b), "l"(c));
    return d;
}
__device__ __forceinline__ void f2unpack(unsigned long long v, float& lo, float& hi) {
    asm("mov.b64 {%0, %1}, %2;" : "=f"(lo), "=f"(hi) : "l"(v));
}

// ---------------- warp-mma helpers (baseline PTX, compiles at compute_103) ----------------
__device__ __forceinline__ uint32_t smem_u32(const void* p) {
    uint32_t a;
    asm("{ .reg .u64 t; cvta.to.shared.u64 t, %1; cvt.u32.u64 %0, t; }" : "=r"(a) : "l"(p));
    return a;
}
#define SWZ128(off) ((off) ^ (((off) >> 3) & 0x70))

__device__ __forceinline__ void ldm4(uint32_t* r, uint32_t addr) {
    asm volatile("ldmatrix.sync.aligned.m8n8.x4.shared.b16 {%0,%1,%2,%3}, [%4];"
                 : "=r"(r[0]), "=r"(r[1]), "=r"(r[2]), "=r"(r[3]) : "r"(addr));
}
__device__ __forceinline__ void ldm2(uint32_t* r, uint32_t addr) {
    asm volatile("ldmatrix.sync.aligned.m8n8.x2.shared.b16 {%0,%1}, [%2];"
                 : "=r"(r[0]), "=r"(r[1]) : "r"(addr));
}
__device__ __forceinline__ void mma_bf16(float* c, const uint32_t* a, const uint32_t* b) {
    asm volatile(
        "mma.sync.aligned.m16n8k16.row.col.f32.bf16.bf16.f32 "
        "{%0,%1,%2,%3}, {%4,%5,%6,%7}, {%8,%9}, {%0,%1,%2,%3};"
        : "+f"(c[0]), "+f"(c[1]), "+f"(c[2]), "+f"(c[3])
        : "r"(a[0]), "r"(a[1]), "r"(a[2]), "r"(a[3]), "r"(b[0]), "r"(b[1]));
}

// ---------------- setup kernels ----------------
__global__ void k_init() {
    int i = blockIdx.x * blockDim.x + threadIdx.x;
    int st = gridDim.x * blockDim.x;
    for (int j = i; j < Nn * Hh; j += st) { g_h[j] = 0.f; g_macc[j] = 0.f; }
    for (int j = i; j < Nn * 6; j += st) g_prev[j] = 0.f;
    for (int j = i; j < Nn; j += st) g_deg[j] = 0;
    if (i == 0) g_is32 = 0;
}

__global__ void k_detect(const int* __restrict__ w) {
    int i = blockIdx.x * blockDim.x + threadIdx.x;
    int st = gridDim.x * blockDim.x;
    for (int j = i; j < 2 * Ee; j += st) {
        if ((j & 1) && w[j] != 0) g_is32 = 1;
    }
}

__global__ void k_extract(const void* __restrict__ eiraw) {
    int e = blockIdx.x * blockDim.x + threadIdx.x;
    if (e >= Ee) return;
    if (g_is32) {
        const int* p = (const int*)eiraw;
        g_src[e] = p[e];
        g_dst[e] = p[Ee + e];
    } else {
        const long long* p = (const long long*)eiraw;
        g_src[e] = (int)p[e];
        g_dst[e] = (int)p[Ee + e];
    }
}

__global__ void k_hist() {
    int e = blockIdx.x * blockDim.x + threadIdx.x;
    if (e < Ee) atomicAdd(&g_deg[g_dst[e]], 1);
}

__global__ void k_cnt() {
    int n = blockIdx.x * blockDim.x + threadIdx.x;
    if (n < Nn) g_invcnt[n] = 1.f / fmaxf((float)g_deg[n], 1.f);
}

__global__ void k_pack_w1(const float* __restrict__ W1, const float* __restrict__ b1) {
    int idx = blockIdx.x * blockDim.x + threadIdx.x;
    if (idx < 192 * 1536) {
        int row = idx / 1536, c = idx % 1536;
        float v;
        if (c < 768) {
            int k = c >> 8, j = c & 255;
            v = W1[k * 98304 + row * 256 + j];
        } else {
            int c2 = c - 768;
            int k = c2 >> 8, j = c2 & 255;
            v = W1[k * 98304 + (row + 192) * 256 + j];
        }
        g_W1ab[idx] = v;
    }
    if (idx < 1536) g_biasab[idx] = (idx < 768) ? b1[idx] : 0.f;
}

__global__ void k_pack_whh(const float* __restrict__ Whh) {
    int idx = blockIdx.x * blockDim.x + threadIdx.x;
    if (idx >= 256 * 768) return;
    int kk = idx / 768, g = idx % 768;
    g_WhhT[idx] = Whh[g * 256 + kk];
}

// W2 [768,256] -> per-(chunk, nhalf) swizzled bf16 hi/lo tiles: [n 128][k 64], 128B rows
__global__ void k_pack_w2(const float* __restrict__ W2) {
    int idx = blockIdx.x * blockDim.x + threadIdx.x;
    if (idx >= NCHUNK * 2 * ENH * ECH) return;
    int chunk = idx / (2 * ENH * ECH);
    int rem = idx % (2 * ENH * ECH);
    int nh = rem / (ENH * ECH);
    int rem2 = rem % (ENH * ECH);
    int n = rem2 / ECH, k = rem2 % ECH;
    float w = W2[(size_t)(chunk * ECH + k) * 256 + nh * ENH + n];
    __nv_bfloat16 hi = __float2bfloat16(w);
    float rl = w - __bfloat162float(hi);
    __nv_bfloat16 lo = __float2bfloat16(rl);
    uint32_t off = SWZ128((uint32_t)(n * 128 + k * 2));   // byte offset in 16KB tile
    size_t base = (size_t)(chunk * 2 + nh) * (ENH * ECH);
    g_Bpk_hi[base + off / 2] = hi;
    g_Bpk_lo[base + off / 2] = lo;
}

// ---------------- generic fp32 GEMM (node-side) ----------------
__global__ void __launch_bounds__(256) k_gemm(
    const float* __restrict__ A, const float* __restrict__ B,
    const float* __restrict__ bias, float* __restrict__ C,
    int M, int Kd, int Nd, const float* __restrict__ rowscale, int relu)
{
    __shared__ float As[16][68];
    __shared__ float Bs[16][64];
    int tid = threadIdx.x;
    int tx = tid & 15, ty = tid >> 4;
    int m0 = blockIdx.x * 64, n0 = blockIdx.y * 64;

    int arow = tid >> 2, akk = (tid & 3) * 4;
    int bkk = tid >> 4, bcol = (tid & 15) * 4;

    unsigned long long acc[4][2];
#pragma unroll
    for (int r = 0; r < 4; r++) { acc[r][0] = 0ull; acc[r][1] = 0ull; }

    int am = m0 + arow;
    bool avalid = am < M;
    float rs = 1.f;
    if (rowscale && avalid) rs = rowscale[am];
    const float* Aptr = A + (size_t)(avalid ? am : 0) * Kd + akk;

    for (int kt = 0; kt < Kd; kt += 16) {
        float4 af = make_float4(0.f, 0.f, 0.f, 0.f);
        if (avalid) af = *(const float4*)(Aptr + kt);
        As[akk + 0][arow] = af.x * rs;
        As[akk + 1][arow] = af.y * rs;
        As[akk + 2][arow] = af.z * rs;
        As[akk + 3][arow] = af.w * rs;

        float4 bf4 = *(const float4*)(B + (size_t)(kt + bkk) * Nd + n0 + bcol);
        *(float4*)&Bs[bkk][bcol] = bf4;
        __syncthreads();

#pragma unroll
        for (int kk = 0; kk < 16; kk++) {
            const float4 a4 = *(const float4*)&As[kk][ty * 4];
            const float4 b4 = *(const float4*)&Bs[kk][tx * 4];
            unsigned long long b01 = f2pack(b4.x, b4.y);
            unsigned long long b23 = f2pack(b4.z, b4.w);
            unsigned long long ad;
            ad = f2dup(a4.x); acc[0][0] = f2fma(ad, b01, acc[0][0]); acc[0][1] = f2fma(ad, b23, acc[0][1]);
            ad = f2dup(a4.y); acc[1][0] = f2fma(ad, b01, acc[1][0]); acc[1][1] = f2fma(ad, b23, acc[1][1]);
            ad = f2dup(a4.z); acc[2][0] = f2fma(ad, b01, acc[2][0]); acc[2][1] = f2fma(ad, b23, acc[2][1]);
            ad = f2dup(a4.w); acc[3][0] = f2fma(ad, b01, acc[3][0]); acc[3][1] = f2fma(ad, b23, acc[3][1]);
        }
        __syncthreads();
    }

    int nbase = n0 + tx * 4;
    float bv0 = bias[nbase + 0], bv1 = bias[nbase + 1], bv2 = bias[nbase + 2], bv3 = bias[nbase + 3];
#pragma unroll
    for (int r = 0; r < 4; r++) {
        int m = m0 + ty * 4 + r;
        if (m >= M) continue;
        float o0, o1, o2, o3;
        f2unpack(acc[r][0], o0, o1);
        f2unpack(acc[r][1], o2, o3);
        o0 += bv0; o1 += bv1; o2 += bv2; o3 += bv3;
        if (relu) {
            o0 = fmaxf(o0, 0.f); o1 = fmaxf(o1, 0.f);
            o2 = fmaxf(o2, 0.f); o3 = fmaxf(o3, 0.f);
        }
        *(float4*)(C + (size_t)m * Nd + nbase) = make_float4(o0, o1, o2, o3);
    }
}

// ---------------- edge GEMM via warp mma.sync (bf16 split) + scatter ----------------
// CTA: 128 edges x 128 cols (blockIdx.y selects N half). K=768 in 12 chunks of 64.
// A row e = z[e]*relu(AB[dst,k]+AB[src,768+k]) split to bf16 hi+lo in SMEM (SW128).
// D = Ahi*Bhi + Ahi*Blo + Alo*Bhi, fp32 accumulators in registers.
__global__ void __launch_bounds__(256)
k_edge_mma(const float* __restrict__ z, const float* __restrict__ b2)
{
    extern __shared__ char dsm[];
    __shared__ int sdst[EM], ssrc[EM];
    __shared__ float sz[3][EM];

    const uint32_t smem_base = smem_u32(dsm);
    const int tid = threadIdx.x;
    const int wid = tid >> 5;
    const int lane = tid & 31;
    const int e0 = blockIdx.x * EM;
    const int nh = blockIdx.y;
    const int ncol0 = nh * ENH;

    if (tid < EM) {
        sdst[tid] = g_dst[e0 + tid];
        ssrc[tid] = g_src[e0 + tid];
        const float* zp = z + (size_t)(e0 + tid) * 4;
        sz[0][tid] = zp[1];
        sz[1][tid] = zp[2];
        sz[2][tid] = zp[3];
    }
    __syncthreads();

    // warp tiling: 2 (M) x 4 (N); warp tile 64 x 32
    const int m0w = (wid >> 2) * 64;
    const int n0w = (wid & 3) * 32;

    float c[4][4][4];
#pragma unroll
    for (int mi = 0; mi < 4; mi++)
#pragma unroll
        for (int ni = 0; ni < 4; ni++)
#pragma unroll
            for (int r = 0; r < 4; r++) c[mi][ni][r] = 0.f;

    // A build assignment: 2 threads per edge row, 32 cols each
    const int arow = tid >> 1;
    const int acol0 = (tid & 1) * 32;
    const float* pd = g_AB + (size_t)sdst[arow] * 1536;
    const float* ps = g_AB + (size_t)ssrc[arow] * 1536 + 768;

    // ldmatrix lane address components (precomputed)
    const int a_r = lane & 15;                 // A: row within 16
    const uint32_t a_kb = (uint32_t)((lane >> 4) << 4);   // A: +16B for k8-15 matrices
    const int b_r = lane & 7;                  // B: row within 8
    const uint32_t b_kb = (uint32_t)(((lane >> 3) & 1) << 4);

    for (int chunk = 0; chunk < NCHUNK; chunk++) {
        const int kc = chunk * ECH;
        const float zz = sz[chunk >> 2][arow];

        // ---- build A hi/lo tile (swizzled, 128B rows) ----
#pragma unroll
        for (int i = 0; i < 8; i++) {
            int cc = acol0 + i * 4;
            float4 a = *(const float4*)(pd + kc + cc);
            float4 b = *(const float4*)(ps + kc + cc);
            float v0 = fmaxf(a.x + b.x, 0.f) * zz;
            float v1 = fmaxf(a.y + b.y, 0.f) * zz;
            float v2 = fmaxf(a.z + b.z, 0.f) * zz;
            float v3 = fmaxf(a.w + b.w, 0.f) * zz;
            __nv_bfloat162 h01 = __floats2bfloat162_rn(v0, v1);
            __nv_bfloat162 h23 = __floats2bfloat162_rn(v2, v3);
            float r0 = v0 - __bfloat162float(h01.x);
            float r1 = v1 - __bfloat162float(h01.y);
            float r2 = v2 - __bfloat162float(h23.x);
            float r3 = v3 - __bfloat162float(h23.y);
            __nv_bfloat162 l01 = __floats2bfloat162_rn(r0, r1);
            __nv_bfloat162 l23 = __floats2bfloat162_rn(r2, r3);
            uint32_t off = SWZ128((uint32_t)(arow * 128 + cc * 2));  // 8B aligned, swizzle-stable
            uint2 hv, lv;
            hv.x = *(uint32_t*)&h01; hv.y = *(uint32_t*)&h23;
            lv.x = *(uint32_t*)&l01; lv.y = *(uint32_t*)&l23;
            *(uint2*)(dsm + SM_AHI + off) = hv;
            *(uint2*)(dsm + SM_ALO + off) = lv;
        }

        // ---- copy B hi/lo tile (pre-swizzled in gmem), 16KB each ----
        {
            size_t tb = (size_t)(chunk * 2 + nh) * (ENH * ECH);
            const uint4* gh4 = (const uint4*)(g_Bpk_hi + tb);
            const uint4* gl4 = (const uint4*)(g_Bpk_lo + tb);
            uint4* sh4 = (uint4*)(dsm + SM_BHI);
            uint4* sl4 = (uint4*)(dsm + SM_BLO);
#pragma unroll
            for (int i = 0; i < 4; i++) {
                int j = tid + i * 256;
                sh4[j] = gh4[j];
                sl4[j] = gl4[j];
            }
        }
        __syncthreads();

        // ---- mma over 4 k16 steps ----
#pragma unroll
        for (int ks = 0; ks < 4; ks++) {
            uint32_t ahi[4][4], alo[4][4];
#pragma unroll
            for (int mi = 0; mi < 4; mi++) {
                uint32_t row = (uint32_t)(m0w + mi * 16 + a_r);
                uint32_t off = SWZ128(row * 128 + (uint32_t)(ks * 32) + a_kb);
                ldm4(ahi[mi], smem_base + SM_AHI + off);
                ldm4(alo[mi], smem_base + SM_ALO + off);
            }
#pragma unroll
            for (int ni = 0; ni < 4; ni++) {
                uint32_t nrow = (uint32_t)(n0w + ni * 8 + b_r);
                uint32_t offb = SWZ128(nrow * 128 + (uint32_t)(ks * 32) + b_kb);
                uint32_t bhi[2], blo[2];
                ldm2(bhi, smem_base + SM_BHI + offb);
                ldm2(blo, smem_base + SM_BLO + offb);
#pragma unroll
                for (int mi = 0; mi < 4; mi++) {
                    mma_bf16(c[mi][ni], ahi[mi], bhi);
                    mma_bf16(c[mi][ni], ahi[mi], blo);
                    mma_bf16(c[mi][ni], alo[mi], bhi);
                }
            }
        }
        __syncthreads();
    }

    // ---- epilogue: + z-weighted b2, scatter-add ----
#pragma unroll
    for (int mi = 0; mi < 4; mi++) {
        int r0 = m0w + mi * 16 + (lane >> 2);
        int r1 = r0 + 8;
        int n0d = sdst[r0], n1d = sdst[r1];
        float z00 = sz[0][r0], z01 = sz[1][r0], z02 = sz[2][r0];
        float z10 = sz[0][r1], z11 = sz[1][r1], z12 = sz[2][r1];
        float* mb0 = g_macc + (size_t)n0d * 256;
        float* mb1 = g_macc + (size_t)n1d * 256;
#pragma unroll
        for (int ni = 0; ni < 4; ni++) {
            int col = ncol0 + n0w + ni * 8 + 2 * (lane & 3);
            float ba0 = b2[col],       bb0 = b2[col + 1];
            float ba1 = b2[256 + col], bb1 = b2[256 + col + 1];
            float ba2 = b2[512 + col], bb2 = b2[512 + col + 1];
            float* cc = c[mi][ni];
            atomicAdd(mb0 + col,     cc[0] + z00 * ba0 + z01 * ba1 + z02 * ba2);
            atomicAdd(mb0 + col + 1, cc[1] + z00 * bb0 + z01 * bb1 + z02 * bb2);
            atomicAdd(mb1 + col,     cc[2] + z10 * ba0 + z11 * ba1 + z12 * ba2);
            atomicAdd(mb1 + col + 1, cc[3] + z10 * bb0 + z11 * bb1 + z12 * bb2);
        }
    }
}

// ---------------- GRU + output, zeroes macc for next step ----------------
__global__ void k_gru(int t, const float* __restrict__ x,
                      const float* __restrict__ Wih, const float* __restrict__ bih,
                      const float* __restrict__ Wo, const float* __restrict__ bo,
                      float* __restrict__ out)
{
    int n = blockIdx.x;
    int i = threadIdx.x;
    __shared__ float sin6[6];
    __shared__ float sred[6][8];

    if (i < 6) sin6[i] = (t < TTEACH) ? x[(size_t)n * NFd + t * 6 + i] : g_prev[n * 6 + i];
    __syncthreads();

    float ic = g_invcnt[n];
    float m = g_macc[(size_t)n * 256 + i] * ic;
    g_macc[(size_t)n * 256 + i] = 0.f;

    float gxr = bih[i], gxz = bih[256 + i], gxn = bih[512 + i];
#pragma unroll
    for (int j = 0; j < 6; j++) {
        float xv = sin6[j];
        gxr += Wih[i * 6 + j] * xv;
        gxz += Wih[(256 + i) * 6 + j] * xv;
        gxn += Wih[(512 + i) * 6 + j] * xv;
    }
    size_t gb = (size_t)n * 768;
    float ghr = g_gh[gb + i], ghz = g_gh[gb + 256 + i], ghn = g_gh[gb + 512 + i];

    float r = 1.f / (1.f + expf(-(gxr + ghr)));
    float zg = 1.f / (1.f + expf(-(gxz + ghz)));
    float nn = tanhf(gxn + r * ghn);
    float hn = (1.f - zg) * nn + zg * m;
    g_h[(size_t)n * 256 + i] = hn;

#pragma unroll
    for (int j = 0; j < 6; j++) {
        float v = hn * Wo[i * 6 + j];
#pragma unroll
        for (int off = 16; off > 0; off >>= 1)
            v += __shfl_down_sync(0xffffffffu, v, off);
        if ((i & 31) == 0) sred[j][i >> 5] = v;
    }
    __syncthreads();
    if (i < 6) {
        float s = 0.f;
#pragma unroll
        for (int w = 0; w < 8; w++) s += sred[i][w];
        float mu = sin6[i] + fmaxf(s + bo[i], 0.f);
        out[(size_t)n * NFd + t * 6 + i] = mu;
        g_prev[n * 6 + i] = mu;
    }
}

// ---------------- launch ----------------
extern "C" void kernel_launch(void* const* d_in, const int* in_sizes, int n_in,
                              void* d_out, int out_size)
{
    const float* x   = (const float*)d_in[0];
    const void*  ei  = d_in[1];
    const float* z   = (const float*)d_in[2];
    const float* Wf  = (const float*)d_in[3];
    const float* bf  = (const float*)d_in[4];
    const float* W1  = (const float*)d_in[5];
    const float* b1  = (const float*)d_in[6];
    const float* W2  = (const float*)d_in[7];
    const float* b2  = (const float*)d_in[8];
    const float* Wih = (const float*)d_in[9];
    const float* bih = (const float*)d_in[10];
    const float* Whh = (const float*)d_in[11];
    const float* bhh = (const float*)d_in[12];
    const float* Wo  = (const float*)d_in[13];
    const float* bo  = (const float*)d_in[14];
    float* out = (float*)d_out;

    float *p_h, *p_fh, *p_AB, *p_macc, *p_gh, *p_W1ab, *p_biasab, *p_WhhT, *p_ic;
    cudaGetSymbolAddress((void**)&p_h, g_h);
    cudaGetSymbolAddress((void**)&p_fh, g_fh);
    cudaGetSymbolAddress((void**)&p_AB, g_AB);
    cudaGetSymbolAddress((void**)&p_macc, g_macc);
    cudaGetSymbolAddress((void**)&p_gh, g_gh);
    cudaGetSymbolAddress((void**)&p_W1ab, g_W1ab);
    cudaGetSymbolAddress((void**)&p_biasab, g_biasab);
    cudaGetSymbolAddress((void**)&p_WhhT, g_WhhT);
    cudaGetSymbolAddress((void**)&p_ic, g_invcnt);

    static int smem_set = 0;
    if (!smem_set) {
        cudaFuncSetAttribute(k_edge_mma, cudaFuncAttributeMaxDynamicSharedMemorySize,
                             SM_EDGE_TOTAL);
        smem_set = 1;
    }

    k_init<<<512, 256>>>();
    k_detect<<<512, 256>>>((const int*)ei);
    k_extract<<<(Ee + 255) / 256, 256>>>(ei);
    k_hist<<<(Ee + 255) / 256, 256>>>();
    k_cnt<<<(Nn + 255) / 256, 256>>>();
    k_pack_w1<<<(192 * 1536 + 255) / 256, 256>>>(W1, b1);
    k_pack_whh<<<(256 * 768 + 255) / 256, 256>>>(Whh);
    k_pack_w2<<<(NCHUNK * 2 * ENH * ECH + 255) / 256, 256>>>(W2);

    dim3 gfh((Nn + 63) / 64, NFd / 64);
    dim3 gab((Nn + 63) / 64, 1536 / 64);
    dim3 ggh((Nn + 63) / 64, 768 / 64);
    dim3 gedge(Ee / EM, 2);                 // 1250 x 2

    for (int t = 0; t < Tt; t++) {
        k_gemm<<<gfh, 256>>>(p_h, Wf, bf, p_fh, Nn, 256, NFd, nullptr, 1);
        k_gemm<<<gab, 256>>>(p_fh, p_W1ab, p_biasab, p_AB, Nn, 192, 1536, nullptr, 0);
        k_edge_mma<<<gedge, 256, SM_EDGE_TOTAL>>>(z, b2);
        k_gemm<<<ggh, 256>>>(p_macc, p_WhhT, bhh, p_gh, Nn, 256, 768, p_ic, 0);
        k_gru<<<Nn, 256>>>(t, x, Wih, bih, Wo, bo, out);
    }
}

// round 4
// speedup vs baseline: 2.5366x; 1.8916x over previous
#include <cuda_runtime.h>
#include <cuda_fp16.h>
#include <cstdint>

// ---------------- problem constants ----------------
#define Nn 10000
#define Ee 160000
#define Tt 32
#define Hh 256
#define NFd 192            // T*6
#define TTEACH 24

// edge-GEMM tiling
#define EM 128             // edges per CTA
#define EN 256             // full msg width per CTA
#define EK 768
#define ECH 64             // K chunk
#define NCHUNK (EK/ECH)    // 12

// dynamic SMEM (bytes): A fp16 128x64 = 16KB, B fp16 256x64 = 32KB
#define SM_A 0
#define SM_B 16384
#define SM_EDGE_TOTAL 49152

// ---------------- device scratch ----------------
static __device__ float g_h[Nn * Hh];
static __device__ float g_prev[Nn * 6];
static __device__ float g_fh[Nn * NFd];
static __device__ float g_AB[Nn * 1536];
static __device__ float g_macc[Nn * Hh];
static __device__ float g_gh[Nn * 768];
static __device__ float g_W1ab[192 * 1536];
static __device__ float g_biasab[1536];
static __device__ float g_WhhT[256 * 768];
static __device__ float g_invcnt[Nn];
static __device__ int   g_deg[Nn];
static __device__ int   g_src[Ee];
static __device__ int   g_dst[Ee];
static __device__ int   g_is32;
// W2^T fp16, pre-swizzled per chunk: tile [n 256][k 64], 128B rows
static __device__ __half g_W2h[NCHUNK * EN * ECH];

// ---------------- f32x2 packed-FMA helpers ----------------
__device__ __forceinline__ unsigned long long f2pack(float lo, float hi) {
    unsigned long long r;
    asm("mov.b64 %0, {%1, %2};" : "=l"(r) : "f"(lo), "f"(hi));
    return r;
}
__device__ __forceinline__ unsigned long long f2dup(float v) {
    unsigned long long r;
    asm("mov.b64 %0, {%1, %1};" : "=l"(r) : "f"(v));
    return r;
}
__device__ __forceinline__ unsigned long long f2fma(unsigned long long a,
                                                    unsigned long long b,
                                                    unsigned long long c) {
    unsigned long long d;
    asm("fma.rn.f32x2 %0, %1, %2, %3;" : "=l"(d) : "l"(a), "l"(b), "l"(c));
    return d;
}
__device__ __forceinline__ void f2unpack(unsigned long long v, float& lo, float& hi) {
    asm("mov.b64 {%0, %1}, %2;" : "=f"(lo), "=f"(hi) : "l"(v));
}

// ---------------- warp-mma helpers (baseline PTX) ----------------
__device__ __forceinline__ uint32_t smem_u32(const void* p) {
    uint32_t a;
    asm("{ .reg .u64 t; cvta.to.shared.u64 t, %1; cvt.u32.u64 %0, t; }" : "=r"(a) : "l"(p));
    return a;
}
#define SWZ128(off) ((off) ^ (((off) >> 3) & 0x70))

__device__ __forceinline__ void ldm4(uint32_t* r, uint32_t addr) {
    asm volatile("ldmatrix.sync.aligned.m8n8.x4.shared.b16 {%0,%1,%2,%3}, [%4];"
                 : "=r"(r[0]), "=r"(r[1]), "=r"(r[2]), "=r"(r[3]) : "r"(addr));
}
__device__ __forceinline__ void ldm2(uint32_t* r, uint32_t addr) {
    asm volatile("ldmatrix.sync.aligned.m8n8.x2.shared.b16 {%0,%1}, [%2];"
                 : "=r"(r[0]), "=r"(r[1]) : "r"(addr));
}
__device__ __forceinline__ void mma_f16(float* c, const uint32_t* a, const uint32_t* b) {
    asm volatile(
        "mma.sync.aligned.m16n8k16.row.col.f32.f16.f16.f32 "
        "{%0,%1,%2,%3}, {%4,%5,%6,%7}, {%8,%9}, {%0,%1,%2,%3};"
        : "+f"(c[0]), "+f"(c[1]), "+f"(c[2]), "+f"(c[3])
        : "r"(a[0]), "r"(a[1]), "r"(a[2]), "r"(a[3]), "r"(b[0]), "r"(b[1]));
}

// ---------------- setup kernels ----------------
__global__ void k_init() {
    int i = blockIdx.x * blockDim.x + threadIdx.x;
    int st = gridDim.x * blockDim.x;
    for (int j = i; j < Nn * Hh; j += st) { g_h[j] = 0.f; g_macc[j] = 0.f; }
    for (int j = i; j < Nn * 6; j += st) g_prev[j] = 0.f;
    for (int j = i; j < Nn; j += st) g_deg[j] = 0;
    if (i == 0) g_is32 = 0;
}

__global__ void k_detect(const int* __restrict__ w) {
    int i = blockIdx.x * blockDim.x + threadIdx.x;
    int st = gridDim.x * blockDim.x;
    for (int j = i; j < 2 * Ee; j += st) {
        if ((j & 1) && w[j] != 0) g_is32 = 1;
    }
}

__global__ void k_extract(const void* __restrict__ eiraw) {
    int e = blockIdx.x * blockDim.x + threadIdx.x;
    if (e >= Ee) return;
    if (g_is32) {
        const int* p = (const int*)eiraw;
        g_src[e] = p[e];
        g_dst[e] = p[Ee + e];
    } else {
        const long long* p = (const long long*)eiraw;
        g_src[e] = (int)p[e];
        g_dst[e] = (int)p[Ee + e];
    }
}

__global__ void k_hist() {
    int e = blockIdx.x * blockDim.x + threadIdx.x;
    if (e < Ee) atomicAdd(&g_deg[g_dst[e]], 1);
}

__global__ void k_cnt() {
    int n = blockIdx.x * blockDim.x + threadIdx.x;
    if (n < Nn) g_invcnt[n] = 1.f / fmaxf((float)g_deg[n], 1.f);
}

__global__ void k_pack_w1(const float* __restrict__ W1, const float* __restrict__ b1) {
    int idx = blockIdx.x * blockDim.x + threadIdx.x;
    if (idx < 192 * 1536) {
        int row = idx / 1536, c = idx % 1536;
        float v;
        if (c < 768) {
            int k = c >> 8, j = c & 255;
            v = W1[k * 98304 + row * 256 + j];
        } else {
            int c2 = c - 768;
            int k = c2 >> 8, j = c2 & 255;
            v = W1[k * 98304 + (row + 192) * 256 + j];
        }
        g_W1ab[idx] = v;
    }
    if (idx < 1536) g_biasab[idx] = (idx < 768) ? b1[idx] : 0.f;
}

__global__ void k_pack_whh(const float* __restrict__ Whh) {
    int idx = blockIdx.x * blockDim.x + threadIdx.x;
    if (idx >= 256 * 768) return;
    int kk = idx / 768, g = idx % 768;
    g_WhhT[idx] = Whh[g * 256 + kk];
}

// W2 [768,256] -> per-chunk swizzled fp16 tile of W2^T: [n 256][k 64], 128B rows
__global__ void k_pack_w2(const float* __restrict__ W2) {
    int idx = blockIdx.x * blockDim.x + threadIdx.x;
    if (idx >= NCHUNK * EN * ECH) return;
    int chunk = idx / (EN * ECH);
    int rem = idx % (EN * ECH);
    int n = rem / ECH, k = rem % ECH;
    float w = W2[(size_t)(chunk * ECH + k) * 256 + n];
    uint32_t off = SWZ128((uint32_t)(n * 128 + k * 2));  // byte offset in 32KB tile
    g_W2h[(size_t)chunk * (EN * ECH) + off / 2] = __float2half_rn(w);
}

// ---------------- generic fp32 GEMM (node-side) ----------------
__global__ void __launch_bounds__(256) k_gemm(
    const float* __restrict__ A, const float* __restrict__ B,
    const float* __restrict__ bias, float* __restrict__ C,
    int M, int Kd, int Nd, const float* __restrict__ rowscale, int relu)
{
    __shared__ float As[16][68];
    __shared__ float Bs[16][64];
    int tid = threadIdx.x;
    int tx = tid & 15, ty = tid >> 4;
    int m0 = blockIdx.x * 64, n0 = blockIdx.y * 64;

    int arow = tid >> 2, akk = (tid & 3) * 4;
    int bkk = tid >> 4, bcol = (tid & 15) * 4;

    unsigned long long acc[4][2];
#pragma unroll
    for (int r = 0; r < 4; r++) { acc[r][0] = 0ull; acc[r][1] = 0ull; }

    int am = m0 + arow;
    bool avalid = am < M;
    float rs = 1.f;
    if (rowscale && avalid) rs = rowscale[am];
    const float* Aptr = A + (size_t)(avalid ? am : 0) * Kd + akk;

    for (int kt = 0; kt < Kd; kt += 16) {
        float4 af = make_float4(0.f, 0.f, 0.f, 0.f);
        if (avalid) af = *(const float4*)(Aptr + kt);
        As[akk + 0][arow] = af.x * rs;
        As[akk + 1][arow] = af.y * rs;
        As[akk + 2][arow] = af.z * rs;
        As[akk + 3][arow] = af.w * rs;

        float4 bf4 = *(const float4*)(B + (size_t)(kt + bkk) * Nd + n0 + bcol);
        *(float4*)&Bs[bkk][bcol] = bf4;
        __syncthreads();

#pragma unroll
        for (int kk = 0; kk < 16; kk++) {
            const float4 a4 = *(const float4*)&As[kk][ty * 4];
            const float4 b4 = *(const float4*)&Bs[kk][tx * 4];
            unsigned long long b01 = f2pack(b4.x, b4.y);
            unsigned long long b23 = f2pack(b4.z, b4.w);
            unsigned long long ad;
            ad = f2dup(a4.x); acc[0][0] = f2fma(ad, b01, acc[0][0]); acc[0][1] = f2fma(ad, b23, acc[0][1]);
            ad = f2dup(a4.y); acc[1][0] = f2fma(ad, b01, acc[1][0]); acc[1][1] = f2fma(ad, b23, acc[1][1]);
            ad = f2dup(a4.z); acc[2][0] = f2fma(ad, b01, acc[2][0]); acc[2][1] = f2fma(ad, b23, acc[2][1]);
            ad = f2dup(a4.w); acc[3][0] = f2fma(ad, b01, acc[3][0]); acc[3][1] = f2fma(ad, b23, acc[3][1]);
        }
        __syncthreads();
    }

    int nbase = n0 + tx * 4;
    float bv0 = bias[nbase + 0], bv1 = bias[nbase + 1], bv2 = bias[nbase + 2], bv3 = bias[nbase + 3];
#pragma unroll
    for (int r = 0; r < 4; r++) {
        int m = m0 + ty * 4 + r;
        if (m >= M) continue;
        float o0, o1, o2, o3;
        f2unpack(acc[r][0], o0, o1);
        f2unpack(acc[r][1], o2, o3);
        o0 += bv0; o1 += bv1; o2 += bv2; o3 += bv3;
        if (relu) {
            o0 = fmaxf(o0, 0.f); o1 = fmaxf(o1, 0.f);
            o2 = fmaxf(o2, 0.f); o3 = fmaxf(o3, 0.f);
        }
        *(float4*)(C + (size_t)m * Nd + nbase) = make_float4(o0, o1, o2, o3);
    }
}

// ---------------- edge GEMM: fp16 single-term mma + scatter ----------------
// CTA: 128 edges x 256 cols, 512 threads (16 warps, 4Mx4N, warp tile 32x64).
// A row e = relu((AB[dst,k]+AB[src,768+k]) * z) as fp16 (z>=0 so relu commutes).
__global__ void __launch_bounds__(512)
k_edge_mma(const float* __restrict__ z, const float* __restrict__ b2)
{
    extern __shared__ char dsm[];
    __shared__ int sdst[EM], ssrc[EM];
    __shared__ float sz[3][EM];

    const uint32_t smem_base = smem_u32(dsm);
    const int tid = threadIdx.x;
    const int wid = tid >> 5;
    const int lane = tid & 31;
    const int e0 = blockIdx.x * EM;

    if (tid < EM) {
        sdst[tid] = g_dst[e0 + tid];
        ssrc[tid] = g_src[e0 + tid];
        const float* zp = z + (size_t)(e0 + tid) * 4;
        sz[0][tid] = zp[1];
        sz[1][tid] = zp[2];
        sz[2][tid] = zp[3];
    }
    __syncthreads();

    // warp tiling: 4 (M) x 4 (N); warp tile 32 x 64
    const int m0w = (wid >> 2) * 32;
    const int n0w = (wid & 3) * 64;

    float c[2][8][4];
#pragma unroll
    for (int mi = 0; mi < 2; mi++)
#pragma unroll
        for (int ni = 0; ni < 8; ni++)
#pragma unroll
            for (int r = 0; r < 4; r++) c[mi][ni][r] = 0.f;

    // A build: 4 threads per edge row, 16 cols each
    const int arow = tid >> 2;
    const int acol0 = (tid & 3) * 16;
    const float* pd = g_AB + (size_t)sdst[arow] * 1536;
    const float* ps = g_AB + (size_t)ssrc[arow] * 1536 + 768;

    // ldmatrix lane address components
    const int a_r = lane & 15;
    const uint32_t a_kb = (uint32_t)((lane >> 4) << 4);
    const int b_r = lane & 7;
    const uint32_t b_kb = (uint32_t)(((lane >> 3) & 1) << 4);

    const __half2 hzero = __float2half2_rn(0.f);

    for (int chunk = 0; chunk < NCHUNK; chunk++) {
        const int kc = chunk * ECH;
        const float zz = sz[chunk >> 2][arow];

        // ---- build A fp16 tile (swizzled, 128B rows) ----
#pragma unroll
        for (int i = 0; i < 2; i++) {
            int cc = acol0 + i * 8;
            float4 a0 = *(const float4*)(pd + kc + cc);
            float4 a1 = *(const float4*)(pd + kc + cc + 4);
            float4 b0 = *(const float4*)(ps + kc + cc);
            float4 b1 = *(const float4*)(ps + kc + cc + 4);
            __half2 h0 = __hmax2(__floats2half2_rn((a0.x + b0.x) * zz, (a0.y + b0.y) * zz), hzero);
            __half2 h1 = __hmax2(__floats2half2_rn((a0.z + b0.z) * zz, (a0.w + b0.w) * zz), hzero);
            __half2 h2 = __hmax2(__floats2half2_rn((a1.x + b1.x) * zz, (a1.y + b1.y) * zz), hzero);
            __half2 h3 = __hmax2(__floats2half2_rn((a1.z + b1.z) * zz, (a1.w + b1.w) * zz), hzero);
            uint4 v;
            v.x = *(uint32_t*)&h0; v.y = *(uint32_t*)&h1;
            v.z = *(uint32_t*)&h2; v.w = *(uint32_t*)&h3;
            *(uint4*)(dsm + SM_A + SWZ128((uint32_t)(arow * 128 + cc * 2))) = v;
        }

        // ---- copy B fp16 tile (pre-swizzled), 32KB ----
        {
            const uint4* g4 = (const uint4*)(g_W2h + (size_t)chunk * (EN * ECH));
            uint4* s4 = (uint4*)(dsm + SM_B);
#pragma unroll
            for (int i = 0; i < 4; i++) {
                int j = tid + i * 512;
                s4[j] = g4[j];
            }
        }
        __syncthreads();

        // ---- mma over 4 k16 steps ----
#pragma unroll
        for (int ks = 0; ks < 4; ks++) {
            uint32_t a[2][4];
#pragma unroll
            for (int mi = 0; mi < 2; mi++) {
                uint32_t row = (uint32_t)(m0w + mi * 16 + a_r);
                ldm4(a[mi], smem_base + SM_A + SWZ128(row * 128 + (uint32_t)(ks * 32) + a_kb));
            }
#pragma unroll
            for (int ni = 0; ni < 8; ni++) {
                uint32_t nrow = (uint32_t)(n0w + ni * 8 + b_r);
                uint32_t b[2];
                ldm2(b, smem_base + SM_B + SWZ128(nrow * 128 + (uint32_t)(ks * 32) + b_kb));
                mma_f16(c[0][ni], a[0], b);
                mma_f16(c[1][ni], a[1], b);
            }
        }
        __syncthreads();
    }

    // ---- epilogue: + z-weighted b2, scatter-add ----
#pragma unroll
    for (int mi = 0; mi < 2; mi++) {
        int r0 = m0w + mi * 16 + (lane >> 2);
        int r1 = r0 + 8;
        int n0d = sdst[r0], n1d = sdst[r1];
        float z00 = sz[0][r0], z01 = sz[1][r0], z02 = sz[2][r0];
        float z10 = sz[0][r1], z11 = sz[1][r1], z12 = sz[2][r1];
        float* mb0 = g_macc + (size_t)n0d * 256;
        float* mb1 = g_macc + (size_t)n1d * 256;
#pragma unroll
        for (int ni = 0; ni < 8; ni++) {
            int col = n0w + ni * 8 + 2 * (lane & 3);
            float ba0 = b2[col],       bb0 = b2[col + 1];
            float ba1 = b2[256 + col], bb1 = b2[256 + col + 1];
            float ba2 = b2[512 + col], bb2 = b2[512 + col + 1];
            float* cc = c[mi][ni];
            atomicAdd(mb0 + col,     cc[0] + z00 * ba0 + z01 * ba1 + z02 * ba2);
            atomicAdd(mb0 + col + 1, cc[1] + z00 * bb0 + z01 * bb1 + z02 * bb2);
            atomicAdd(mb1 + col,     cc[2] + z10 * ba0 + z11 * ba1 + z12 * ba2);
            atomicAdd(mb1 + col + 1, cc[3] + z10 * bb0 + z11 * bb1 + z12 * bb2);
        }
    }
}

// ---------------- GRU + output, zeroes macc ----------------
__global__ void k_gru(int t, const float* __restrict__ x,
                      const float* __restrict__ Wih, const float* __restrict__ bih,
                      const float* __restrict__ Wo, const float* __restrict__ bo,
                      float* __restrict__ out)
{
    int n = blockIdx.x;
    int i = threadIdx.x;
    __shared__ float sin6[6];
    __shared__ float sred[6][8];

    if (i < 6) sin6[i] = (t < TTEACH) ? x[(size_t)n * NFd + t * 6 + i] : g_prev[n * 6 + i];
    __syncthreads();

    float ic = g_invcnt[n];
    float m = g_macc[(size_t)n * 256 + i] * ic;
    g_macc[(size_t)n * 256 + i] = 0.f;

    float gxr = bih[i], gxz = bih[256 + i], gxn = bih[512 + i];
#pragma unroll
    for (int j = 0; j < 6; j++) {
        float xv = sin6[j];
        gxr += Wih[i * 6 + j] * xv;
        gxz += Wih[(256 + i) * 6 + j] * xv;
        gxn += Wih[(512 + i) * 6 + j] * xv;
    }
    size_t gb = (size_t)n * 768;
    float ghr = g_gh[gb + i], ghz = g_gh[gb + 256 + i], ghn = g_gh[gb + 512 + i];

    float r = 1.f / (1.f + expf(-(gxr + ghr)));
    float zg = 1.f / (1.f + expf(-(gxz + ghz)));
    float nn = tanhf(gxn + r * ghn);
    float hn = (1.f - zg) * nn + zg * m;
    g_h[(size_t)n * 256 + i] = hn;

#pragma unroll
    for (int j = 0; j < 6; j++) {
        float v = hn * Wo[i * 6 + j];
#pragma unroll
        for (int off = 16; off > 0; off >>= 1)
            v += __shfl_down_sync(0xffffffffu, v, off);
        if ((i & 31) == 0) sred[j][i >> 5] = v;
    }
    __syncthreads();
    if (i < 6) {
        float s = 0.f;
#pragma unroll
        for (int w = 0; w < 8; w++) s += sred[i][w];
        float mu = sin6[i] + fmaxf(s + bo[i], 0.f);
        out[(size_t)n * NFd + t * 6 + i] = mu;
        g_prev[n * 6 + i] = mu;
    }
}

// ---------------- launch ----------------
extern "C" void kernel_launch(void* const* d_in, const int* in_sizes, int n_in,
                              void* d_out, int out_size)
{
    const float* x   = (const float*)d_in[0];
    const void*  ei  = d_in[1];
    const float* z   = (const float*)d_in[2];
    const float* Wf  = (const float*)d_in[3];
    const float* bf  = (const float*)d_in[4];
    const float* W1  = (const float*)d_in[5];
    const float* b1  = (const float*)d_in[6];
    const float* W2  = (const float*)d_in[7];
    const float* b2  = (const float*)d_in[8];
    const float* Wih = (const float*)d_in[9];
    const float* bih = (const float*)d_in[10];
    const float* Whh = (const float*)d_in[11];
    const float* bhh = (const float*)d_in[12];
    const float* Wo  = (const float*)d_in[13];
    const float* bo  = (const float*)d_in[14];
    float* out = (float*)d_out;

    float *p_h, *p_fh, *p_AB, *p_macc, *p_gh, *p_W1ab, *p_biasab, *p_WhhT, *p_ic;
    cudaGetSymbolAddress((void**)&p_h, g_h);
    cudaGetSymbolAddress((void**)&p_fh, g_fh);
    cudaGetSymbolAddress((void**)&p_AB, g_AB);
    cudaGetSymbolAddress((void**)&p_macc, g_macc);
    cudaGetSymbolAddress((void**)&p_gh, g_gh);
    cudaGetSymbolAddress((void**)&p_W1ab, g_W1ab);
    cudaGetSymbolAddress((void**)&p_biasab, g_biasab);
    cudaGetSymbolAddress((void**)&p_WhhT, g_WhhT);
    cudaGetSymbolAddress((void**)&p_ic, g_invcnt);

    static int smem_set = 0;
    if (!smem_set) {
        cudaFuncSetAttribute(k_edge_mma, cudaFuncAttributeMaxDynamicSharedMemorySize,
                             SM_EDGE_TOTAL);
        smem_set = 1;
    }

    k_init<<<512, 256>>>();
    k_detect<<<512, 256>>>((const int*)ei);
    k_extract<<<(Ee + 255) / 256, 256>>>(ei);
    k_hist<<<(Ee + 255) / 256, 256>>>();
    k_cnt<<<(Nn + 255) / 256, 256>>>();
    k_pack_w1<<<(192 * 1536 + 255) / 256, 256>>>(W1, b1);
    k_pack_whh<<<(256 * 768 + 255) / 256, 256>>>(Whh);
    k_pack_w2<<<(NCHUNK * EN * ECH + 255) / 256, 256>>>(W2);

    dim3 gfh((Nn + 63) / 64, NFd / 64);
    dim3 gab((Nn + 63) / 64, 1536 / 64);
    dim3 ggh((Nn + 63) / 64, 768 / 64);
    int  gedge = Ee / EM;                   // 1250

    for (int t = 0; t < Tt; t++) {
        k_gemm<<<gfh, 256>>>(p_h, Wf, bf, p_fh, Nn, 256, NFd, nullptr, 1);
        k_gemm<<<gab, 256>>>(p_fh, p_W1ab, p_biasab, p_AB, Nn, 192, 1536, nullptr, 0);
        k_edge_mma<<<gedge, 512, SM_EDGE_TOTAL>>>(z, b2);
        k_gemm<<<ggh, 256>>>(p_macc, p_WhhT, bhh, p_gh, Nn, 256, 768, p_ic, 0);
        k_gru<<<Nn, 256>>>(t, x, Wih, bih, Wo, bo, out);
    }
}

// round 5
// speedup vs baseline: 4.0004x; 1.5771x over previous
#include <cuda_runtime.h>
#include <cuda_fp16.h>
#include <cstdint>

// ---------------- problem constants ----------------
#define Nn 10000
#define Ee 160000
#define Tt 32
#define Hh 256
#define NFd 192            // T*6
#define TTEACH 24

// edge-GEMM tiling
#define EM 128
#define EN 256
#define EK 768
#define ECH 64
#define NCHUNK (EK/ECH)    // 12

// edge dynamic SMEM: A fp16 128x64 = 16KB, B fp16 256x64 = 32KB
#define SM_A 0
#define SM_B 16384
#define SM_EDGE_TOTAL 49152

// ---------------- device scratch ----------------
static __device__ float  g_h[Nn * Hh];
static __device__ float  g_prev[Nn * 6];
static __device__ __half g_fh16[Nn * NFd];
static __device__ __half g_AB16[Nn * 1536];
static __device__ float  g_macc[Nn * Hh];
static __device__ float  g_gh[Nn * 768];
static __device__ float  g_W1ab[192 * 1536];     // fp32 staging (packed layout)
static __device__ float  g_biasab[1536];
static __device__ float  g_WhhT[256 * 768];      // fp32 staging
static __device__ float  g_invcnt[Nn];
static __device__ int    g_deg[Nn];
static __device__ int    g_src[Ee];
static __device__ int    g_dst[Ee];
static __device__ int    g_is32;
// fp16 pre-swizzled weight tiles ([k64 x n64] tiles, 128B rows, tile=4096 halves)
static __device__ __half g_Wf16[256 * 192];
static __device__ __half g_W1ab16[192 * 1536];
static __device__ __half g_WhhT16[256 * 768];
// edge B: W2^T fp16 per chunk [n 256][k 64]
static __device__ __half g_W2h[NCHUNK * EN * ECH];

// ---------------- helpers ----------------
__device__ __forceinline__ uint32_t smem_u32(const void* p) {
    uint32_t a;
    asm("{ .reg .u64 t; cvta.to.shared.u64 t, %1; cvt.u32.u64 %0, t; }" : "=r"(a) : "l"(p));
    return a;
}
#define SWZ128(off) ((off) ^ (((off) >> 3) & 0x70))

__device__ __forceinline__ void ldm4(uint32_t* r, uint32_t addr) {
    asm volatile("ldmatrix.sync.aligned.m8n8.x4.shared.b16 {%0,%1,%2,%3}, [%4];"
                 : "=r"(r[0]), "=r"(r[1]), "=r"(r[2]), "=r"(r[3]) : "r"(addr));
}
__device__ __forceinline__ void ldm2(uint32_t* r, uint32_t addr) {
    asm volatile("ldmatrix.sync.aligned.m8n8.x2.shared.b16 {%0,%1}, [%2];"
                 : "=r"(r[0]), "=r"(r[1]) : "r"(addr));
}
__device__ __forceinline__ void mma_f16(float* c, const uint32_t* a, const uint32_t* b) {
    asm volatile(
        "mma.sync.aligned.m16n8k16.row.col.f32.f16.f16.f32 "
        "{%0,%1,%2,%3}, {%4,%5,%6,%7}, {%8,%9}, {%0,%1,%2,%3};"
        : "+f"(c[0]), "+f"(c[1]), "+f"(c[2]), "+f"(c[3])
        : "r"(a[0]), "r"(a[1]), "r"(a[2]), "r"(a[3]), "r"(b[0]), "r"(b[1]));
}

// ---------------- setup kernels ----------------
__global__ void k_init() {
    int i = blockIdx.x * blockDim.x + threadIdx.x;
    int st = gridDim.x * blockDim.x;
    for (int j = i; j < Nn * Hh; j += st) { g_h[j] = 0.f; g_macc[j] = 0.f; }
    for (int j = i; j < Nn * 6; j += st) g_prev[j] = 0.f;
    for (int j = i; j < Nn; j += st) g_deg[j] = 0;
    if (i == 0) g_is32 = 0;
}

__global__ void k_detect(const int* __restrict__ w) {
    int i = blockIdx.x * blockDim.x + threadIdx.x;
    int st = gridDim.x * blockDim.x;
    for (int j = i; j < 2 * Ee; j += st) {
        if ((j & 1) && w[j] != 0) g_is32 = 1;
    }
}

__global__ void k_extract(const void* __restrict__ eiraw) {
    int e = blockIdx.x * blockDim.x + threadIdx.x;
    if (e >= Ee) return;
    if (g_is32) {
        const int* p = (const int*)eiraw;
        g_src[e] = p[e];
        g_dst[e] = p[Ee + e];
    } else {
        const long long* p = (const long long*)eiraw;
        g_src[e] = (int)p[e];
        g_dst[e] = (int)p[Ee + e];
    }
}

__global__ void k_hist() {
    int e = blockIdx.x * blockDim.x + threadIdx.x;
    if (e < Ee) atomicAdd(&g_deg[g_dst[e]], 1);
}

__global__ void k_cnt() {
    int n = blockIdx.x * blockDim.x + threadIdx.x;
    if (n < Nn) g_invcnt[n] = 1.f / fmaxf((float)g_deg[n], 1.f);
}

__global__ void k_pack_w1(const float* __restrict__ W1, const float* __restrict__ b1) {
    int idx = blockIdx.x * blockDim.x + threadIdx.x;
    if (idx < 192 * 1536) {
        int row = idx / 1536, c = idx % 1536;
        float v;
        if (c < 768) {
            int k = c >> 8, j = c & 255;
            v = W1[k * 98304 + row * 256 + j];
        } else {
            int c2 = c - 768;
            int k = c2 >> 8, j = c2 & 255;
            v = W1[k * 98304 + (row + 192) * 256 + j];
        }
        g_W1ab[idx] = v;
    }
    if (idx < 1536) g_biasab[idx] = (idx < 768) ? b1[idx] : 0.f;
}

__global__ void k_pack_whh(const float* __restrict__ Whh) {
    int idx = blockIdx.x * blockDim.x + threadIdx.x;
    if (idx >= 256 * 768) return;
    int kk = idx / 768, g = idx % 768;
    g_WhhT[idx] = Whh[g * 256 + kk];
}

// pack fp32 [Kd,Nd] row-major -> fp16 swizzled 64x64 tiles for k_gemm16 B operand
__global__ void k_pack_b16(const float* __restrict__ src, __half* __restrict__ dst,
                           int Kd, int Nd) {
    int idx = blockIdx.x * blockDim.x + threadIdx.x;
    if (idx >= Kd * Nd) return;
    int k = idx / Nd, n = idx % Nd;
    int kc = k >> 6, kk = k & 63, nb = n >> 6, nn = n & 63;
    int tile = kc * (Nd >> 6) + nb;
    uint32_t off = SWZ128((uint32_t)(nn * 128 + kk * 2));
    dst[(size_t)tile * 4096 + off / 2] = __float2half_rn(src[idx]);
}

// W2 [768,256] -> per-chunk swizzled fp16 tile of W2^T: [n 256][k 64]
__global__ void k_pack_w2(const float* __restrict__ W2) {
    int idx = blockIdx.x * blockDim.x + threadIdx.x;
    if (idx >= NCHUNK * EN * ECH) return;
    int chunk = idx / (EN * ECH);
    int rem = idx % (EN * ECH);
    int n = rem / ECH, k = rem % ECH;
    float w = W2[(size_t)(chunk * ECH + k) * 256 + n];
    uint32_t off = SWZ128((uint32_t)(n * 128 + k * 2));
    g_W2h[(size_t)chunk * (EN * ECH) + off / 2] = __float2half_rn(w);
}

// ---------------- unified fp16 tensor-core GEMM ----------------
// C[M,Nd] = act( fp16(rowscale(A)) @ B + bias ); A fp32 or fp16; C fp32 or fp16.
// BM=128 BN=64 BK=64, 256 threads, 8 warps (4M x 2N), warp tile 32x32.
__global__ void __launch_bounds__(256) k_gemm16(
    const void* __restrict__ A, const __half* __restrict__ Bpk,
    const float* __restrict__ bias, void* __restrict__ C,
    int M, int Kd, int Nd, const float* __restrict__ rowscale,
    int relu, int a_fp16, int c_fp16)
{
    __shared__ __half As[128 * 64];
    __shared__ __half Bs[64 * 64];
    char* asb = (char*)As;
    char* bsb = (char*)Bs;
    const uint32_t a_base = smem_u32(As);
    const uint32_t b_base = smem_u32(Bs);

    const int tid = threadIdx.x;
    const int wid = tid >> 5;
    const int lane = tid & 31;
    const int m0 = blockIdx.x * 128;
    const int nblk = blockIdx.y;
    const int n0 = nblk * 64;
    const int nblocks = Nd >> 6;

    const int m0w = (wid >> 1) * 32;
    const int n0w = (wid & 1) * 32;

    float c[2][4][4];
#pragma unroll
    for (int mi = 0; mi < 2; mi++)
#pragma unroll
        for (int ni = 0; ni < 4; ni++)
#pragma unroll
            for (int r = 0; r < 4; r++) c[mi][ni][r] = 0.f;

    const int arow = tid >> 1;
    const int acol0 = (tid & 1) * 32;
    const int am = m0 + arow;
    const bool av = am < M;
    float rs = 1.f;
    if (rowscale && av) rs = rowscale[am];

    const int a_r = lane & 15;
    const uint32_t a_kb = (uint32_t)((lane >> 4) << 4);
    const int b_r = lane & 7;
    const uint32_t b_kb = (uint32_t)(((lane >> 3) & 1) << 4);

    for (int kt = 0; kt < Kd; kt += 64) {
        // ---- stage A (convert or copy), swizzled ----
        if (a_fp16) {
            const __half* Ah = (const __half*)A + (size_t)am * Kd + kt;
#pragma unroll
            for (int i = 0; i < 4; i++) {
                int cc = acol0 + i * 8;
                uint4 v = make_uint4(0u, 0u, 0u, 0u);
                if (av) v = *(const uint4*)(Ah + cc);
                *(uint4*)(asb + SWZ128((uint32_t)(arow * 128 + cc * 2))) = v;
            }
        } else {
            const float* Af = (const float*)A + (size_t)am * Kd + kt;
#pragma unroll
            for (int i = 0; i < 4; i++) {
                int cc = acol0 + i * 8;
                uint4 v = make_uint4(0u, 0u, 0u, 0u);
                if (av) {
                    float4 f0 = *(const float4*)(Af + cc);
                    float4 f1 = *(const float4*)(Af + cc + 4);
                    __half2 h0 = __floats2half2_rn(f0.x * rs, f0.y * rs);
                    __half2 h1 = __floats2half2_rn(f0.z * rs, f0.w * rs);
                    __half2 h2 = __floats2half2_rn(f1.x * rs, f1.y * rs);
                    __half2 h3 = __floats2half2_rn(f1.z * rs, f1.w * rs);
                    v.x = *(uint32_t*)&h0; v.y = *(uint32_t*)&h1;
                    v.z = *(uint32_t*)&h2; v.w = *(uint32_t*)&h3;
                }
                *(uint4*)(asb + SWZ128((uint32_t)(arow * 128 + cc * 2))) = v;
            }
        }
        // ---- stage B tile (8KB copy) ----
        {
            const uint4* g4 = (const uint4*)(Bpk + (size_t)((kt >> 6) * nblocks + nblk) * 4096);
            uint4* s4 = (uint4*)bsb;
            s4[tid] = g4[tid];
            s4[tid + 256] = g4[tid + 256];
        }
        __syncthreads();

        // ---- mma: 4 k16 steps ----
#pragma unroll
        for (int ks = 0; ks < 4; ks++) {
            uint32_t a[2][4];
#pragma unroll
            for (int mi = 0; mi < 2; mi++) {
                uint32_t row = (uint32_t)(m0w + mi * 16 + a_r);
                ldm4(a[mi], a_base + SWZ128(row * 128 + (uint32_t)(ks * 32) + a_kb));
            }
#pragma unroll
            for (int ni = 0; ni < 4; ni++) {
                uint32_t nrow = (uint32_t)(n0w + ni * 8 + b_r);
                uint32_t b[2];
                ldm2(b, b_base + SWZ128(nrow * 128 + (uint32_t)(ks * 32) + b_kb));
                mma_f16(c[0][ni], a[0], b);
                mma_f16(c[1][ni], a[1], b);
            }
        }
        __syncthreads();
    }

    // ---- epilogue ----
#pragma unroll
    for (int mi = 0; mi < 2; mi++) {
        int r0 = m0 + m0w + mi * 16 + (lane >> 2);
        int r1 = r0 + 8;
#pragma unroll
        for (int ni = 0; ni < 4; ni++) {
            int col = n0 + n0w + ni * 8 + 2 * (lane & 3);
            float bv0 = bias[col], bv1 = bias[col + 1];
            float* cc = c[mi][ni];
            float o00 = cc[0] + bv0, o01 = cc[1] + bv1;
            float o10 = cc[2] + bv0, o11 = cc[3] + bv1;
            if (relu) {
                o00 = fmaxf(o00, 0.f); o01 = fmaxf(o01, 0.f);
                o10 = fmaxf(o10, 0.f); o11 = fmaxf(o11, 0.f);
            }
            if (c_fp16) {
                __half* Ch = (__half*)C;
                if (r0 < M) {
                    __half2 h = __floats2half2_rn(o00, o01);
                    *(__half2*)(Ch + (size_t)r0 * Nd + col) = h;
                }
                if (r1 < M) {
                    __half2 h = __floats2half2_rn(o10, o11);
                    *(__half2*)(Ch + (size_t)r1 * Nd + col) = h;
                }
            } else {
                float* Cf = (float*)C;
                if (r0 < M) *(float2*)(Cf + (size_t)r0 * Nd + col) = make_float2(o00, o01);
                if (r1 < M) *(float2*)(Cf + (size_t)r1 * Nd + col) = make_float2(o10, o11);
            }
        }
    }
}

// ---------------- edge GEMM: fp16 gather + mma + scatter ----------------
// CTA: 128 edges x 256 cols, 512 threads (16 warps, 4Mx4N, warp tile 32x64).
// A row e = relu((AB16[dst,k]+AB16[src,768+k]) * z) fp16.
__global__ void __launch_bounds__(512)
k_edge_mma(const float* __restrict__ z, const float* __restrict__ b2)
{
    extern __shared__ char dsm[];
    __shared__ int sdst[EM], ssrc[EM];
    __shared__ float sz[3][EM];

    const uint32_t smem_base = smem_u32(dsm);
    const int tid = threadIdx.x;
    const int wid = tid >> 5;
    const int lane = tid & 31;
    const int e0 = blockIdx.x * EM;

    if (tid < EM) {
        sdst[tid] = g_dst[e0 + tid];
        ssrc[tid] = g_src[e0 + tid];
        const float* zp = z + (size_t)(e0 + tid) * 4;
        sz[0][tid] = zp[1];
        sz[1][tid] = zp[2];
        sz[2][tid] = zp[3];
    }
    __syncthreads();

    const int m0w = (wid >> 2) * 32;
    const int n0w = (wid & 3) * 64;

    float c[2][8][4];
#pragma unroll
    for (int mi = 0; mi < 2; mi++)
#pragma unroll
        for (int ni = 0; ni < 8; ni++)
#pragma unroll
            for (int r = 0; r < 4; r++) c[mi][ni][r] = 0.f;

    // A build: 4 threads per edge row, 16 fp16 cols each
    const int arow = tid >> 2;
    const int acol0 = (tid & 3) * 16;
    const __half* pd = g_AB16 + (size_t)sdst[arow] * 1536;
    const __half* ps = g_AB16 + (size_t)ssrc[arow] * 1536 + 768;

    const int a_r = lane & 15;
    const uint32_t a_kb = (uint32_t)((lane >> 4) << 4);
    const int b_r = lane & 7;
    const uint32_t b_kb = (uint32_t)(((lane >> 3) & 1) << 4);

    const __half2 hzero = __float2half2_rn(0.f);

    for (int chunk = 0; chunk < NCHUNK; chunk++) {
        const int kc = chunk * ECH;
        const __half2 zh = __float2half2_rn(sz[chunk >> 2][arow]);

        // ---- build A fp16 tile ----
#pragma unroll
        for (int i = 0; i < 2; i++) {
            int cc = acol0 + i * 8;
            uint4 a = *(const uint4*)(pd + kc + cc);
            uint4 b = *(const uint4*)(ps + kc + cc);
            __half2 r0 = __hmax2(__hmul2(__hadd2(*(__half2*)&a.x, *(__half2*)&b.x), zh), hzero);
            __half2 r1 = __hmax2(__hmul2(__hadd2(*(__half2*)&a.y, *(__half2*)&b.y), zh), hzero);
            __half2 r2 = __hmax2(__hmul2(__hadd2(*(__half2*)&a.z, *(__half2*)&b.z), zh), hzero);
            __half2 r3 = __hmax2(__hmul2(__hadd2(*(__half2*)&a.w, *(__half2*)&b.w), zh), hzero);
            uint4 v;
            v.x = *(uint32_t*)&r0; v.y = *(uint32_t*)&r1;
            v.z = *(uint32_t*)&r2; v.w = *(uint32_t*)&r3;
            *(uint4*)(dsm + SM_A + SWZ128((uint32_t)(arow * 128 + cc * 2))) = v;
        }

        // ---- copy B fp16 tile (pre-swizzled), 32KB ----
        {
            const uint4* g4 = (const uint4*)(g_W2h + (size_t)chunk * (EN * ECH));
            uint4* s4 = (uint4*)(dsm + SM_B);
#pragma unroll
            for (int i = 0; i < 4; i++) {
                int j = tid + i * 512;
                s4[j] = g4[j];
            }
        }
        __syncthreads();

        // ---- mma over 4 k16 steps ----
#pragma unroll
        for (int ks = 0; ks < 4; ks++) {
            uint32_t a[2][4];
#pragma unroll
            for (int mi = 0; mi < 2; mi++) {
                uint32_t row = (uint32_t)(m0w + mi * 16 + a_r);
                ldm4(a[mi], smem_base + SM_A + SWZ128(row * 128 + (uint32_t)(ks * 32) + a_kb));
            }
#pragma unroll
            for (int ni = 0; ni < 8; ni++) {
                uint32_t nrow = (uint32_t)(n0w + ni * 8 + b_r);
                uint32_t b[2];
                ldm2(b, smem_base + SM_B + SWZ128(nrow * 128 + (uint32_t)(ks * 32) + b_kb));
                mma_f16(c[0][ni], a[0], b);
                mma_f16(c[1][ni], a[1], b);
            }
        }
        __syncthreads();
    }

    // ---- epilogue: + z-weighted b2, scatter-add ----
#pragma unroll
    for (int mi = 0; mi < 2; mi++) {
        int r0 = m0w + mi * 16 + (lane >> 2);
        int r1 = r0 + 8;
        int n0d = sdst[r0], n1d = sdst[r1];
        float z00 = sz[0][r0], z01 = sz[1][r0], z02 = sz[2][r0];
        float z10 = sz[0][r1], z11 = sz[1][r1], z12 = sz[2][r1];
        float* mb0 = g_macc + (size_t)n0d * 256;
        float* mb1 = g_macc + (size_t)n1d * 256;
#pragma unroll
        for (int ni = 0; ni < 8; ni++) {
            int col = n0w + ni * 8 + 2 * (lane & 3);
            float ba0 = b2[col],       bb0 = b2[col + 1];
            float ba1 = b2[256 + col], bb1 = b2[256 + col + 1];
            float ba2 = b2[512 + col], bb2 = b2[512 + col + 1];
            float* cc = c[mi][ni];
            atomicAdd(mb0 + col,     cc[0] + z00 * ba0 + z01 * ba1 + z02 * ba2);
            atomicAdd(mb0 + col + 1, cc[1] + z00 * bb0 + z01 * bb1 + z02 * bb2);
            atomicAdd(mb1 + col,     cc[2] + z10 * ba0 + z11 * ba1 + z12 * ba2);
            atomicAdd(mb1 + col + 1, cc[3] + z10 * bb0 + z11 * bb1 + z12 * bb2);
        }
    }
}

// ---------------- GRU + output, zeroes macc ----------------
__global__ void k_gru(int t, const float* __restrict__ x,
                      const float* __restrict__ Wih, const float* __restrict__ bih,
                      const float* __restrict__ Wo, const float* __restrict__ bo,
                      float* __restrict__ out)
{
    int n = blockIdx.x;
    int i = threadIdx.x;
    __shared__ float sin6[6];
    __shared__ float sred[6][8];

    if (i < 6) sin6[i] = (t < TTEACH) ? x[(size_t)n * NFd + t * 6 + i] : g_prev[n * 6 + i];
    __syncthreads();

    float ic = g_invcnt[n];
    float m = g_macc[(size_t)n * 256 + i] * ic;
    g_macc[(size_t)n * 256 + i] = 0.f;

    float gxr = bih[i], gxz = bih[256 + i], gxn = bih[512 + i];
#pragma unroll
    for (int j = 0; j < 6; j++) {
        float xv = sin6[j];
        gxr += Wih[i * 6 + j] * xv;
        gxz += Wih[(256 + i) * 6 + j] * xv;
        gxn += Wih[(512 + i) * 6 + j] * xv;
    }
    size_t gb = (size_t)n * 768;
    float ghr = g_gh[gb + i], ghz = g_gh[gb + 256 + i], ghn = g_gh[gb + 512 + i];

    float r = 1.f / (1.f + expf(-(gxr + ghr)));
    float zg = 1.f / (1.f + expf(-(gxz + ghz)));
    float nn = tanhf(gxn + r * ghn);
    float hn = (1.f - zg) * nn + zg * m;
    g_h[(size_t)n * 256 + i] = hn;

#pragma unroll
    for (int j = 0; j < 6; j++) {
        float v = hn * Wo[i * 6 + j];
#pragma unroll
        for (int off = 16; off > 0; off >>= 1)
            v += __shfl_down_sync(0xffffffffu, v, off);
        if ((i & 31) == 0) sred[j][i >> 5] = v;
    }
    __syncthreads();
    if (i < 6) {
        float s = 0.f;
#pragma unroll
        for (int w = 0; w < 8; w++) s += sred[i][w];
        float mu = sin6[i] + fmaxf(s + bo[i], 0.f);
        out[(size_t)n * NFd + t * 6 + i] = mu;
        g_prev[n * 6 + i] = mu;
    }
}

// ---------------- launch ----------------
extern "C" void kernel_launch(void* const* d_in, const int* in_sizes, int n_in,
                              void* d_out, int out_size)
{
    const float* x   = (const float*)d_in[0];
    const void*  ei  = d_in[1];
    const float* z   = (const float*)d_in[2];
    const float* Wf  = (const float*)d_in[3];
    const float* bf  = (const float*)d_in[4];
    const float* W1  = (const float*)d_in[5];
    const float* b1  = (const float*)d_in[6];
    const float* W2  = (const float*)d_in[7];
    const float* b2  = (const float*)d_in[8];
    const float* Wih = (const float*)d_in[9];
    const float* bih = (const float*)d_in[10];
    const float* Whh = (const float*)d_in[11];
    const float* bhh = (const float*)d_in[12];
    const float* Wo  = (const float*)d_in[13];
    const float* bo  = (const float*)d_in[14];
    float* out = (float*)d_out;

    float *p_h, *p_macc, *p_gh, *p_W1ab, *p_biasab, *p_WhhT, *p_ic;
    __half *p_fh16, *p_AB16, *p_Wf16, *p_W1ab16, *p_WhhT16;
    cudaGetSymbolAddress((void**)&p_h, g_h);
    cudaGetSymbolAddress((void**)&p_macc, g_macc);
    cudaGetSymbolAddress((void**)&p_gh, g_gh);
    cudaGetSymbolAddress((void**)&p_W1ab, g_W1ab);
    cudaGetSymbolAddress((void**)&p_biasab, g_biasab);
    cudaGetSymbolAddress((void**)&p_WhhT, g_WhhT);
    cudaGetSymbolAddress((void**)&p_ic, g_invcnt);
    cudaGetSymbolAddress((void**)&p_fh16, g_fh16);
    cudaGetSymbolAddress((void**)&p_AB16, g_AB16);
    cudaGetSymbolAddress((void**)&p_Wf16, g_Wf16);
    cudaGetSymbolAddress((void**)&p_W1ab16, g_W1ab16);
    cudaGetSymbolAddress((void**)&p_WhhT16, g_WhhT16);

    static int smem_set = 0;
    if (!smem_set) {
        cudaFuncSetAttribute(k_edge_mma, cudaFuncAttributeMaxDynamicSharedMemorySize,
                             SM_EDGE_TOTAL);
        smem_set = 1;
    }

    k_init<<<512, 256>>>();
    k_detect<<<512, 256>>>((const int*)ei);
    k_extract<<<(Ee + 255) / 256, 256>>>(ei);
    k_hist<<<(Ee + 255) / 256, 256>>>();
    k_cnt<<<(Nn + 255) / 256, 256>>>();
    k_pack_w1<<<(192 * 1536 + 255) / 256, 256>>>(W1, b1);
    k_pack_whh<<<(256 * 768 + 255) / 256, 256>>>(Whh);
    k_pack_w2<<<(NCHUNK * EN * ECH + 255) / 256, 256>>>(W2);
    k_pack_b16<<<(256 * 192 + 255) / 256, 256>>>(Wf, p_Wf16, 256, 192);
    k_pack_b16<<<(192 * 1536 + 255) / 256, 256>>>(p_W1ab, p_W1ab16, 192, 1536);
    k_pack_b16<<<(256 * 768 + 255) / 256, 256>>>(p_WhhT, p_WhhT16, 256, 768);

    dim3 gfh((Nn + 127) / 128, 192 / 64);    // 79 x 3
    dim3 gab((Nn + 127) / 128, 1536 / 64);   // 79 x 24
    dim3 ggh((Nn + 127) / 128, 768 / 64);    // 79 x 12
    int  gedge = Ee / EM;                    // 1250

    for (int t = 0; t < Tt; t++) {
        // fh16 = fp16(relu(h @ Wf + bf))
        k_gemm16<<<gfh, 256>>>(p_h, p_Wf16, bf, p_fh16,
                               Nn, 256, 192, nullptr, 1, 0, 1);
        // AB16 = fp16(fh16 @ W1ab + biasab)
        k_gemm16<<<gab, 256>>>(p_fh16, p_W1ab16, p_biasab, p_AB16,
                               Nn, 192, 1536, nullptr, 0, 1, 1);
        // edge MLP2 + z-sum + scatter
        k_edge_mma<<<gedge, 512, SM_EDGE_TOTAL>>>(z, b2);
        // gh = (macc * invcnt) @ WhhT + bhh   (fp32 out)
        k_gemm16<<<ggh, 256>>>(p_macc, p_WhhT16, bhh, p_gh,
                               Nn, 256, 768, p_ic, 0, 0, 0);
        // GRU + output head (also zeroes macc)
        k_gru<<<Nn, 256>>>(t, x, Wih, bih, Wo, bo, out);
    }
}

// round 6
// speedup vs baseline: 4.1185x; 1.0295x over previous
#include <cuda_runtime.h>
#include <cuda_fp16.h>
#include <cstdint>

// ---------------- problem constants ----------------
#define Nn 10000
#define Ee 160000
#define Tt 32
#define Hh 256
#define NFd 192            // T*6
#define TTEACH 24

// edge-GEMM tiling
#define EM 128
#define EN 256
#define EK 768
#define ECH 64
#define NCHUNK (EK/ECH)    // 12

// edge dynamic SMEM: staging A 16KB + B 32KB; epilogue tile 128x258 fp32 = 132096
#define SM_A 0
#define SM_B 16384
#define SM_EDGE_TOTAL 132096
#define TSTRIDE 258

// ---------------- device scratch ----------------
static __device__ float  g_h[Nn * Hh];
static __device__ float  g_prev[Nn * 6];
static __device__ __half g_fh16[Nn * NFd];
static __device__ __half g_AB16[Nn * 1536];
static __device__ float  g_macc[Nn * Hh];
static __device__ float  g_mbase[Nn * Hh];       // per-step macc init (b2 term folded)
static __device__ float  g_gh[Nn * 768];
static __device__ float  g_W1ab[192 * 1536];
static __device__ float  g_biasab[1536];
static __device__ float  g_WhhT[256 * 768];
static __device__ float  g_invcnt[Nn];
static __device__ float  g_zsum[Nn * 3];
static __device__ int    g_deg[Nn];
static __device__ int    g_base[Nn + 1];
static __device__ int    g_cur[Nn];
static __device__ int    g_src[Ee];
static __device__ int    g_dst[Ee];
static __device__ int    g_srcs[Ee];             // sorted by dst
static __device__ int    g_dsts[Ee];
static __device__ float  g_zs[3 * Ee];           // sorted z (k-major)
static __device__ int    g_is32;
// fp16 pre-swizzled weights
static __device__ __half g_Wf16[256 * 192];
static __device__ __half g_W1ab16[192 * 1536];
static __device__ __half g_WhhT16[256 * 768];
static __device__ __half g_W2h[NCHUNK * EN * ECH];

// ---------------- helpers ----------------
__device__ __forceinline__ uint32_t smem_u32(const void* p) {
    uint32_t a;
    asm("{ .reg .u64 t; cvta.to.shared.u64 t, %1; cvt.u32.u64 %0, t; }" : "=r"(a) : "l"(p));
    return a;
}
#define SWZ128(off) ((off) ^ (((off) >> 3) & 0x70))

__device__ __forceinline__ void ldm4(uint32_t* r, uint32_t addr) {
    asm volatile("ldmatrix.sync.aligned.m8n8.x4.shared.b16 {%0,%1,%2,%3}, [%4];"
                 : "=r"(r[0]), "=r"(r[1]), "=r"(r[2]), "=r"(r[3]) : "r"(addr));
}
__device__ __forceinline__ void ldm2(uint32_t* r, uint32_t addr) {
    asm volatile("ldmatrix.sync.aligned.m8n8.x2.shared.b16 {%0,%1}, [%2];"
                 : "=r"(r[0]), "=r"(r[1]) : "r"(addr));
}
__device__ __forceinline__ void mma_f16(float* c, const uint32_t* a, const uint32_t* b) {
    asm volatile(
        "mma.sync.aligned.m16n8k16.row.col.f32.f16.f16.f32 "
        "{%0,%1,%2,%3}, {%4,%5,%6,%7}, {%8,%9}, {%0,%1,%2,%3};"
        : "+f"(c[0]), "+f"(c[1]), "+f"(c[2]), "+f"(c[3])
        : "r"(a[0]), "r"(a[1]), "r"(a[2]), "r"(a[3]), "r"(b[0]), "r"(b[1]));
}

// ---------------- setup kernels ----------------
__global__ void k_init() {
    int i = blockIdx.x * blockDim.x + threadIdx.x;
    int st = gridDim.x * blockDim.x;
    for (int j = i; j < Nn * Hh; j += st) g_h[j] = 0.f;
    for (int j = i; j < Nn * 6; j += st) g_prev[j] = 0.f;
    for (int j = i; j < Nn; j += st) g_deg[j] = 0;
    for (int j = i; j < Nn * 3; j += st) g_zsum[j] = 0.f;
    if (i == 0) g_is32 = 0;
}

__global__ void k_detect(const int* __restrict__ w) {
    int i = blockIdx.x * blockDim.x + threadIdx.x;
    int st = gridDim.x * blockDim.x;
    for (int j = i; j < 2 * Ee; j += st) {
        if ((j & 1) && w[j] != 0) g_is32 = 1;
    }
}

__global__ void k_extract(const void* __restrict__ eiraw) {
    int e = blockIdx.x * blockDim.x + threadIdx.x;
    if (e >= Ee) return;
    if (g_is32) {
        const int* p = (const int*)eiraw;
        g_src[e] = p[e];
        g_dst[e] = p[Ee + e];
    } else {
        const long long* p = (const long long*)eiraw;
        g_src[e] = (int)p[e];
        g_dst[e] = (int)p[Ee + e];
    }
}

__global__ void k_hist() {
    int e = blockIdx.x * blockDim.x + threadIdx.x;
    if (e < Ee) atomicAdd(&g_deg[g_dst[e]], 1);
}

__global__ void k_cnt() {
    int n = blockIdx.x * blockDim.x + threadIdx.x;
    if (n < Nn) g_invcnt[n] = 1.f / fmaxf((float)g_deg[n], 1.f);
}

// exclusive prefix scan of deg -> base, cur (single block)
__global__ void k_scan() {
    __shared__ int part[512];
    const int tid = threadIdx.x;
    const int per = (Nn + 511) / 512;
    int start = tid * per;
    int s = 0;
    for (int j = 0; j < per; j++) {
        int idx = start + j;
        if (idx < Nn) s += g_deg[idx];
    }
    part[tid] = s;
    __syncthreads();
    if (tid == 0) {
        int acc = 0;
        for (int i = 0; i < 512; i++) { int v = part[i]; part[i] = acc; acc += v; }
    }
    __syncthreads();
    int acc = part[tid];
    for (int j = 0; j < per; j++) {
        int idx = start + j;
        if (idx < Nn) { g_base[idx] = acc; g_cur[idx] = acc; acc += g_deg[idx]; }
    }
    if (tid == 511) g_base[Nn] = acc;
}

// counting-sort placement + z gather + zsum accumulation
__global__ void k_place(const float* __restrict__ z) {
    int e = blockIdx.x * blockDim.x + threadIdx.x;
    if (e >= Ee) return;
    int d = g_dst[e];
    int pos = atomicAdd(&g_cur[d], 1);
    g_srcs[pos] = g_src[e];
    g_dsts[pos] = d;
    float z1 = z[(size_t)e * 4 + 1];
    float z2 = z[(size_t)e * 4 + 2];
    float z3 = z[(size_t)e * 4 + 3];
    g_zs[pos] = z1;
    g_zs[Ee + pos] = z2;
    g_zs[2 * Ee + pos] = z3;
    atomicAdd(&g_zsum[d * 3 + 0], z1);
    atomicAdd(&g_zsum[d * 3 + 1], z2);
    atomicAdd(&g_zsum[d * 3 + 2], z3);
}

// mbase[n,c] = sum_k zsum[n,k] * b2[k,c]; macc initialized to it
__global__ void k_b2base(const float* __restrict__ b2) {
    int idx = blockIdx.x * blockDim.x + threadIdx.x;
    if (idx >= Nn * 256) return;
    int n = idx >> 8, c = idx & 255;
    float v = g_zsum[n * 3 + 0] * b2[c]
            + g_zsum[n * 3 + 1] * b2[256 + c]
            + g_zsum[n * 3 + 2] * b2[512 + c];
    g_mbase[idx] = v;
    g_macc[idx] = v;
}

__global__ void k_pack_w1(const float* __restrict__ W1, const float* __restrict__ b1) {
    int idx = blockIdx.x * blockDim.x + threadIdx.x;
    if (idx < 192 * 1536) {
        int row = idx / 1536, c = idx % 1536;
        float v;
        if (c < 768) {
            int k = c >> 8, j = c & 255;
            v = W1[k * 98304 + row * 256 + j];
        } else {
            int c2 = c - 768;
            int k = c2 >> 8, j = c2 & 255;
            v = W1[k * 98304 + (row + 192) * 256 + j];
        }
        g_W1ab[idx] = v;
    }
    if (idx < 1536) g_biasab[idx] = (idx < 768) ? b1[idx] : 0.f;
}

__global__ void k_pack_whh(const float* __restrict__ Whh) {
    int idx = blockIdx.x * blockDim.x + threadIdx.x;
    if (idx >= 256 * 768) return;
    int kk = idx / 768, g = idx % 768;
    g_WhhT[idx] = Whh[g * 256 + kk];
}

// pack fp32 [Kd,Nd] -> fp16 swizzled 64x64 tiles
__global__ void k_pack_b16(const float* __restrict__ src, __half* __restrict__ dst,
                           int Kd, int Nd) {
    int idx = blockIdx.x * blockDim.x + threadIdx.x;
    if (idx >= Kd * Nd) return;
    int k = idx / Nd, n = idx % Nd;
    int kc = k >> 6, kk = k & 63, nb = n >> 6, nn = n & 63;
    int tile = kc * (Nd >> 6) + nb;
    uint32_t off = SWZ128((uint32_t)(nn * 128 + kk * 2));
    dst[(size_t)tile * 4096 + off / 2] = __float2half_rn(src[idx]);
}

// W2 [768,256] -> per-chunk swizzled fp16 tile of W2^T: [n 256][k 64]
__global__ void k_pack_w2(const float* __restrict__ W2) {
    int idx = blockIdx.x * blockDim.x + threadIdx.x;
    if (idx >= NCHUNK * EN * ECH) return;
    int chunk = idx / (EN * ECH);
    int rem = idx % (EN * ECH);
    int n = rem / ECH, k = rem % ECH;
    float w = W2[(size_t)(chunk * ECH + k) * 256 + n];
    uint32_t off = SWZ128((uint32_t)(n * 128 + k * 2));
    g_W2h[(size_t)chunk * (EN * ECH) + off / 2] = __float2half_rn(w);
}

// ---------------- unified fp16 tensor-core GEMM ----------------
__global__ void __launch_bounds__(256) k_gemm16(
    const void* __restrict__ A, const __half* __restrict__ Bpk,
    const float* __restrict__ bias, void* __restrict__ C,
    int M, int Kd, int Nd, const float* __restrict__ rowscale,
    int relu, int a_fp16, int c_fp16)
{
    __shared__ __half As[128 * 64];
    __shared__ __half Bs[64 * 64];
    char* asb = (char*)As;
    char* bsb = (char*)Bs;
    const uint32_t a_base = smem_u32(As);
    const uint32_t b_base = smem_u32(Bs);

    const int tid = threadIdx.x;
    const int wid = tid >> 5;
    const int lane = tid & 31;
    const int m0 = blockIdx.x * 128;
    const int nblk = blockIdx.y;
    const int n0 = nblk * 64;
    const int nblocks = Nd >> 6;

    const int m0w = (wid >> 1) * 32;
    const int n0w = (wid & 1) * 32;

    float c[2][4][4];
#pragma unroll
    for (int mi = 0; mi < 2; mi++)
#pragma unroll
        for (int ni = 0; ni < 4; ni++)
#pragma unroll
            for (int r = 0; r < 4; r++) c[mi][ni][r] = 0.f;

    const int arow = tid >> 1;
    const int acol0 = (tid & 1) * 32;
    const int am = m0 + arow;
    const bool av = am < M;
    float rs = 1.f;
    if (rowscale && av) rs = rowscale[am];

    const int a_r = lane & 15;
    const uint32_t a_kb = (uint32_t)((lane >> 4) << 4);
    const int b_r = lane & 7;
    const uint32_t b_kb = (uint32_t)(((lane >> 3) & 1) << 4);

    for (int kt = 0; kt < Kd; kt += 64) {
        if (a_fp16) {
            const __half* Ah = (const __half*)A + (size_t)am * Kd + kt;
#pragma unroll
            for (int i = 0; i < 4; i++) {
                int cc = acol0 + i * 8;
                uint4 v = make_uint4(0u, 0u, 0u, 0u);
                if (av) v = *(const uint4*)(Ah + cc);
                *(uint4*)(asb + SWZ128((uint32_t)(arow * 128 + cc * 2))) = v;
            }
        } else {
            const float* Af = (const float*)A + (size_t)am * Kd + kt;
#pragma unroll
            for (int i = 0; i < 4; i++) {
                int cc = acol0 + i * 8;
                uint4 v = make_uint4(0u, 0u, 0u, 0u);
                if (av) {
                    float4 f0 = *(const float4*)(Af + cc);
                    float4 f1 = *(const float4*)(Af + cc + 4);
                    __half2 h0 = __floats2half2_rn(f0.x * rs, f0.y * rs);
                    __half2 h1 = __floats2half2_rn(f0.z * rs, f0.w * rs);
                    __half2 h2 = __floats2half2_rn(f1.x * rs, f1.y * rs);
                    __half2 h3 = __floats2half2_rn(f1.z * rs, f1.w * rs);
                    v.x = *(uint32_t*)&h0; v.y = *(uint32_t*)&h1;
                    v.z = *(uint32_t*)&h2; v.w = *(uint32_t*)&h3;
                }
                *(uint4*)(asb + SWZ128((uint32_t)(arow * 128 + cc * 2))) = v;
            }
        }
        {
            const uint4* g4 = (const uint4*)(Bpk + (size_t)((kt >> 6) * nblocks + nblk) * 4096);
            uint4* s4 = (uint4*)bsb;
            s4[tid] = g4[tid];
            s4[tid + 256] = g4[tid + 256];
        }
        __syncthreads();

#pragma unroll
        for (int ks = 0; ks < 4; ks++) {
            uint32_t a[2][4];
#pragma unroll
            for (int mi = 0; mi < 2; mi++) {
                uint32_t row = (uint32_t)(m0w + mi * 16 + a_r);
                ldm4(a[mi], a_base + SWZ128(row * 128 + (uint32_t)(ks * 32) + a_kb));
            }
#pragma unroll
            for (int ni = 0; ni < 4; ni++) {
                uint32_t nrow = (uint32_t)(n0w + ni * 8 + b_r);
                uint32_t b[2];
                ldm2(b, b_base + SWZ128(nrow * 128 + (uint32_t)(ks * 32) + b_kb));
                mma_f16(c[0][ni], a[0], b);
                mma_f16(c[1][ni], a[1], b);
            }
        }
        __syncthreads();
    }

#pragma unroll
    for (int mi = 0; mi < 2; mi++) {
        int r0 = m0 + m0w + mi * 16 + (lane >> 2);
        int r1 = r0 + 8;
#pragma unroll
        for (int ni = 0; ni < 4; ni++) {
            int col = n0 + n0w + ni * 8 + 2 * (lane & 3);
            float bv0 = bias[col], bv1 = bias[col + 1];
            float* cc = c[mi][ni];
            float o00 = cc[0] + bv0, o01 = cc[1] + bv1;
            float o10 = cc[2] + bv0, o11 = cc[3] + bv1;
            if (relu) {
                o00 = fmaxf(o00, 0.f); o01 = fmaxf(o01, 0.f);
                o10 = fmaxf(o10, 0.f); o11 = fmaxf(o11, 0.f);
            }
            if (c_fp16) {
                __half* Ch = (__half*)C;
                if (r0 < M) {
                    __half2 h = __floats2half2_rn(o00, o01);
                    *(__half2*)(Ch + (size_t)r0 * Nd + col) = h;
                }
                if (r1 < M) {
                    __half2 h = __floats2half2_rn(o10, o11);
                    *(__half2*)(Ch + (size_t)r1 * Nd + col) = h;
                }
            } else {
                float* Cf = (float*)C;
                if (r0 < M) *(float2*)(Cf + (size_t)r0 * Nd + col) = make_float2(o00, o01);
                if (r1 < M) *(float2*)(Cf + (size_t)r1 * Nd + col) = make_float2(o10, o11);
            }
        }
    }
}

// ---------------- edge GEMM: fp16 mma + segmented-reduction scatter ----------------
// Edges sorted by dst. CTA: 128 edges x 256 cols, 512 threads.
__global__ void __launch_bounds__(512)
k_edge_mma()
{
    extern __shared__ char dsm[];
    __shared__ int sdst[EM];
    __shared__ float sz[3][EM];

    const uint32_t smem_base = smem_u32(dsm);
    const int tid = threadIdx.x;
    const int wid = tid >> 5;
    const int lane = tid & 31;
    const int e0 = blockIdx.x * EM;

    int ssrc_row;
    if (tid < EM) {
        sdst[tid] = g_dsts[e0 + tid];
        sz[0][tid] = g_zs[e0 + tid];
        sz[1][tid] = g_zs[Ee + e0 + tid];
        sz[2][tid] = g_zs[2 * Ee + e0 + tid];
    }
    __syncthreads();

    const int m0w = (wid >> 2) * 32;
    const int n0w = (wid & 3) * 64;

    float c[2][8][4];
#pragma unroll
    for (int mi = 0; mi < 2; mi++)
#pragma unroll
        for (int ni = 0; ni < 8; ni++)
#pragma unroll
            for (int r = 0; r < 4; r++) c[mi][ni][r] = 0.f;

    // A build: 4 threads per edge row, 16 fp16 cols each
    const int arow = tid >> 2;
    const int acol0 = (tid & 3) * 16;
    ssrc_row = g_srcs[e0 + arow];
    const __half* pd = g_AB16 + (size_t)sdst[arow] * 1536;
    const __half* ps = g_AB16 + (size_t)ssrc_row * 1536 + 768;

    const int a_r = lane & 15;
    const uint32_t a_kb = (uint32_t)((lane >> 4) << 4);
    const int b_r = lane & 7;
    const uint32_t b_kb = (uint32_t)(((lane >> 3) & 1) << 4);

    const __half2 hzero = __float2half2_rn(0.f);

    for (int chunk = 0; chunk < NCHUNK; chunk++) {
        const int kc = chunk * ECH;
        const __half2 zh = __float2half2_rn(sz[chunk >> 2][arow]);

#pragma unroll
        for (int i = 0; i < 2; i++) {
            int cc = acol0 + i * 8;
            uint4 a = *(const uint4*)(pd + kc + cc);
            uint4 b = *(const uint4*)(ps + kc + cc);
            __half2 r0 = __hmax2(__hmul2(__hadd2(*(__half2*)&a.x, *(__half2*)&b.x), zh), hzero);
            __half2 r1 = __hmax2(__hmul2(__hadd2(*(__half2*)&a.y, *(__half2*)&b.y), zh), hzero);
            __half2 r2 = __hmax2(__hmul2(__hadd2(*(__half2*)&a.z, *(__half2*)&b.z), zh), hzero);
            __half2 r3 = __hmax2(__hmul2(__hadd2(*(__half2*)&a.w, *(__half2*)&b.w), zh), hzero);
            uint4 v;
            v.x = *(uint32_t*)&r0; v.y = *(uint32_t*)&r1;
            v.z = *(uint32_t*)&r2; v.w = *(uint32_t*)&r3;
            *(uint4*)(dsm + SM_A + SWZ128((uint32_t)(arow * 128 + cc * 2))) = v;
        }

        {
            const uint4* g4 = (const uint4*)(g_W2h + (size_t)chunk * (EN * ECH));
            uint4* s4 = (uint4*)(dsm + SM_B);
#pragma unroll
            for (int i = 0; i < 4; i++) {
                int j = tid + i * 512;
                s4[j] = g4[j];
            }
        }
        __syncthreads();

#pragma unroll
        for (int ks = 0; ks < 4; ks++) {
            uint32_t a[2][4];
#pragma unroll
            for (int mi = 0; mi < 2; mi++) {
                uint32_t row = (uint32_t)(m0w + mi * 16 + a_r);
                ldm4(a[mi], smem_base + SM_A + SWZ128(row * 128 + (uint32_t)(ks * 32) + a_kb));
            }
#pragma unroll
            for (int ni = 0; ni < 8; ni++) {
                uint32_t nrow = (uint32_t)(n0w + ni * 8 + b_r);
                uint32_t b[2];
                ldm2(b, smem_base + SM_B + SWZ128(nrow * 128 + (uint32_t)(ks * 32) + b_kb));
                mma_f16(c[0][ni], a[0], b);
                mma_f16(c[1][ni], a[1], b);
            }
        }
        __syncthreads();
    }

    // ---- epilogue: fragments -> SMEM tile -> segmented reduce -> few atomics ----
    float* tile = (float*)dsm;
#pragma unroll
    for (int mi = 0; mi < 2; mi++) {
        int r0 = m0w + mi * 16 + (lane >> 2);
        int r1 = r0 + 8;
#pragma unroll
        for (int ni = 0; ni < 8; ni++) {
            int col = n0w + ni * 8 + 2 * (lane & 3);
            float* cc = c[mi][ni];
            *(float2*)&tile[r0 * TSTRIDE + col] = make_float2(cc[0], cc[1]);
            *(float2*)&tile[r1 * TSTRIDE + col] = make_float2(cc[2], cc[3]);
        }
    }
    __syncthreads();

    {
        const int col = tid & 255;
        const int half = tid >> 8;
        const int rbeg = half * 64;
        float acc = 0.f;
        int curn = sdst[rbeg];
#pragma unroll 4
        for (int r = rbeg; r < rbeg + 64; r++) {
            int d = sdst[r];
            float v = tile[r * TSTRIDE + col];
            if (d != curn) {
                atomicAdd(g_macc + (size_t)curn * 256 + col, acc);
                acc = 0.f;
                curn = d;
            }
            acc += v;
        }
        atomicAdd(g_macc + (size_t)curn * 256 + col, acc);
    }
}

// ---------------- GRU + output, resets macc to mbase ----------------
__global__ void k_gru(int t, const float* __restrict__ x,
                      const float* __restrict__ Wih, const float* __restrict__ bih,
                      const float* __restrict__ Wo, const float* __restrict__ bo,
                      float* __restrict__ out)
{
    int n = blockIdx.x;
    int i = threadIdx.x;
    __shared__ float sin6[6];
    __shared__ float sred[6][8];

    if (i < 6) sin6[i] = (t < TTEACH) ? x[(size_t)n * NFd + t * 6 + i] : g_prev[n * 6 + i];
    __syncthreads();

    float ic = g_invcnt[n];
    float m = g_macc[(size_t)n * 256 + i] * ic;
    g_macc[(size_t)n * 256 + i] = g_mbase[(size_t)n * 256 + i];

    float gxr = bih[i], gxz = bih[256 + i], gxn = bih[512 + i];
#pragma unroll
    for (int j = 0; j < 6; j++) {
        float xv = sin6[j];
        gxr += Wih[i * 6 + j] * xv;
        gxz += Wih[(256 + i) * 6 + j] * xv;
        gxn += Wih[(512 + i) * 6 + j] * xv;
    }
    size_t gb = (size_t)n * 768;
    float ghr = g_gh[gb + i], ghz = g_gh[gb + 256 + i], ghn = g_gh[gb + 512 + i];

    float r = 1.f / (1.f + expf(-(gxr + ghr)));
    float zg = 1.f / (1.f + expf(-(gxz + ghz)));
    float nn = tanhf(gxn + r * ghn);
    float hn = (1.f - zg) * nn + zg * m;
    g_h[(size_t)n * 256 + i] = hn;

#pragma unroll
    for (int j = 0; j < 6; j++) {
        float v = hn * Wo[i * 6 + j];
#pragma unroll
        for (int off = 16; off > 0; off >>= 1)
            v += __shfl_down_sync(0xffffffffu, v, off);
        if ((i & 31) == 0) sred[j][i >> 5] = v;
    }
    __syncthreads();
    if (i < 6) {
        float s = 0.f;
#pragma unroll
        for (int w = 0; w < 8; w++) s += sred[i][w];
        float mu = sin6[i] + fmaxf(s + bo[i], 0.f);
        out[(size_t)n * NFd + t * 6 + i] = mu;
        g_prev[n * 6 + i] = mu;
    }
}

// ---------------- launch ----------------
extern "C" void kernel_launch(void* const* d_in, const int* in_sizes, int n_in,
                              void* d_out, int out_size)
{
    const float* x   = (const float*)d_in[0];
    const void*  ei  = d_in[1];
    const float* z   = (const float*)d_in[2];
    const float* Wf  = (const float*)d_in[3];
    const float* bf  = (const float*)d_in[4];
    const float* W1  = (const float*)d_in[5];
    const float* b1  = (const float*)d_in[6];
    const float* W2  = (const float*)d_in[7];
    const float* b2  = (const float*)d_in[8];
    const float* Wih = (const float*)d_in[9];
    const float* bih = (const float*)d_in[10];
    const float* Whh = (const float*)d_in[11];
    const float* bhh = (const float*)d_in[12];
    const float* Wo  = (const float*)d_in[13];
    const float* bo  = (const float*)d_in[14];
    float* out = (float*)d_out;

    float *p_h, *p_macc, *p_gh, *p_W1ab, *p_biasab, *p_WhhT, *p_ic;
    __half *p_fh16, *p_AB16, *p_Wf16, *p_W1ab16, *p_WhhT16;
    cudaGetSymbolAddress((void**)&p_h, g_h);
    cudaGetSymbolAddress((void**)&p_macc, g_macc);
    cudaGetSymbolAddress((void**)&p_gh, g_gh);
    cudaGetSymbolAddress((void**)&p_W1ab, g_W1ab);
    cudaGetSymbolAddress((void**)&p_biasab, g_biasab);
    cudaGetSymbolAddress((void**)&p_WhhT, g_WhhT);
    cudaGetSymbolAddress((void**)&p_ic, g_invcnt);
    cudaGetSymbolAddress((void**)&p_fh16, g_fh16);
    cudaGetSymbolAddress((void**)&p_AB16, g_AB16);
    cudaGetSymbolAddress((void**)&p_Wf16, g_Wf16);
    cudaGetSymbolAddress((void**)&p_W1ab16, g_W1ab16);
    cudaGetSymbolAddress((void**)&p_WhhT16, g_WhhT16);

    static int smem_set = 0;
    if (!smem_set) {
        cudaFuncSetAttribute(k_edge_mma, cudaFuncAttributeMaxDynamicSharedMemorySize,
                             SM_EDGE_TOTAL);
        smem_set = 1;
    }

    k_init<<<512, 256>>>();
    k_detect<<<512, 256>>>((const int*)ei);
    k_extract<<<(Ee + 255) / 256, 256>>>(ei);
    k_hist<<<(Ee + 255) / 256, 256>>>();
    k_cnt<<<(Nn + 255) / 256, 256>>>();
    k_scan<<<1, 512>>>();
    k_place<<<(Ee + 255) / 256, 256>>>(z);
    k_b2base<<<(Nn * 256 + 255) / 256, 256>>>(b2);
    k_pack_w1<<<(192 * 1536 + 255) / 256, 256>>>(W1, b1);
    k_pack_whh<<<(256 * 768 + 255) / 256, 256>>>(Whh);
    k_pack_w2<<<(NCHUNK * EN * ECH + 255) / 256, 256>>>(W2);
    k_pack_b16<<<(256 * 192 + 255) / 256, 256>>>(Wf, p_Wf16, 256, 192);
    k_pack_b16<<<(192 * 1536 + 255) / 256, 256>>>(p_W1ab, p_W1ab16, 192, 1536);
    k_pack_b16<<<(256 * 768 + 255) / 256, 256>>>(p_WhhT, p_WhhT16, 256, 768);

    dim3 gfh((Nn + 127) / 128, 192 / 64);
    dim3 gab((Nn + 127) / 128, 1536 / 64);
    dim3 ggh((Nn + 127) / 128, 768 / 64);
    int  gedge = Ee / EM;

    for (int t = 0; t < Tt; t++) {
        k_gemm16<<<gfh, 256>>>(p_h, p_Wf16, bf, p_fh16,
                               Nn, 256, 192, nullptr, 1, 0, 1);
        k_gemm16<<<gab, 256>>>(p_fh16, p_W1ab16, p_biasab, p_AB16,
                               Nn, 192, 1536, nullptr, 0, 1, 1);
        k_edge_mma<<<gedge, 512, SM_EDGE_TOTAL>>>();
        k_gemm16<<<ggh, 256>>>(p_macc, p_WhhT16, bhh, p_gh,
                               Nn, 256, 768, p_ic, 0, 0, 0);
        k_gru<<<Nn, 256>>>(t, x, Wih, bih, Wo, bo, out);
    }
}

// round 7
// speedup vs baseline: 4.4573x; 1.0823x over previous
#include <cuda_runtime.h>
#include <cuda_fp16.h>
#include <cstdint>

// ---------------- problem constants ----------------
#define Nn 10000
#define Ee 160000
#define Tt 32
#define Hh 256
#define NFd 192            // T*6
#define TTEACH 24

// edge-GEMM tiling
#define EM 128
#define EN 256
#define EK 768
#define ECH 64
#define NCHUNK (EK/ECH)    // 12

// edge dynamic SMEM: double-buffered staging A(2x16KB)+B(2x32KB)=96KB;
// epilogue tile 128x258 fp32 = 132096 reuses the same region.
#define SM_A0 0
#define SM_A1 16384
#define SM_B0 32768
#define SM_B1 65536
#define SM_EDGE_TOTAL 132096
#define TSTRIDE 258

// ---------------- device scratch ----------------
static __device__ float  g_h[Nn * Hh];
static __device__ float  g_prev[Nn * 6];
static __device__ __half g_fh16[Nn * NFd];
static __device__ __half g_AB16[Nn * 1536];
static __device__ float  g_macc[Nn * Hh];
static __device__ float  g_mbase[Nn * Hh];
static __device__ float  g_gh[Nn * 768];
static __device__ float  g_W1ab[192 * 1536];
static __device__ float  g_biasab[1536];
static __device__ float  g_WhhT[256 * 768];
static __device__ float  g_invcnt[Nn];
static __device__ float  g_zsum[Nn * 3];
static __device__ int    g_deg[Nn];
static __device__ int    g_base[Nn + 1];
static __device__ int    g_cur[Nn];
static __device__ int    g_src[Ee];
static __device__ int    g_dst[Ee];
static __device__ int    g_srcs[Ee];
static __device__ int    g_dsts[Ee];
static __device__ float  g_zs[3 * Ee];
static __device__ int    g_is32;
static __device__ __half g_Wf16[256 * 192];
static __device__ __half g_W1ab16[192 * 1536];
static __device__ __half g_WhhT16[256 * 768];
static __device__ __half g_W2h[NCHUNK * EN * ECH];

// ---------------- helpers ----------------
__device__ __forceinline__ uint32_t smem_u32(const void* p) {
    uint32_t a;
    asm("{ .reg .u64 t; cvta.to.shared.u64 t, %1; cvt.u32.u64 %0, t; }" : "=r"(a) : "l"(p));
    return a;
}
#define SWZ128(off) ((off) ^ (((off) >> 3) & 0x70))

__device__ __forceinline__ void ldm4(uint32_t* r, uint32_t addr) {
    asm volatile("ldmatrix.sync.aligned.m8n8.x4.shared.b16 {%0,%1,%2,%3}, [%4];"
                 : "=r"(r[0]), "=r"(r[1]), "=r"(r[2]), "=r"(r[3]) : "r"(addr));
}
__device__ __forceinline__ void ldm2(uint32_t* r, uint32_t addr) {
    asm volatile("ldmatrix.sync.aligned.m8n8.x2.shared.b16 {%0,%1}, [%2];"
                 : "=r"(r[0]), "=r"(r[1]) : "r"(addr));
}
__device__ __forceinline__ void mma_f16(float* c, const uint32_t* a, const uint32_t* b) {
    asm volatile(
        "mma.sync.aligned.m16n8k16.row.col.f32.f16.f16.f32 "
        "{%0,%1,%2,%3}, {%4,%5,%6,%7}, {%8,%9}, {%0,%1,%2,%3};"
        : "+f"(c[0]), "+f"(c[1]), "+f"(c[2]), "+f"(c[3])
        : "r"(a[0]), "r"(a[1]), "r"(a[2]), "r"(a[3]), "r"(b[0]), "r"(b[1]));
}
__device__ __forceinline__ void cpasync16(uint32_t smem_addr, const void* gptr) {
    asm volatile("cp.async.cg.shared.global [%0], [%1], 16;"
                 :: "r"(smem_addr), "l"(gptr) : "memory");
}
#define CP_COMMIT() asm volatile("cp.async.commit_group;" ::: "memory")
#define CP_WAIT0()  asm volatile("cp.async.wait_group 0;" ::: "memory")

// ---------------- setup kernels ----------------
__global__ void k_init() {
    int i = blockIdx.x * blockDim.x + threadIdx.x;
    int st = gridDim.x * blockDim.x;
    for (int j = i; j < Nn * Hh; j += st) g_h[j] = 0.f;
    for (int j = i; j < Nn * 6; j += st) g_prev[j] = 0.f;
    for (int j = i; j < Nn; j += st) g_deg[j] = 0;
    for (int j = i; j < Nn * 3; j += st) g_zsum[j] = 0.f;
    if (i == 0) g_is32 = 0;
}

__global__ void k_detect(const int* __restrict__ w) {
    int i = blockIdx.x * blockDim.x + threadIdx.x;
    int st = gridDim.x * blockDim.x;
    for (int j = i; j < 2 * Ee; j += st) {
        if ((j & 1) && w[j] != 0) g_is32 = 1;
    }
}

__global__ void k_extract(const void* __restrict__ eiraw) {
    int e = blockIdx.x * blockDim.x + threadIdx.x;
    if (e >= Ee) return;
    if (g_is32) {
        const int* p = (const int*)eiraw;
        g_src[e] = p[e];
        g_dst[e] = p[Ee + e];
    } else {
        const long long* p = (const long long*)eiraw;
        g_src[e] = (int)p[e];
        g_dst[e] = (int)p[Ee + e];
    }
}

__global__ void k_hist() {
    int e = blockIdx.x * blockDim.x + threadIdx.x;
    if (e < Ee) atomicAdd(&g_deg[g_dst[e]], 1);
}

__global__ void k_cnt() {
    int n = blockIdx.x * blockDim.x + threadIdx.x;
    if (n < Nn) g_invcnt[n] = 1.f / fmaxf((float)g_deg[n], 1.f);
}

__global__ void k_scan() {
    __shared__ int part[512];
    const int tid = threadIdx.x;
    const int per = (Nn + 511) / 512;
    int start = tid * per;
    int s = 0;
    for (int j = 0; j < per; j++) {
        int idx = start + j;
        if (idx < Nn) s += g_deg[idx];
    }
    part[tid] = s;
    __syncthreads();
    if (tid == 0) {
        int acc = 0;
        for (int i = 0; i < 512; i++) { int v = part[i]; part[i] = acc; acc += v; }
    }
    __syncthreads();
    int acc = part[tid];
    for (int j = 0; j < per; j++) {
        int idx = start + j;
        if (idx < Nn) { g_base[idx] = acc; g_cur[idx] = acc; acc += g_deg[idx]; }
    }
    if (tid == 511) g_base[Nn] = acc;
}

__global__ void k_place(const float* __restrict__ z) {
    int e = blockIdx.x * blockDim.x + threadIdx.x;
    if (e >= Ee) return;
    int d = g_dst[e];
    int pos = atomicAdd(&g_cur[d], 1);
    g_srcs[pos] = g_src[e];
    g_dsts[pos] = d;
    float z1 = z[(size_t)e * 4 + 1];
    float z2 = z[(size_t)e * 4 + 2];
    float z3 = z[(size_t)e * 4 + 3];
    g_zs[pos] = z1;
    g_zs[Ee + pos] = z2;
    g_zs[2 * Ee + pos] = z3;
    atomicAdd(&g_zsum[d * 3 + 0], z1);
    atomicAdd(&g_zsum[d * 3 + 1], z2);
    atomicAdd(&g_zsum[d * 3 + 2], z3);
}

__global__ void k_b2base(const float* __restrict__ b2) {
    int idx = blockIdx.x * blockDim.x + threadIdx.x;
    if (idx >= Nn * 256) return;
    int n = idx >> 8, c = idx & 255;
    float v = g_zsum[n * 3 + 0] * b2[c]
            + g_zsum[n * 3 + 1] * b2[256 + c]
            + g_zsum[n * 3 + 2] * b2[512 + c];
    g_mbase[idx] = v;
    g_macc[idx] = v;
}

__global__ void k_pack_w1(const float* __restrict__ W1, const float* __restrict__ b1) {
    int idx = blockIdx.x * blockDim.x + threadIdx.x;
    if (idx < 192 * 1536) {
        int row = idx / 1536, c = idx % 1536;
        float v;
        if (c < 768) {
            int k = c >> 8, j = c & 255;
            v = W1[k * 98304 + row * 256 + j];
        } else {
            int c2 = c - 768;
            int k = c2 >> 8, j = c2 & 255;
            v = W1[k * 98304 + (row + 192) * 256 + j];
        }
        g_W1ab[idx] = v;
    }
    if (idx < 1536) g_biasab[idx] = (idx < 768) ? b1[idx] : 0.f;
}

__global__ void k_pack_whh(const float* __restrict__ Whh) {
    int idx = blockIdx.x * blockDim.x + threadIdx.x;
    if (idx >= 256 * 768) return;
    int kk = idx / 768, g = idx % 768;
    g_WhhT[idx] = Whh[g * 256 + kk];
}

__global__ void k_pack_b16(const float* __restrict__ src, __half* __restrict__ dst,
                           int Kd, int Nd) {
    int idx = blockIdx.x * blockDim.x + threadIdx.x;
    if (idx >= Kd * Nd) return;
    int k = idx / Nd, n = idx % Nd;
    int kc = k >> 6, kk = k & 63, nb = n >> 6, nn = n & 63;
    int tile = kc * (Nd >> 6) + nb;
    uint32_t off = SWZ128((uint32_t)(nn * 128 + kk * 2));
    dst[(size_t)tile * 4096 + off / 2] = __float2half_rn(src[idx]);
}

__global__ void k_pack_w2(const float* __restrict__ W2) {
    int idx = blockIdx.x * blockDim.x + threadIdx.x;
    if (idx >= NCHUNK * EN * ECH) return;
    int chunk = idx / (EN * ECH);
    int rem = idx % (EN * ECH);
    int n = rem / ECH, k = rem % ECH;
    float w = W2[(size_t)(chunk * ECH + k) * 256 + n];
    uint32_t off = SWZ128((uint32_t)(n * 128 + k * 2));
    g_W2h[(size_t)chunk * (EN * ECH) + off / 2] = __float2half_rn(w);
}

// ---------------- unified fp16 tensor-core GEMM ----------------
__global__ void __launch_bounds__(256) k_gemm16(
    const void* __restrict__ A, const __half* __restrict__ Bpk,
    const float* __restrict__ bias, void* __restrict__ C,
    int M, int Kd, int Nd, const float* __restrict__ rowscale,
    int relu, int a_fp16, int c_fp16)
{
    __shared__ __half As[128 * 64];
    __shared__ __half Bs[64 * 64];
    char* asb = (char*)As;
    char* bsb = (char*)Bs;
    const uint32_t a_base = smem_u32(As);
    const uint32_t b_base = smem_u32(Bs);

    const int tid = threadIdx.x;
    const int wid = tid >> 5;
    const int lane = tid & 31;
    const int m0 = blockIdx.x * 128;
    const int nblk = blockIdx.y;
    const int n0 = nblk * 64;
    const int nblocks = Nd >> 6;

    const int m0w = (wid >> 1) * 32;
    const int n0w = (wid & 1) * 32;

    float c[2][4][4];
#pragma unroll
    for (int mi = 0; mi < 2; mi++)
#pragma unroll
        for (int ni = 0; ni < 4; ni++)
#pragma unroll
            for (int r = 0; r < 4; r++) c[mi][ni][r] = 0.f;

    const int arow = tid >> 1;
    const int acol0 = (tid & 1) * 32;
    const int am = m0 + arow;
    const bool av = am < M;
    float rs = 1.f;
    if (rowscale && av) rs = rowscale[am];

    const int a_r = lane & 15;
    const uint32_t a_kb = (uint32_t)((lane >> 4) << 4);
    const int b_r = lane & 7;
    const uint32_t b_kb = (uint32_t)(((lane >> 3) & 1) << 4);

    for (int kt = 0; kt < Kd; kt += 64) {
        if (a_fp16) {
            const __half* Ah = (const __half*)A + (size_t)am * Kd + kt;
#pragma unroll
            for (int i = 0; i < 4; i++) {
                int cc = acol0 + i * 8;
                uint4 v = make_uint4(0u, 0u, 0u, 0u);
                if (av) v = *(const uint4*)(Ah + cc);
                *(uint4*)(asb + SWZ128((uint32_t)(arow * 128 + cc * 2))) = v;
            }
        } else {
            const float* Af = (const float*)A + (size_t)am * Kd + kt;
#pragma unroll
            for (int i = 0; i < 4; i++) {
                int cc = acol0 + i * 8;
                uint4 v = make_uint4(0u, 0u, 0u, 0u);
                if (av) {
                    float4 f0 = *(const float4*)(Af + cc);
                    float4 f1 = *(const float4*)(Af + cc + 4);
                    __half2 h0 = __floats2half2_rn(f0.x * rs, f0.y * rs);
                    __half2 h1 = __floats2half2_rn(f0.z * rs, f0.w * rs);
                    __half2 h2 = __floats2half2_rn(f1.x * rs, f1.y * rs);
                    __half2 h3 = __floats2half2_rn(f1.z * rs, f1.w * rs);
                    v.x = *(uint32_t*)&h0; v.y = *(uint32_t*)&h1;
                    v.z = *(uint32_t*)&h2; v.w = *(uint32_t*)&h3;
                }
                *(uint4*)(asb + SWZ128((uint32_t)(arow * 128 + cc * 2))) = v;
            }
        }
        {
            const uint4* g4 = (const uint4*)(Bpk + (size_t)((kt >> 6) * nblocks + nblk) * 4096);
            uint4* s4 = (uint4*)bsb;
            s4[tid] = g4[tid];
            s4[tid + 256] = g4[tid + 256];
        }
        __syncthreads();

#pragma unroll
        for (int ks = 0; ks < 4; ks++) {
            uint32_t a[2][4];
#pragma unroll
            for (int mi = 0; mi < 2; mi++) {
                uint32_t row = (uint32_t)(m0w + mi * 16 + a_r);
                ldm4(a[mi], a_base + SWZ128(row * 128 + (uint32_t)(ks * 32) + a_kb));
            }
#pragma unroll
            for (int ni = 0; ni < 4; ni++) {
                uint32_t nrow = (uint32_t)(n0w + ni * 8 + b_r);
                uint32_t b[2];
                ldm2(b, b_base + SWZ128(nrow * 128 + (uint32_t)(ks * 32) + b_kb));
                mma_f16(c[0][ni], a[0], b);
                mma_f16(c[1][ni], a[1], b);
            }
        }
        __syncthreads();
    }

#pragma unroll
    for (int mi = 0; mi < 2; mi++) {
        int r0 = m0 + m0w + mi * 16 + (lane >> 2);
        int r1 = r0 + 8;
#pragma unroll
        for (int ni = 0; ni < 4; ni++) {
            int col = n0 + n0w + ni * 8 + 2 * (lane & 3);
            float bv0 = bias[col], bv1 = bias[col + 1];
            float* cc = c[mi][ni];
            float o00 = cc[0] + bv0, o01 = cc[1] + bv1;
            float o10 = cc[2] + bv0, o11 = cc[3] + bv1;
            if (relu) {
                o00 = fmaxf(o00, 0.f); o01 = fmaxf(o01, 0.f);
                o10 = fmaxf(o10, 0.f); o11 = fmaxf(o11, 0.f);
            }
            if (c_fp16) {
                __half* Ch = (__half*)C;
                if (r0 < M) {
                    __half2 h = __floats2half2_rn(o00, o01);
                    *(__half2*)(Ch + (size_t)r0 * Nd + col) = h;
                }
                if (r1 < M) {
                    __half2 h = __floats2half2_rn(o10, o11);
                    *(__half2*)(Ch + (size_t)r1 * Nd + col) = h;
                }
            } else {
                float* Cf = (float*)C;
                if (r0 < M) *(float2*)(Cf + (size_t)r0 * Nd + col) = make_float2(o00, o01);
                if (r1 < M) *(float2*)(Cf + (size_t)r1 * Nd + col) = make_float2(o10, o11);
            }
        }
    }
}

// ---------------- edge GEMM: pipelined fp16 mma + segmented-reduction scatter ----
// Edges sorted by dst. CTA: 128 edges x 256 cols, 512 threads.
// Double-buffered A/B staging; next chunk's A gathered into regs and B via
// cp.async while the current chunk's MMA runs.
__global__ void __launch_bounds__(512)
k_edge_mma()
{
    extern __shared__ char dsm[];
    __shared__ int sdst[EM];
    __shared__ float sz[3][EM];

    const uint32_t smem_base = smem_u32(dsm);
    const int tid = threadIdx.x;
    const int wid = tid >> 5;
    const int lane = tid & 31;
    const int e0 = blockIdx.x * EM;

    if (tid < EM) {
        sdst[tid] = g_dsts[e0 + tid];
        sz[0][tid] = g_zs[e0 + tid];
        sz[1][tid] = g_zs[Ee + e0 + tid];
        sz[2][tid] = g_zs[2 * Ee + e0 + tid];
    }
    __syncthreads();

    const int m0w = (wid >> 2) * 32;
    const int n0w = (wid & 3) * 64;

    float c[2][8][4];
#pragma unroll
    for (int mi = 0; mi < 2; mi++)
#pragma unroll
        for (int ni = 0; ni < 8; ni++)
#pragma unroll
            for (int r = 0; r < 4; r++) c[mi][ni][r] = 0.f;

    // A build: 4 threads per edge row, 16 fp16 cols each
    const int arow = tid >> 2;
    const int acol0 = (tid & 3) * 16;
    const int srow = g_srcs[e0 + arow];
    const __half* pd = g_AB16 + (size_t)sdst[arow] * 1536;
    const __half* ps = g_AB16 + (size_t)srow * 1536 + 768;
    const uint32_t a_sw0 = SWZ128((uint32_t)(arow * 128 + acol0 * 2));
    const uint32_t a_sw1 = SWZ128((uint32_t)(arow * 128 + (acol0 + 8) * 2));

    const int a_r = lane & 15;
    const uint32_t a_kb = (uint32_t)((lane >> 4) << 4);
    const int b_r = lane & 7;
    const uint32_t b_kb = (uint32_t)(((lane >> 3) & 1) << 4);

    const __half2 hzero = __float2half2_rn(0.f);
    const uint32_t aoff[2] = {SM_A0, SM_A1};
    const uint32_t boff[2] = {SM_B0, SM_B1};

    uint4 ra0, ra1, rb0, rb1;   // prefetch regs for next chunk's A inputs

    // ---- prologue: stage chunk 0 ----
    {
        ra0 = *(const uint4*)(pd + acol0);
        ra1 = *(const uint4*)(pd + acol0 + 8);
        rb0 = *(const uint4*)(ps + acol0);
        rb1 = *(const uint4*)(ps + acol0 + 8);
        const char* gB = (const char*)g_W2h;
#pragma unroll
        for (int i = 0; i < 4; i++) {
            int j = (tid + i * 512) * 16;
            cpasync16(smem_base + SM_B0 + (uint32_t)j, gB + j);
        }
        CP_COMMIT();
        __half2 zh = __float2half2_rn(sz[0][arow]);
        __half2 r0 = __hmax2(__hmul2(__hadd2(*(__half2*)&ra0.x, *(__half2*)&rb0.x), zh), hzero);
        __half2 r1 = __hmax2(__hmul2(__hadd2(*(__half2*)&ra0.y, *(__half2*)&rb0.y), zh), hzero);
        __half2 r2 = __hmax2(__hmul2(__hadd2(*(__half2*)&ra0.z, *(__half2*)&rb0.z), zh), hzero);
        __half2 r3 = __hmax2(__hmul2(__hadd2(*(__half2*)&ra0.w, *(__half2*)&rb0.w), zh), hzero);
        uint4 v;
        v.x = *(uint32_t*)&r0; v.y = *(uint32_t*)&r1;
        v.z = *(uint32_t*)&r2; v.w = *(uint32_t*)&r3;
        *(uint4*)(dsm + SM_A0 + a_sw0) = v;
        r0 = __hmax2(__hmul2(__hadd2(*(__half2*)&ra1.x, *(__half2*)&rb1.x), zh), hzero);
        r1 = __hmax2(__hmul2(__hadd2(*(__half2*)&ra1.y, *(__half2*)&rb1.y), zh), hzero);
        r2 = __hmax2(__hmul2(__hadd2(*(__half2*)&ra1.z, *(__half2*)&rb1.z), zh), hzero);
        r3 = __hmax2(__hmul2(__hadd2(*(__half2*)&ra1.w, *(__half2*)&rb1.w), zh), hzero);
        v.x = *(uint32_t*)&r0; v.y = *(uint32_t*)&r1;
        v.z = *(uint32_t*)&r2; v.w = *(uint32_t*)&r3;
        *(uint4*)(dsm + SM_A0 + a_sw1) = v;
        CP_WAIT0();
        __syncthreads();
    }

    for (int chunk = 0; chunk < NCHUNK; chunk++) {
        const int cur = chunk & 1;
        const int nxt = cur ^ 1;

        // ---- issue next chunk's loads (overlap with this chunk's MMA) ----
        if (chunk < NCHUNK - 1) {
            const int kc = (chunk + 1) * ECH;
            ra0 = *(const uint4*)(pd + kc + acol0);
            ra1 = *(const uint4*)(pd + kc + acol0 + 8);
            rb0 = *(const uint4*)(ps + kc + acol0);
            rb1 = *(const uint4*)(ps + kc + acol0 + 8);
            const char* gB = (const char*)(g_W2h + (size_t)(chunk + 1) * (EN * ECH));
#pragma unroll
            for (int i = 0; i < 4; i++) {
                int j = (tid + i * 512) * 16;
                cpasync16(smem_base + boff[nxt] + (uint32_t)j, gB + j);
            }
            CP_COMMIT();
        }

        // ---- MMA on current buffers ----
#pragma unroll
        for (int ks = 0; ks < 4; ks++) {
            uint32_t a[2][4];
#pragma unroll
            for (int mi = 0; mi < 2; mi++) {
                uint32_t row = (uint32_t)(m0w + mi * 16 + a_r);
                ldm4(a[mi], smem_base + aoff[cur] + SWZ128(row * 128 + (uint32_t)(ks * 32) + a_kb));
            }
#pragma unroll
            for (int ni = 0; ni < 8; ni++) {
                uint32_t nrow = (uint32_t)(n0w + ni * 8 + b_r);
                uint32_t b[2];
                ldm2(b, smem_base + boff[cur] + SWZ128(nrow * 128 + (uint32_t)(ks * 32) + b_kb));
                mma_f16(c[0][ni], a[0], b);
                mma_f16(c[1][ni], a[1], b);
            }
        }

        // ---- convert + store next A, drain cp.async ----
        if (chunk < NCHUNK - 1) {
            __half2 zh = __float2half2_rn(sz[(chunk + 1) >> 2][arow]);
            __half2 r0 = __hmax2(__hmul2(__hadd2(*(__half2*)&ra0.x, *(__half2*)&rb0.x), zh), hzero);
            __half2 r1 = __hmax2(__hmul2(__hadd2(*(__half2*)&ra0.y, *(__half2*)&rb0.y), zh), hzero);
            __half2 r2 = __hmax2(__hmul2(__hadd2(*(__half2*)&ra0.z, *(__half2*)&rb0.z), zh), hzero);
            __half2 r3 = __hmax2(__hmul2(__hadd2(*(__half2*)&ra0.w, *(__half2*)&rb0.w), zh), hzero);
            uint4 v;
            v.x = *(uint32_t*)&r0; v.y = *(uint32_t*)&r1;
            v.z = *(uint32_t*)&r2; v.w = *(uint32_t*)&r3;
            *(uint4*)(dsm + aoff[nxt] + a_sw0) = v;
            r0 = __hmax2(__hmul2(__hadd2(*(__half2*)&ra1.x, *(__half2*)&rb1.x), zh), hzero);
            r1 = __hmax2(__hmul2(__hadd2(*(__half2*)&ra1.y, *(__half2*)&rb1.y), zh), hzero);
            r2 = __hmax2(__hmul2(__hadd2(*(__half2*)&ra1.z, *(__half2*)&rb1.z), zh), hzero);
            r3 = __hmax2(__hmul2(__hadd2(*(__half2*)&ra1.w, *(__half2*)&rb1.w), zh), hzero);
            v.x = *(uint32_t*)&r0; v.y = *(uint32_t*)&r1;
            v.z = *(uint32_t*)&r2; v.w = *(uint32_t*)&r3;
            *(uint4*)(dsm + aoff[nxt] + a_sw1) = v;
            CP_WAIT0();
        }
        __syncthreads();
    }

    // ---- epilogue: fragments -> SMEM tile -> segmented reduce -> few atomics ----
    float* tile = (float*)dsm;
#pragma unroll
    for (int mi = 0; mi < 2; mi++) {
        int r0 = m0w + mi * 16 + (lane >> 2);
        int r1 = r0 + 8;
#pragma unroll
        for (int ni = 0; ni < 8; ni++) {
            int col = n0w + ni * 8 + 2 * (lane & 3);
            float* cc = c[mi][ni];
            *(float2*)&tile[r0 * TSTRIDE + col] = make_float2(cc[0], cc[1]);
            *(float2*)&tile[r1 * TSTRIDE + col] = make_float2(cc[2], cc[3]);
        }
    }
    __syncthreads();

    {
        const int col = tid & 255;
        const int half = tid >> 8;
        const int rbeg = half * 64;
        float acc = 0.f;
        int curn = sdst[rbeg];
#pragma unroll 4
        for (int r = rbeg; r < rbeg + 64; r++) {
            int d = sdst[r];
            float v = tile[r * TSTRIDE + col];
            if (d != curn) {
                atomicAdd(g_macc + (size_t)curn * 256 + col, acc);
                acc = 0.f;
                curn = d;
            }
            acc += v;
        }
        atomicAdd(g_macc + (size_t)curn * 256 + col, acc);
    }
}

// ---------------- GRU + output, resets macc to mbase ----------------
__global__ void k_gru(int t, const float* __restrict__ x,
                      const float* __restrict__ Wih, const float* __restrict__ bih,
                      const float* __restrict__ Wo, const float* __restrict__ bo,
                      float* __restrict__ out)
{
    int n = blockIdx.x;
    int i = threadIdx.x;
    __shared__ float sin6[6];
    __shared__ float sred[6][8];

    if (i < 6) sin6[i] = (t < TTEACH) ? x[(size_t)n * NFd + t * 6 + i] : g_prev[n * 6 + i];
    __syncthreads();

    float ic = g_invcnt[n];
    float m = g_macc[(size_t)n * 256 + i] * ic;
    g_macc[(size_t)n * 256 + i] = g_mbase[(size_t)n * 256 + i];

    float gxr = bih[i], gxz = bih[256 + i], gxn = bih[512 + i];
#pragma unroll
    for (int j = 0; j < 6; j++) {
        float xv = sin6[j];
        gxr += Wih[i * 6 + j] * xv;
        gxz += Wih[(256 + i) * 6 + j] * xv;
        gxn += Wih[(512 + i) * 6 + j] * xv;
    }
    size_t gb = (size_t)n * 768;
    float ghr = g_gh[gb + i], ghz = g_gh[gb + 256 + i], ghn = g_gh[gb + 512 + i];

    float r = 1.f / (1.f + expf(-(gxr + ghr)));
    float zg = 1.f / (1.f + expf(-(gxz + ghz)));
    float nn = tanhf(gxn + r * ghn);
    float hn = (1.f - zg) * nn + zg * m;
    g_h[(size_t)n * 256 + i] = hn;

#pragma unroll
    for (int j = 0; j < 6; j++) {
        float v = hn * Wo[i * 6 + j];
#pragma unroll
        for (int off = 16; off > 0; off >>= 1)
            v += __shfl_down_sync(0xffffffffu, v, off);
        if ((i & 31) == 0) sred[j][i >> 5] = v;
    }
    __syncthreads();
    if (i < 6) {
        float s = 0.f;
#pragma unroll
        for (int w = 0; w < 8; w++) s += sred[i][w];
        float mu = sin6[i] + fmaxf(s + bo[i], 0.f);
        out[(size_t)n * NFd + t * 6 + i] = mu;
        g_prev[n * 6 + i] = mu;
    }
}

// ---------------- launch ----------------
extern "C" void kernel_launch(void* const* d_in, const int* in_sizes, int n_in,
                              void* d_out, int out_size)
{
    const float* x   = (const float*)d_in[0];
    const void*  ei  = d_in[1];
    const float* z   = (const float*)d_in[2];
    const float* Wf  = (const float*)d_in[3];
    const float* bf  = (const float*)d_in[4];
    const float* W1  = (const float*)d_in[5];
    const float* b1  = (const float*)d_in[6];
    const float* W2  = (const float*)d_in[7];
    const float* b2  = (const float*)d_in[8];
    const float* Wih = (const float*)d_in[9];
    const float* bih = (const float*)d_in[10];
    const float* Whh = (const float*)d_in[11];
    const float* bhh = (const float*)d_in[12];
    const float* Wo  = (const float*)d_in[13];
    const float* bo  = (const float*)d_in[14];
    float* out = (float*)d_out;

    float *p_h, *p_macc, *p_gh, *p_W1ab, *p_biasab, *p_WhhT, *p_ic;
    __half *p_fh16, *p_AB16, *p_Wf16, *p_W1ab16, *p_WhhT16;
    cudaGetSymbolAddress((void**)&p_h, g_h);
    cudaGetSymbolAddress((void**)&p_macc, g_macc);
    cudaGetSymbolAddress((void**)&p_gh, g_gh);
    cudaGetSymbolAddress((void**)&p_W1ab, g_W1ab);
    cudaGetSymbolAddress((void**)&p_biasab, g_biasab);
    cudaGetSymbolAddress((void**)&p_WhhT, g_WhhT);
    cudaGetSymbolAddress((void**)&p_ic, g_invcnt);
    cudaGetSymbolAddress((void**)&p_fh16, g_fh16);
    cudaGetSymbolAddress((void**)&p_AB16, g_AB16);
    cudaGetSymbolAddress((void**)&p_Wf16, g_Wf16);
    cudaGetSymbolAddress((void**)&p_W1ab16, g_W1ab16);
    cudaGetSymbolAddress((void**)&p_WhhT16, g_WhhT16);

    static int smem_set = 0;
    if (!smem_set) {
        cudaFuncSetAttribute(k_edge_mma, cudaFuncAttributeMaxDynamicSharedMemorySize,
                             SM_EDGE_TOTAL);
        smem_set = 1;
    }

    k_init<<<512, 256>>>();
    k_detect<<<512, 256>>>((const int*)ei);
    k_extract<<<(Ee + 255) / 256, 256>>>(ei);
    k_hist<<<(Ee + 255) / 256, 256>>>();
    k_cnt<<<(Nn + 255) / 256, 256>>>();
    k_scan<<<1, 512>>>();
    k_place<<<(Ee + 255) / 256, 256>>>(z);
    k_b2base<<<(Nn * 256 + 255) / 256, 256>>>(b2);
    k_pack_w1<<<(192 * 1536 + 255) / 256, 256>>>(W1, b1);
    k_pack_whh<<<(256 * 768 + 255) / 256, 256>>>(Whh);
    k_pack_w2<<<(NCHUNK * EN * ECH + 255) / 256, 256>>>(W2);
    k_pack_b16<<<(256 * 192 + 255) / 256, 256>>>(Wf, p_Wf16, 256, 192);
    k_pack_b16<<<(192 * 1536 + 255) / 256, 256>>>(p_W1ab, p_W1ab16, 192, 1536);
    k_pack_b16<<<(256 * 768 + 255) / 256, 256>>>(p_WhhT, p_WhhT16, 256, 768);

    dim3 gfh((Nn + 127) / 128, 192 / 64);
    dim3 gab((Nn + 127) / 128, 1536 / 64);
    dim3 ggh((Nn + 127) / 128, 768 / 64);
    int  gedge = Ee / EM;

    for (int t = 0; t < Tt; t++) {
        k_gemm16<<<gfh, 256>>>(p_h, p_Wf16, bf, p_fh16,
                               Nn, 256, 192, nullptr, 1, 0, 1);
        k_gemm16<<<gab, 256>>>(p_fh16, p_W1ab16, p_biasab, p_AB16,
                               Nn, 192, 1536, nullptr, 0, 1, 1);
        k_edge_mma<<<gedge, 512, SM_EDGE_TOTAL>>>();
        k_gemm16<<<ggh, 256>>>(p_macc, p_WhhT16, bhh, p_gh,
                               Nn, 256, 768, p_ic, 0, 0, 0);
        k_gru<<<Nn, 256>>>(t, x, Wih, bih, Wo, bo, out);
    }
}

// round 8
// speedup vs baseline: 4.8214x; 1.0817x over previous
#include <cuda_runtime.h>
#include <cuda_fp16.h>
#include <cstdint>

// ---------------- problem constants ----------------
#define Nn 10000
#define Ee 160000
#define Tt 32
#define Hh 256
#define NFd 192            // T*6
#define TTEACH 24

// edge-GEMM tiling
#define EM 64              // edges per CTA (2 CTAs/SM)
#define EN 256
#define EK 768
#define ECH 64
#define NCHUNK (EK/ECH)    // 12

// edge dynamic SMEM: A(2x8KB)+B(2x32KB)=80KB; epilogue tile 64x258 fp32=66KB reuses it
#define SM_A0 0
#define SM_A1 8192
#define SM_B0 16384
#define SM_B1 49152
#define SM_EDGE_TOTAL 81920
#define TSTRIDE 258

// node GEMM smem: 2x16KB A + 2x8KB B = 48KB (dynamic)
#define GM_A0 0
#define GM_A1 16384
#define GM_B0 32768
#define GM_B1 40960
#define SM_GEMM_TOTAL 49152

// ---------------- device scratch ----------------
static __device__ float  g_h[Nn * Hh];
static __device__ float  g_prev[Nn * 6];
static __device__ __half g_fh16[Nn * NFd];
static __device__ __half g_AB16[Nn * 1536];
static __device__ float  g_macc[Nn * Hh];
static __device__ float  g_mbase[Nn * Hh];
static __device__ float  g_gh[Nn * 768];
static __device__ float  g_W1ab[192 * 1536];
static __device__ float  g_biasab[1536];
static __device__ float  g_WhhT[256 * 768];
static __device__ float  g_invcnt[Nn];
static __device__ float  g_zsum[Nn * 3];
static __device__ int    g_deg[Nn];
static __device__ int    g_base[Nn + 1];
static __device__ int    g_cur[Nn];
static __device__ int    g_src[Ee];
static __device__ int    g_dst[Ee];
static __device__ int    g_srcs[Ee];
static __device__ int    g_dsts[Ee];
static __device__ float  g_zs[3 * Ee];
static __device__ int    g_is32;
static __device__ __half g_Wf16[256 * 192];
static __device__ __half g_W1ab16[192 * 1536];
static __device__ __half g_WhhT16[256 * 768];
static __device__ __half g_W2h[NCHUNK * EN * ECH];

// ---------------- helpers ----------------
__device__ __forceinline__ uint32_t smem_u32(const void* p) {
    uint32_t a;
    asm("{ .reg .u64 t; cvta.to.shared.u64 t, %1; cvt.u32.u64 %0, t; }" : "=r"(a) : "l"(p));
    return a;
}
#define SWZ128(off) ((off) ^ (((off) >> 3) & 0x70))

__device__ __forceinline__ void ldm4(uint32_t* r, uint32_t addr) {
    asm volatile("ldmatrix.sync.aligned.m8n8.x4.shared.b16 {%0,%1,%2,%3}, [%4];"
                 : "=r"(r[0]), "=r"(r[1]), "=r"(r[2]), "=r"(r[3]) : "r"(addr));
}
__device__ __forceinline__ void ldm2(uint32_t* r, uint32_t addr) {
    asm volatile("ldmatrix.sync.aligned.m8n8.x2.shared.b16 {%0,%1}, [%2];"
                 : "=r"(r[0]), "=r"(r[1]) : "r"(addr));
}
__device__ __forceinline__ void mma_f16(float* c, const uint32_t* a, const uint32_t* b) {
    asm volatile(
        "mma.sync.aligned.m16n8k16.row.col.f32.f16.f16.f32 "
        "{%0,%1,%2,%3}, {%4,%5,%6,%7}, {%8,%9}, {%0,%1,%2,%3};"
        : "+f"(c[0]), "+f"(c[1]), "+f"(c[2]), "+f"(c[3])
        : "r"(a[0]), "r"(a[1]), "r"(a[2]), "r"(a[3]), "r"(b[0]), "r"(b[1]));
}
__device__ __forceinline__ void cpasync16(uint32_t smem_addr, const void* gptr) {
    asm volatile("cp.async.cg.shared.global [%0], [%1], 16;"
                 :: "r"(smem_addr), "l"(gptr) : "memory");
}
#define CP_COMMIT() asm volatile("cp.async.commit_group;" ::: "memory")
#define CP_WAIT0()  asm volatile("cp.async.wait_group 0;" ::: "memory")

// ---------------- setup kernels ----------------
__global__ void k_init() {
    int i = blockIdx.x * blockDim.x + threadIdx.x;
    int st = gridDim.x * blockDim.x;
    for (int j = i; j < Nn * Hh; j += st) g_h[j] = 0.f;
    for (int j = i; j < Nn * 6; j += st) g_prev[j] = 0.f;
    for (int j = i; j < Nn; j += st) g_deg[j] = 0;
    for (int j = i; j < Nn * 3; j += st) g_zsum[j] = 0.f;
    if (i == 0) g_is32 = 0;
}

__global__ void k_detect(const int* __restrict__ w) {
    int i = blockIdx.x * blockDim.x + threadIdx.x;
    int st = gridDim.x * blockDim.x;
    for (int j = i; j < 2 * Ee; j += st) {
        if ((j & 1) && w[j] != 0) g_is32 = 1;
    }
}

__global__ void k_extract(const void* __restrict__ eiraw) {
    int e = blockIdx.x * blockDim.x + threadIdx.x;
    if (e >= Ee) return;
    if (g_is32) {
        const int* p = (const int*)eiraw;
        g_src[e] = p[e];
        g_dst[e] = p[Ee + e];
    } else {
        const long long* p = (const long long*)eiraw;
        g_src[e] = (int)p[e];
        g_dst[e] = (int)p[Ee + e];
    }
}

__global__ void k_hist() {
    int e = blockIdx.x * blockDim.x + threadIdx.x;
    if (e < Ee) atomicAdd(&g_deg[g_dst[e]], 1);
}

__global__ void k_cnt() {
    int n = blockIdx.x * blockDim.x + threadIdx.x;
    if (n < Nn) g_invcnt[n] = 1.f / fmaxf((float)g_deg[n], 1.f);
}

__global__ void k_scan() {
    __shared__ int part[512];
    const int tid = threadIdx.x;
    const int per = (Nn + 511) / 512;
    int start = tid * per;
    int s = 0;
    for (int j = 0; j < per; j++) {
        int idx = start + j;
        if (idx < Nn) s += g_deg[idx];
    }
    part[tid] = s;
    __syncthreads();
    if (tid == 0) {
        int acc = 0;
        for (int i = 0; i < 512; i++) { int v = part[i]; part[i] = acc; acc += v; }
    }
    __syncthreads();
    int acc = part[tid];
    for (int j = 0; j < per; j++) {
        int idx = start + j;
        if (idx < Nn) { g_base[idx] = acc; g_cur[idx] = acc; acc += g_deg[idx]; }
    }
    if (tid == 511) g_base[Nn] = acc;
}

__global__ void k_place(const float* __restrict__ z) {
    int e = blockIdx.x * blockDim.x + threadIdx.x;
    if (e >= Ee) return;
    int d = g_dst[e];
    int pos = atomicAdd(&g_cur[d], 1);
    g_srcs[pos] = g_src[e];
    g_dsts[pos] = d;
    float z1 = z[(size_t)e * 4 + 1];
    float z2 = z[(size_t)e * 4 + 2];
    float z3 = z[(size_t)e * 4 + 3];
    g_zs[pos] = z1;
    g_zs[Ee + pos] = z2;
    g_zs[2 * Ee + pos] = z3;
    atomicAdd(&g_zsum[d * 3 + 0], z1);
    atomicAdd(&g_zsum[d * 3 + 1], z2);
    atomicAdd(&g_zsum[d * 3 + 2], z3);
}

__global__ void k_b2base(const float* __restrict__ b2) {
    int idx = blockIdx.x * blockDim.x + threadIdx.x;
    if (idx >= Nn * 256) return;
    int n = idx >> 8, c = idx & 255;
    float v = g_zsum[n * 3 + 0] * b2[c]
            + g_zsum[n * 3 + 1] * b2[256 + c]
            + g_zsum[n * 3 + 2] * b2[512 + c];
    g_mbase[idx] = v;
    g_macc[idx] = v;
}

__global__ void k_pack_w1(const float* __restrict__ W1, const float* __restrict__ b1) {
    int idx = blockIdx.x * blockDim.x + threadIdx.x;
    if (idx < 192 * 1536) {
        int row = idx / 1536, c = idx % 1536;
        float v;
        if (c < 768) {
            int k = c >> 8, j = c & 255;
            v = W1[k * 98304 + row * 256 + j];
        } else {
            int c2 = c - 768;
            int k = c2 >> 8, j = c2 & 255;
            v = W1[k * 98304 + (row + 192) * 256 + j];
        }
        g_W1ab[idx] = v;
    }
    if (idx < 1536) g_biasab[idx] = (idx < 768) ? b1[idx] : 0.f;
}

__global__ void k_pack_whh(const float* __restrict__ Whh) {
    int idx = blockIdx.x * blockDim.x + threadIdx.x;
    if (idx >= 256 * 768) return;
    int kk = idx / 768, g = idx % 768;
    g_WhhT[idx] = Whh[g * 256 + kk];
}

__global__ void k_pack_b16(const float* __restrict__ src, __half* __restrict__ dst,
                           int Kd, int Nd) {
    int idx = blockIdx.x * blockDim.x + threadIdx.x;
    if (idx >= Kd * Nd) return;
    int k = idx / Nd, n = idx % Nd;
    int kc = k >> 6, kk = k & 63, nb = n >> 6, nn = n & 63;
    int tile = kc * (Nd >> 6) + nb;
    uint32_t off = SWZ128((uint32_t)(nn * 128 + kk * 2));
    dst[(size_t)tile * 4096 + off / 2] = __float2half_rn(src[idx]);
}

__global__ void k_pack_w2(const float* __restrict__ W2) {
    int idx = blockIdx.x * blockDim.x + threadIdx.x;
    if (idx >= NCHUNK * EN * ECH) return;
    int chunk = idx / (EN * ECH);
    int rem = idx % (EN * ECH);
    int n = rem / ECH, k = rem % ECH;
    float w = W2[(size_t)(chunk * ECH + k) * 256 + n];
    uint32_t off = SWZ128((uint32_t)(n * 128 + k * 2));
    g_W2h[(size_t)chunk * (EN * ECH) + off / 2] = __float2half_rn(w);
}

// ---------------- unified fp16 tensor-core GEMM (pipelined) ----------------
// C[M,Nd] = act( fp16(rowscale(A)) @ B + bias ). BM=128 BN=64 BK=64, 256 thr.
// Double-buffered: B via cp.async; A reg-prefetch (fp16 path) or direct (fp32).
__global__ void __launch_bounds__(256) k_gemm16(
    const void* __restrict__ A, const __half* __restrict__ Bpk,
    const float* __restrict__ bias, void* __restrict__ C,
    int M, int Kd, int Nd, const float* __restrict__ rowscale,
    int relu, int a_fp16, int c_fp16)
{
    extern __shared__ char gsm[];
    const uint32_t smem_base = smem_u32(gsm);

    const int tid = threadIdx.x;
    const int wid = tid >> 5;
    const int lane = tid & 31;
    const int m0 = blockIdx.x * 128;
    const int nblk = blockIdx.y;
    const int n0 = nblk * 64;
    const int nblocks = Nd >> 6;
    const int niter = Kd >> 6;

    const int m0w = (wid >> 1) * 32;
    const int n0w = (wid & 1) * 32;

    float c[2][4][4];
#pragma unroll
    for (int mi = 0; mi < 2; mi++)
#pragma unroll
        for (int ni = 0; ni < 4; ni++)
#pragma unroll
            for (int r = 0; r < 4; r++) c[mi][ni][r] = 0.f;

    const int arow = tid >> 1;
    const int acol0 = (tid & 1) * 32;
    const int am = m0 + arow;
    const bool av = am < M;
    float rs = 1.f;
    if (rowscale && av) rs = rowscale[am];
    const uint32_t a_sw[4] = {
        SWZ128((uint32_t)(arow * 128 + acol0 * 2)),
        SWZ128((uint32_t)(arow * 128 + (acol0 + 8) * 2)),
        SWZ128((uint32_t)(arow * 128 + (acol0 + 16) * 2)),
        SWZ128((uint32_t)(arow * 128 + (acol0 + 24) * 2))
    };

    const int a_r = lane & 15;
    const uint32_t a_kb = (uint32_t)((lane >> 4) << 4);
    const int b_r = lane & 7;
    const uint32_t b_kb = (uint32_t)(((lane >> 3) & 1) << 4);

    const uint32_t aoff[2] = {GM_A0, GM_A1};
    const uint32_t boff[2] = {GM_B0, GM_B1};

    // stage A chunk kt into buffer bi
    auto stageA = [&](int kt, int bi) {
        if (a_fp16) {
            const __half* Ah = (const __half*)A + (size_t)am * Kd + kt;
#pragma unroll
            for (int i = 0; i < 4; i++) {
                uint4 v = make_uint4(0u, 0u, 0u, 0u);
                if (av) v = *(const uint4*)(Ah + acol0 + i * 8);
                *(uint4*)(gsm + aoff[bi] + a_sw[i]) = v;
            }
        } else {
            const float* Af = (const float*)A + (size_t)am * Kd + kt;
#pragma unroll
            for (int i = 0; i < 4; i++) {
                uint4 v = make_uint4(0u, 0u, 0u, 0u);
                if (av) {
                    float4 f0 = *(const float4*)(Af + acol0 + i * 8);
                    float4 f1 = *(const float4*)(Af + acol0 + i * 8 + 4);
                    __half2 h0 = __floats2half2_rn(f0.x * rs, f0.y * rs);
                    __half2 h1 = __floats2half2_rn(f0.z * rs, f0.w * rs);
                    __half2 h2 = __floats2half2_rn(f1.x * rs, f1.y * rs);
                    __half2 h3 = __floats2half2_rn(f1.z * rs, f1.w * rs);
                    v.x = *(uint32_t*)&h0; v.y = *(uint32_t*)&h1;
                    v.z = *(uint32_t*)&h2; v.w = *(uint32_t*)&h3;
                }
                *(uint4*)(gsm + aoff[bi] + a_sw[i]) = v;
            }
        }
    };
    auto issueB = [&](int kt, int bi) {
        const char* gB = (const char*)(Bpk + (size_t)((kt >> 6) * nblocks + nblk) * 4096);
        int j0 = tid * 16;
        cpasync16(smem_base + boff[bi] + (uint32_t)j0, gB + j0);
        cpasync16(smem_base + boff[bi] + (uint32_t)(j0 + 4096), gB + j0 + 4096);
        CP_COMMIT();
    };

    // prologue
    issueB(0, 0);
    stageA(0, 0);
    CP_WAIT0();
    __syncthreads();

    for (int it = 0; it < niter; it++) {
        const int cur = it & 1;
        const int nxt = cur ^ 1;
        if (it + 1 < niter) issueB((it + 1) << 6, nxt);

#pragma unroll
        for (int ks = 0; ks < 4; ks++) {
            uint32_t a[2][4];
#pragma unroll
            for (int mi = 0; mi < 2; mi++) {
                uint32_t row = (uint32_t)(m0w + mi * 16 + a_r);
                ldm4(a[mi], smem_base + aoff[cur] + SWZ128(row * 128 + (uint32_t)(ks * 32) + a_kb));
            }
#pragma unroll
            for (int ni = 0; ni < 4; ni++) {
                uint32_t nrow = (uint32_t)(n0w + ni * 8 + b_r);
                uint32_t b[2];
                ldm2(b, smem_base + boff[cur] + SWZ128(nrow * 128 + (uint32_t)(ks * 32) + b_kb));
                mma_f16(c[0][ni], a[0], b);
                mma_f16(c[1][ni], a[1], b);
            }
        }

        if (it + 1 < niter) {
            stageA((it + 1) << 6, nxt);
            CP_WAIT0();
        }
        __syncthreads();
    }

#pragma unroll
    for (int mi = 0; mi < 2; mi++) {
        int r0 = m0 + m0w + mi * 16 + (lane >> 2);
        int r1 = r0 + 8;
#pragma unroll
        for (int ni = 0; ni < 4; ni++) {
            int col = n0 + n0w + ni * 8 + 2 * (lane & 3);
            float bv0 = bias[col], bv1 = bias[col + 1];
            float* cc = c[mi][ni];
            float o00 = cc[0] + bv0, o01 = cc[1] + bv1;
            float o10 = cc[2] + bv0, o11 = cc[3] + bv1;
            if (relu) {
                o00 = fmaxf(o00, 0.f); o01 = fmaxf(o01, 0.f);
                o10 = fmaxf(o10, 0.f); o11 = fmaxf(o11, 0.f);
            }
            if (c_fp16) {
                __half* Ch = (__half*)C;
                if (r0 < M) {
                    __half2 h = __floats2half2_rn(o00, o01);
                    *(__half2*)(Ch + (size_t)r0 * Nd + col) = h;
                }
                if (r1 < M) {
                    __half2 h = __floats2half2_rn(o10, o11);
                    *(__half2*)(Ch + (size_t)r1 * Nd + col) = h;
                }
            } else {
                float* Cf = (float*)C;
                if (r0 < M) *(float2*)(Cf + (size_t)r0 * Nd + col) = make_float2(o00, o01);
                if (r1 < M) *(float2*)(Cf + (size_t)r1 * Nd + col) = make_float2(o10, o11);
            }
        }
    }
}

// ---------------- edge GEMM: 64x256 tiles, 2 CTAs/SM, pipelined ----------------
__global__ void __launch_bounds__(256, 2)
k_edge_mma()
{
    extern __shared__ char dsm[];
    __shared__ int sdst[EM];
    __shared__ float sz[3][EM];

    const uint32_t smem_base = smem_u32(dsm);
    const int tid = threadIdx.x;
    const int wid = tid >> 5;
    const int lane = tid & 31;
    const int e0 = blockIdx.x * EM;

    if (tid < EM) {
        sdst[tid] = g_dsts[e0 + tid];
        sz[0][tid] = g_zs[e0 + tid];
        sz[1][tid] = g_zs[Ee + e0 + tid];
        sz[2][tid] = g_zs[2 * Ee + e0 + tid];
    }
    __syncthreads();

    const int m0w = (wid >> 2) * 32;    // 2 M groups
    const int n0w = (wid & 3) * 64;     // 4 N groups

    float c[2][8][4];
#pragma unroll
    for (int mi = 0; mi < 2; mi++)
#pragma unroll
        for (int ni = 0; ni < 8; ni++)
#pragma unroll
            for (int r = 0; r < 4; r++) c[mi][ni][r] = 0.f;

    // A build: 4 threads per edge row, 16 fp16 cols each (64 rows x 4 = 256)
    const int arow = tid >> 2;
    const int acol0 = (tid & 3) * 16;
    const int srow = g_srcs[e0 + arow];
    const __half* pd = g_AB16 + (size_t)sdst[arow] * 1536;
    const __half* ps = g_AB16 + (size_t)srow * 1536 + 768;
    const uint32_t a_sw0 = SWZ128((uint32_t)(arow * 128 + acol0 * 2));
    const uint32_t a_sw1 = SWZ128((uint32_t)(arow * 128 + (acol0 + 8) * 2));

    const int a_r = lane & 15;
    const uint32_t a_kb = (uint32_t)((lane >> 4) << 4);
    const int b_r = lane & 7;
    const uint32_t b_kb = (uint32_t)(((lane >> 3) & 1) << 4);

    const __half2 hzero = __float2half2_rn(0.f);
    const uint32_t aoff[2] = {SM_A0, SM_A1};
    const uint32_t boff[2] = {SM_B0, SM_B1};

    uint4 ra0, ra1, rb0, rb1;

    auto convStoreA = [&](int chunk, int bi) {
        __half2 zh = __float2half2_rn(sz[chunk >> 2][arow]);
        __half2 r0 = __hmax2(__hmul2(__hadd2(*(__half2*)&ra0.x, *(__half2*)&rb0.x), zh), hzero);
        __half2 r1 = __hmax2(__hmul2(__hadd2(*(__half2*)&ra0.y, *(__half2*)&rb0.y), zh), hzero);
        __half2 r2 = __hmax2(__hmul2(__hadd2(*(__half2*)&ra0.z, *(__half2*)&rb0.z), zh), hzero);
        __half2 r3 = __hmax2(__hmul2(__hadd2(*(__half2*)&ra0.w, *(__half2*)&rb0.w), zh), hzero);
        uint4 v;
        v.x = *(uint32_t*)&r0; v.y = *(uint32_t*)&r1;
        v.z = *(uint32_t*)&r2; v.w = *(uint32_t*)&r3;
        *(uint4*)(dsm + aoff[bi] + a_sw0) = v;
        r0 = __hmax2(__hmul2(__hadd2(*(__half2*)&ra1.x, *(__half2*)&rb1.x), zh), hzero);
        r1 = __hmax2(__hmul2(__hadd2(*(__half2*)&ra1.y, *(__half2*)&rb1.y), zh), hzero);
        r2 = __hmax2(__hmul2(__hadd2(*(__half2*)&ra1.z, *(__half2*)&rb1.z), zh), hzero);
        r3 = __hmax2(__hmul2(__hadd2(*(__half2*)&ra1.w, *(__half2*)&rb1.w), zh), hzero);
        v.x = *(uint32_t*)&r0; v.y = *(uint32_t*)&r1;
        v.z = *(uint32_t*)&r2; v.w = *(uint32_t*)&r3;
        *(uint4*)(dsm + aoff[bi] + a_sw1) = v;
    };
    auto loadA = [&](int chunk) {
        const int kc = chunk * ECH;
        ra0 = *(const uint4*)(pd + kc + acol0);
        ra1 = *(const uint4*)(pd + kc + acol0 + 8);
        rb0 = *(const uint4*)(ps + kc + acol0);
        rb1 = *(const uint4*)(ps + kc + acol0 + 8);
    };
    auto issueB = [&](int chunk, int bi) {
        const char* gB = (const char*)(g_W2h + (size_t)chunk * (EN * ECH));
#pragma unroll
        for (int i = 0; i < 8; i++) {
            int j = (tid + i * 256) * 16;
            cpasync16(smem_base + boff[bi] + (uint32_t)j, gB + j);
        }
        CP_COMMIT();
    };

    // prologue: chunk 0
    loadA(0);
    issueB(0, 0);
    convStoreA(0, 0);
    CP_WAIT0();
    __syncthreads();

    for (int chunk = 0; chunk < NCHUNK; chunk++) {
        const int cur = chunk & 1;
        const int nxt = cur ^ 1;

        if (chunk < NCHUNK - 1) {
            loadA(chunk + 1);
            issueB(chunk + 1, nxt);
        }

#pragma unroll
        for (int ks = 0; ks < 4; ks++) {
            uint32_t a[2][4];
#pragma unroll
            for (int mi = 0; mi < 2; mi++) {
                uint32_t row = (uint32_t)(m0w + mi * 16 + a_r);
                ldm4(a[mi], smem_base + aoff[cur] + SWZ128(row * 128 + (uint32_t)(ks * 32) + a_kb));
            }
#pragma unroll
            for (int ni = 0; ni < 8; ni++) {
                uint32_t nrow = (uint32_t)(n0w + ni * 8 + b_r);
                uint32_t b[2];
                ldm2(b, smem_base + boff[cur] + SWZ128(nrow * 128 + (uint32_t)(ks * 32) + b_kb));
                mma_f16(c[0][ni], a[0], b);
                mma_f16(c[1][ni], a[1], b);
            }
        }

        if (chunk < NCHUNK - 1) {
            convStoreA(chunk + 1, nxt);
            CP_WAIT0();
        }
        __syncthreads();
    }

    // ---- epilogue: fragments -> SMEM tile (64x258) -> segmented reduce ----
    float* tile = (float*)dsm;
#pragma unroll
    for (int mi = 0; mi < 2; mi++) {
        int r0 = m0w + mi * 16 + (lane >> 2);
        int r1 = r0 + 8;
#pragma unroll
        for (int ni = 0; ni < 8; ni++) {
            int col = n0w + ni * 8 + 2 * (lane & 3);
            float* cc = c[mi][ni];
            *(float2*)&tile[r0 * TSTRIDE + col] = make_float2(cc[0], cc[1]);
            *(float2*)&tile[r1 * TSTRIDE + col] = make_float2(cc[2], cc[3]);
        }
    }
    __syncthreads();

    {
        const int col = tid;     // 256 threads = 256 cols
        float acc = 0.f;
        int curn = sdst[0];
#pragma unroll 4
        for (int r = 0; r < EM; r++) {
            int d = sdst[r];
            float v = tile[r * TSTRIDE + col];
            if (d != curn) {
                atomicAdd(g_macc + (size_t)curn * 256 + col, acc);
                acc = 0.f;
                curn = d;
            }
            acc += v;
        }
        atomicAdd(g_macc + (size_t)curn * 256 + col, acc);
    }
}

// ---------------- GRU + output, resets macc to mbase ----------------
__global__ void k_gru(int t, const float* __restrict__ x,
                      const float* __restrict__ Wih, const float* __restrict__ bih,
                      const float* __restrict__ Wo, const float* __restrict__ bo,
                      float* __restrict__ out)
{
    int n = blockIdx.x;
    int i = threadIdx.x;
    __shared__ float sin6[6];
    __shared__ float sred[6][8];

    if (i < 6) sin6[i] = (t < TTEACH) ? x[(size_t)n * NFd + t * 6 + i] : g_prev[n * 6 + i];
    __syncthreads();

    float ic = g_invcnt[n];
    float m = g_macc[(size_t)n * 256 + i] * ic;
    g_macc[(size_t)n * 256 + i] = g_mbase[(size_t)n * 256 + i];

    float gxr = bih[i], gxz = bih[256 + i], gxn = bih[512 + i];
#pragma unroll
    for (int j = 0; j < 6; j++) {
        float xv = sin6[j];
        gxr += Wih[i * 6 + j] * xv;
        gxz += Wih[(256 + i) * 6 + j] * xv;
        gxn += Wih[(512 + i) * 6 + j] * xv;
    }
    size_t gb = (size_t)n * 768;
    float ghr = g_gh[gb + i], ghz = g_gh[gb + 256 + i], ghn = g_gh[gb + 512 + i];

    float r = 1.f / (1.f + expf(-(gxr + ghr)));
    float zg = 1.f / (1.f + expf(-(gxz + ghz)));
    float nn = tanhf(gxn + r * ghn);
    float hn = (1.f - zg) * nn + zg * m;
    g_h[(size_t)n * 256 + i] = hn;

#pragma unroll
    for (int j = 0; j < 6; j++) {
        float v = hn * Wo[i * 6 + j];
#pragma unroll
        for (int off = 16; off > 0; off >>= 1)
            v += __shfl_down_sync(0xffffffffu, v, off);
        if ((i & 31) == 0) sred[j][i >> 5] = v;
    }
    __syncthreads();
    if (i < 6) {
        float s = 0.f;
#pragma unroll
        for (int w = 0; w < 8; w++) s += sred[i][w];
        float mu = sin6[i] + fmaxf(s + bo[i], 0.f);
        out[(size_t)n * NFd + t * 6 + i] = mu;
        g_prev[n * 6 + i] = mu;
    }
}

// ---------------- launch ----------------
extern "C" void kernel_launch(void* const* d_in, const int* in_sizes, int n_in,
                              void* d_out, int out_size)
{
    const float* x   = (const float*)d_in[0];
    const void*  ei  = d_in[1];
    const float* z   = (const float*)d_in[2];
    const float* Wf  = (const float*)d_in[3];
    const float* bf  = (const float*)d_in[4];
    const float* W1  = (const float*)d_in[5];
    const float* b1  = (const float*)d_in[6];
    const float* W2  = (const float*)d_in[7];
    const float* b2  = (const float*)d_in[8];
    const float* Wih = (const float*)d_in[9];
    const float* bih = (const float*)d_in[10];
    const float* Whh = (const float*)d_in[11];
    const float* bhh = (const float*)d_in[12];
    const float* Wo  = (const float*)d_in[13];
    const float* bo  = (const float*)d_in[14];
    float* out = (float*)d_out;

    float *p_h, *p_macc, *p_gh, *p_W1ab, *p_biasab, *p_WhhT, *p_ic;
    __half *p_fh16, *p_AB16, *p_Wf16, *p_W1ab16, *p_WhhT16;
    cudaGetSymbolAddress((void**)&p_h, g_h);
    cudaGetSymbolAddress((void**)&p_macc, g_macc);
    cudaGetSymbolAddress((void**)&p_gh, g_gh);
    cudaGetSymbolAddress((void**)&p_W1ab, g_W1ab);
    cudaGetSymbolAddress((void**)&p_biasab, g_biasab);
    cudaGetSymbolAddress((void**)&p_WhhT, g_WhhT);
    cudaGetSymbolAddress((void**)&p_ic, g_invcnt);
    cudaGetSymbolAddress((void**)&p_fh16, g_fh16);
    cudaGetSymbolAddress((void**)&p_AB16, g_AB16);
    cudaGetSymbolAddress((void**)&p_Wf16, g_Wf16);
    cudaGetSymbolAddress((void**)&p_W1ab16, g_W1ab16);
    cudaGetSymbolAddress((void**)&p_WhhT16, g_WhhT16);

    static int smem_set = 0;
    if (!smem_set) {
        cudaFuncSetAttribute(k_edge_mma, cudaFuncAttributeMaxDynamicSharedMemorySize,
                             SM_EDGE_TOTAL);
        cudaFuncSetAttribute(k_gemm16, cudaFuncAttributeMaxDynamicSharedMemorySize,
                             SM_GEMM_TOTAL);
        smem_set = 1;
    }

    k_init<<<512, 256>>>();
    k_detect<<<512, 256>>>((const int*)ei);
    k_extract<<<(Ee + 255) / 256, 256>>>(ei);
    k_hist<<<(Ee + 255) / 256, 256>>>();
    k_cnt<<<(Nn + 255) / 256, 256>>>();
    k_scan<<<1, 512>>>();
    k_place<<<(Ee + 255) / 256, 256>>>(z);
    k_b2base<<<(Nn * 256 + 255) / 256, 256>>>(b2);
    k_pack_w1<<<(192 * 1536 + 255) / 256, 256>>>(W1, b1);
    k_pack_whh<<<(256 * 768 + 255) / 256, 256>>>(Whh);
    k_pack_w2<<<(NCHUNK * EN * ECH + 255) / 256, 256>>>(W2);
    k_pack_b16<<<(256 * 192 + 255) / 256, 256>>>(Wf, p_Wf16, 256, 192);
    k_pack_b16<<<(192 * 1536 + 255) / 256, 256>>>(p_W1ab, p_W1ab16, 192, 1536);
    k_pack_b16<<<(256 * 768 + 255) / 256, 256>>>(p_WhhT, p_WhhT16, 256, 768);

    dim3 gfh((Nn + 127) / 128, 192 / 64);
    dim3 gab((Nn + 127) / 128, 1536 / 64);
    dim3 ggh((Nn + 127) / 128, 768 / 64);
    int  gedge = Ee / EM;   // 2500

    for (int t = 0; t < Tt; t++) {
        k_gemm16<<<gfh, 256, SM_GEMM_TOTAL>>>(p_h, p_Wf16, bf, p_fh16,
                               Nn, 256, 192, nullptr, 1, 0, 1);
        k_gemm16<<<gab, 256, SM_GEMM_TOTAL>>>(p_fh16, p_W1ab16, p_biasab, p_AB16,
                               Nn, 192, 1536, nullptr, 0, 1, 1);
        k_edge_mma<<<gedge, 256, SM_EDGE_TOTAL>>>();
        k_gemm16<<<ggh, 256, SM_GEMM_TOTAL>>>(p_macc, p_WhhT16, bhh, p_gh,
                               Nn, 256, 768, p_ic, 0, 0, 0);
        k_gru<<<Nn, 256>>>(t, x, Wih, bih, Wo, bo, out);
    }
}

// round 9
// speedup vs baseline: 5.0906x; 1.0558x over previous
#include <cuda_runtime.h>
#include <cuda_fp16.h>
#include <cstdint>

// ---------------- problem constants ----------------
#define Nn 10000
#define Ee 160000
#define Tt 32
#define Hh 256
#define NFd 192
#define TTEACH 24
#define MST 320            // macc row stride (256 msg + 6 inputs + pad)

// edge-GEMM tiling
#define EM 64
#define EN 256
#define EK 768
#define ECH 64
#define NCHUNK (EK/ECH)

#define SM_A0 0
#define SM_A1 8192
#define SM_B0 16384
#define SM_B1 49152
#define SM_EDGE_TOTAL 81920
#define TSTRIDE 258

// node GEMM smem
#define GM_A0 0
#define GM_A1 16384
#define GM_B0 32768
#define GM_B1 40960
#define SM_GEMM_TOTAL 49152

// ---------------- device scratch ----------------
static __device__ float  g_h[Nn * Hh];
static __device__ __half g_fh16[Nn * NFd];
static __device__ __half g_AB16[Nn * 1536];
static __device__ float  g_macc[Nn * MST];       // [msg 256 | inputs*cnt 6 | pad]
static __device__ float  g_mbase[Nn * Hh];
static __device__ float  g_gh[Nn * 1024];        // [r~ | z~ | nh | nx]
static __device__ float  g_W1ab[192 * 1536];
static __device__ float  g_biasab[1536];
static __device__ float  g_invcnt[Nn];
static __device__ float  g_cntf[Nn];
static __device__ float  g_zsum[Nn * 3];
static __device__ int    g_deg[Nn];
static __device__ int    g_base[Nn + 1];
static __device__ int    g_cur[Nn];
static __device__ int    g_src[Ee];
static __device__ int    g_dst[Ee];
static __device__ int    g_srcs[Ee];
static __device__ int    g_dsts[Ee];
static __device__ float  g_zs[3 * Ee];
static __device__ int    g_is32;
static __device__ float  g_fhmu[Nn * 6];
static __device__ float  g_in6[Nn * 6];
// weight staging + fp16 packs
static __device__ float  g_WfXF[256 * 256];
static __device__ float  g_biasWfX[256];
static __device__ float  g_WhxF[320 * 1024];
static __device__ float  g_biasWhx[1024];
static __device__ __half g_WfX16[256 * 256];
static __device__ __half g_W1ab16[192 * 1536];
static __device__ __half g_Whx16[320 * 1024];
static __device__ __half g_W2h[NCHUNK * EN * ECH];

// ---------------- helpers ----------------
__device__ __forceinline__ uint32_t smem_u32(const void* p) {
    uint32_t a;
    asm("{ .reg .u64 t; cvta.to.shared.u64 t, %1; cvt.u32.u64 %0, t; }" : "=r"(a) : "l"(p));
    return a;
}
#define SWZ128(off) ((off) ^ (((off) >> 3) & 0x70))

__device__ __forceinline__ void ldm4(uint32_t* r, uint32_t addr) {
    asm volatile("ldmatrix.sync.aligned.m8n8.x4.shared.b16 {%0,%1,%2,%3}, [%4];"
                 : "=r"(r[0]), "=r"(r[1]), "=r"(r[2]), "=r"(r[3]) : "r"(addr));
}
__device__ __forceinline__ void ldm2(uint32_t* r, uint32_t addr) {
    asm volatile("ldmatrix.sync.aligned.m8n8.x2.shared.b16 {%0,%1}, [%2];"
                 : "=r"(r[0]), "=r"(r[1]) : "r"(addr));
}
__device__ __forceinline__ void mma_f16(float* c, const uint32_t* a, const uint32_t* b) {
    asm volatile(
        "mma.sync.aligned.m16n8k16.row.col.f32.f16.f16.f32 "
        "{%0,%1,%2,%3}, {%4,%5,%6,%7}, {%8,%9}, {%0,%1,%2,%3};"
        : "+f"(c[0]), "+f"(c[1]), "+f"(c[2]), "+f"(c[3])
        : "r"(a[0]), "r"(a[1]), "r"(a[2]), "r"(a[3]), "r"(b[0]), "r"(b[1]));
}
__device__ __forceinline__ void cpasync16(uint32_t smem_addr, const void* gptr) {
    asm volatile("cp.async.cg.shared.global [%0], [%1], 16;"
                 :: "r"(smem_addr), "l"(gptr) : "memory");
}
#define CP_COMMIT() asm volatile("cp.async.commit_group;" ::: "memory")
#define CP_WAIT0()  asm volatile("cp.async.wait_group 0;" ::: "memory")

// ---------------- setup kernels ----------------
__global__ void k_init() {
    int i = blockIdx.x * blockDim.x + threadIdx.x;
    int st = gridDim.x * blockDim.x;
    for (int j = i; j < Nn * Hh; j += st) g_h[j] = 0.f;
    for (int j = i; j < Nn * 6; j += st) g_in6[j] = 0.f;
    for (int j = i; j < Nn; j += st) g_deg[j] = 0;
    for (int j = i; j < Nn * 3; j += st) g_zsum[j] = 0.f;
    if (i == 0) g_is32 = 0;
}

__global__ void k_detect(const int* __restrict__ w) {
    int i = blockIdx.x * blockDim.x + threadIdx.x;
    int st = gridDim.x * blockDim.x;
    for (int j = i; j < 2 * Ee; j += st) {
        if ((j & 1) && w[j] != 0) g_is32 = 1;
    }
}

__global__ void k_extract(const void* __restrict__ eiraw) {
    int e = blockIdx.x * blockDim.x + threadIdx.x;
    if (e >= Ee) return;
    if (g_is32) {
        const int* p = (const int*)eiraw;
        g_src[e] = p[e];
        g_dst[e] = p[Ee + e];
    } else {
        const long long* p = (const long long*)eiraw;
        g_src[e] = (int)p[e];
        g_dst[e] = (int)p[Ee + e];
    }
}

__global__ void k_hist() {
    int e = blockIdx.x * blockDim.x + threadIdx.x;
    if (e < Ee) atomicAdd(&g_deg[g_dst[e]], 1);
}

__global__ void k_cnt() {
    int n = blockIdx.x * blockDim.x + threadIdx.x;
    if (n < Nn) {
        float c = fmaxf((float)g_deg[n], 1.f);
        g_cntf[n] = c;
        g_invcnt[n] = 1.f / c;
    }
}

__global__ void k_scan() {
    __shared__ int part[512];
    const int tid = threadIdx.x;
    const int per = (Nn + 511) / 512;
    int start = tid * per;
    int s = 0;
    for (int j = 0; j < per; j++) {
        int idx = start + j;
        if (idx < Nn) s += g_deg[idx];
    }
    part[tid] = s;
    __syncthreads();
    if (tid == 0) {
        int acc = 0;
        for (int i = 0; i < 512; i++) { int v = part[i]; part[i] = acc; acc += v; }
    }
    __syncthreads();
    int acc = part[tid];
    for (int j = 0; j < per; j++) {
        int idx = start + j;
        if (idx < Nn) { g_base[idx] = acc; g_cur[idx] = acc; acc += g_deg[idx]; }
    }
    if (tid == 511) g_base[Nn] = acc;
}

__global__ void k_place(const float* __restrict__ z) {
    int e = blockIdx.x * blockDim.x + threadIdx.x;
    if (e >= Ee) return;
    int d = g_dst[e];
    int pos = atomicAdd(&g_cur[d], 1);
    g_srcs[pos] = g_src[e];
    g_dsts[pos] = d;
    float z1 = z[(size_t)e * 4 + 1];
    float z2 = z[(size_t)e * 4 + 2];
    float z3 = z[(size_t)e * 4 + 3];
    g_zs[pos] = z1;
    g_zs[Ee + pos] = z2;
    g_zs[2 * Ee + pos] = z3;
    atomicAdd(&g_zsum[d * 3 + 0], z1);
    atomicAdd(&g_zsum[d * 3 + 1], z2);
    atomicAdd(&g_zsum[d * 3 + 2], z3);
}

// macc init: cols<256 -> b2 base term; cols>=256 -> 0
__global__ void k_b2base(const float* __restrict__ b2) {
    int idx = blockIdx.x * blockDim.x + threadIdx.x;
    if (idx >= Nn * MST) return;
    int n = idx / MST, c = idx % MST;
    if (c < 256) {
        float v = g_zsum[n * 3 + 0] * b2[c]
                + g_zsum[n * 3 + 1] * b2[256 + c]
                + g_zsum[n * 3 + 2] * b2[512 + c];
        g_mbase[n * 256 + c] = v;
        g_macc[idx] = v;
    } else {
        g_macc[idx] = 0.f;
    }
}

__global__ void k_pack_w1(const float* __restrict__ W1, const float* __restrict__ b1) {
    int idx = blockIdx.x * blockDim.x + threadIdx.x;
    if (idx < 192 * 1536) {
        int row = idx / 1536, c = idx % 1536;
        float v;
        if (c < 768) {
            int k = c >> 8, j = c & 255;
            v = W1[k * 98304 + row * 256 + j];
        } else {
            int c2 = c - 768;
            int k = c2 >> 8, j = c2 & 255;
            v = W1[k * 98304 + (row + 192) * 256 + j];
        }
        g_W1ab[idx] = v;
    }
    if (idx < 1536) g_biasab[idx] = (idx < 768) ? b1[idx] : 0.f;
}

// fh-GEMM B: [256 k][256 n]: n<192 Wf, 192-197 Wo, else 0. bias [bf|bo|0]
__global__ void k_build_wfx(const float* __restrict__ Wf, const float* __restrict__ Wo,
                            const float* __restrict__ bf, const float* __restrict__ bo) {
    int idx = blockIdx.x * blockDim.x + threadIdx.x;
    if (idx >= 256 * 256) return;
    int k = idx >> 8, n = idx & 255;
    float v = 0.f;
    if (n < 192) v = Wf[k * 192 + n];
    else if (n < 198) v = Wo[k * 6 + (n - 192)];
    g_WfXF[idx] = v;
    if (idx < 256) {
        float b = 0.f;
        if (idx < 192) b = bf[idx];
        else if (idx < 198) b = bo[idx - 192];
        g_biasWfX[idx] = b;
    }
}

// gh-GEMM B: [320 k][1024 n] = [r~ | z~ | nh | nx]
// k<256 = hidden (Whh); k 256-261 = inputs (Wih); rest 0.
__global__ void k_build_whx(const float* __restrict__ Whh, const float* __restrict__ Wih,
                            const float* __restrict__ bhh, const float* __restrict__ bih) {
    int idx = blockIdx.x * blockDim.x + threadIdx.x;
    if (idx >= 320 * 1024) return;
    int k = idx >> 10, j = idx & 1023;
    float v = 0.f;
    if (k < 256) {
        if (j < 768) v = Whh[j * 256 + k];     // gates r(0-255) z(256-511) n(512-767)
    } else if (k < 262) {
        int q = k - 256;
        if (j < 512) v = Wih[j * 6 + q];       // r,z input parts
        else if (j >= 768) v = Wih[(j - 256) * 6 + q];  // nx = Wih rows 512-767
    }
    g_WhxF[idx] = v;
    if (idx < 1024) {
        float b;
        if (idx < 512) b = bhh[idx] + bih[idx];
        else if (idx < 768) b = bhh[idx];      // nh bias
        else b = bih[idx - 256];               // nx bias = bih[512..767]
        g_biasWhx[idx] = b;
    }
}

__global__ void k_pack_b16(const float* __restrict__ src, __half* __restrict__ dst,
                           int Kd, int Nd) {
    int idx = blockIdx.x * blockDim.x + threadIdx.x;
    if (idx >= Kd * Nd) return;
    int k = idx / Nd, n = idx % Nd;
    int kc = k >> 6, kk = k & 63, nb = n >> 6, nn = n & 63;
    int tile = kc * (Nd >> 6) + nb;
    uint32_t off = SWZ128((uint32_t)(nn * 128 + kk * 2));
    dst[(size_t)tile * 4096 + off / 2] = __float2half_rn(src[idx]);
}

__global__ void k_pack_w2(const float* __restrict__ W2) {
    int idx = blockIdx.x * blockDim.x + threadIdx.x;
    if (idx >= NCHUNK * EN * ECH) return;
    int chunk = idx / (EN * ECH);
    int rem = idx % (EN * ECH);
    int n = rem / ECH, k = rem % ECH;
    float w = W2[(size_t)(chunk * ECH + k) * 256 + n];
    uint32_t off = SWZ128((uint32_t)(n * 128 + k * 2));
    g_W2h[(size_t)chunk * (EN * ECH) + off / 2] = __float2half_rn(w);
}

// ---------------- unified fp16 tensor-core GEMM (pipelined) ----------------
// If mu_out != null: cols<192 -> fp16 C (stride c_stride), cols 192-197 -> fp32 mu_out, rest skip.
__global__ void __launch_bounds__(256) k_gemm16(
    const void* __restrict__ A, const __half* __restrict__ Bpk,
    const float* __restrict__ bias, void* __restrict__ C,
    int M, int Kd, int Nd, const float* __restrict__ rowscale,
    int relu, int a_fp16, int c_fp16, int c_stride, float* __restrict__ mu_out)
{
    extern __shared__ char gsm[];
    const uint32_t smem_base = smem_u32(gsm);

    const int tid = threadIdx.x;
    const int wid = tid >> 5;
    const int lane = tid & 31;
    const int m0 = blockIdx.x * 128;
    const int nblk = blockIdx.y;
    const int n0 = nblk * 64;
    const int nblocks = Nd >> 6;
    const int niter = Kd >> 6;

    const int m0w = (wid >> 1) * 32;
    const int n0w = (wid & 1) * 32;

    float c[2][4][4];
#pragma unroll
    for (int mi = 0; mi < 2; mi++)
#pragma unroll
        for (int ni = 0; ni < 4; ni++)
#pragma unroll
            for (int r = 0; r < 4; r++) c[mi][ni][r] = 0.f;

    const int arow = tid >> 1;
    const int acol0 = (tid & 1) * 32;
    const int am = m0 + arow;
    const bool av = am < M;
    float rs = 1.f;
    if (rowscale && av) rs = rowscale[am];
    const uint32_t a_sw[4] = {
        SWZ128((uint32_t)(arow * 128 + acol0 * 2)),
        SWZ128((uint32_t)(arow * 128 + (acol0 + 8) * 2)),
        SWZ128((uint32_t)(arow * 128 + (acol0 + 16) * 2)),
        SWZ128((uint32_t)(arow * 128 + (acol0 + 24) * 2))
    };

    const int a_r = lane & 15;
    const uint32_t a_kb = (uint32_t)((lane >> 4) << 4);
    const int b_r = lane & 7;
    const uint32_t b_kb = (uint32_t)(((lane >> 3) & 1) << 4);

    const uint32_t aoff[2] = {GM_A0, GM_A1};
    const uint32_t boff[2] = {GM_B0, GM_B1};

    auto stageA = [&](int kt, int bi) {
        if (a_fp16) {
            const __half* Ah = (const __half*)A + (size_t)am * Kd + kt;
#pragma unroll
            for (int i = 0; i < 4; i++) {
                uint4 v = make_uint4(0u, 0u, 0u, 0u);
                if (av) v = *(const uint4*)(Ah + acol0 + i * 8);
                *(uint4*)(gsm + aoff[bi] + a_sw[i]) = v;
            }
        } else {
            const float* Af = (const float*)A + (size_t)am * Kd + kt;
#pragma unroll
            for (int i = 0; i < 4; i++) {
                uint4 v = make_uint4(0u, 0u, 0u, 0u);
                if (av) {
                    float4 f0 = *(const float4*)(Af + acol0 + i * 8);
                    float4 f1 = *(const float4*)(Af + acol0 + i * 8 + 4);
                    __half2 h0 = __floats2half2_rn(f0.x * rs, f0.y * rs);
                    __half2 h1 = __floats2half2_rn(f0.z * rs, f0.w * rs);
                    __half2 h2 = __floats2half2_rn(f1.x * rs, f1.y * rs);
                    __half2 h3 = __floats2half2_rn(f1.z * rs, f1.w * rs);
                    v.x = *(uint32_t*)&h0; v.y = *(uint32_t*)&h1;
                    v.z = *(uint32_t*)&h2; v.w = *(uint32_t*)&h3;
                }
                *(uint4*)(gsm + aoff[bi] + a_sw[i]) = v;
            }
        }
    };
    auto issueB = [&](int kt, int bi) {
        const char* gB = (const char*)(Bpk + (size_t)((kt >> 6) * nblocks + nblk) * 4096);
        int j0 = tid * 16;
        cpasync16(smem_base + boff[bi] + (uint32_t)j0, gB + j0);
        cpasync16(smem_base + boff[bi] + (uint32_t)(j0 + 4096), gB + j0 + 4096);
        CP_COMMIT();
    };

    issueB(0, 0);
    stageA(0, 0);
    CP_WAIT0();
    __syncthreads();

    for (int it = 0; it < niter; it++) {
        const int cur = it & 1;
        const int nxt = cur ^ 1;
        if (it + 1 < niter) issueB((it + 1) << 6, nxt);

#pragma unroll
        for (int ks = 0; ks < 4; ks++) {
            uint32_t a[2][4];
#pragma unroll
            for (int mi = 0; mi < 2; mi++) {
                uint32_t row = (uint32_t)(m0w + mi * 16 + a_r);
                ldm4(a[mi], smem_base + aoff[cur] + SWZ128(row * 128 + (uint32_t)(ks * 32) + a_kb));
            }
#pragma unroll
            for (int ni = 0; ni < 4; ni++) {
                uint32_t nrow = (uint32_t)(n0w + ni * 8 + b_r);
                uint32_t b[2];
                ldm2(b, smem_base + boff[cur] + SWZ128(nrow * 128 + (uint32_t)(ks * 32) + b_kb));
                mma_f16(c[0][ni], a[0], b);
                mma_f16(c[1][ni], a[1], b);
            }
        }

        if (it + 1 < niter) {
            stageA((it + 1) << 6, nxt);
            CP_WAIT0();
        }
        __syncthreads();
    }

#pragma unroll
    for (int mi = 0; mi < 2; mi++) {
        int r0 = m0 + m0w + mi * 16 + (lane >> 2);
        int r1 = r0 + 8;
#pragma unroll
        for (int ni = 0; ni < 4; ni++) {
            int col = n0 + n0w + ni * 8 + 2 * (lane & 3);
            float bv0 = bias[col], bv1 = bias[col + 1];
            float* cc = c[mi][ni];
            float o00 = cc[0] + bv0, o01 = cc[1] + bv1;
            float o10 = cc[2] + bv0, o11 = cc[3] + bv1;
            if (relu) {
                o00 = fmaxf(o00, 0.f); o01 = fmaxf(o01, 0.f);
                o10 = fmaxf(o10, 0.f); o11 = fmaxf(o11, 0.f);
            }
            if (mu_out) {
                if (col < 192) {
                    __half* Ch = (__half*)C;
                    if (r0 < M) {
                        __half2 h = __floats2half2_rn(o00, o01);
                        *(__half2*)(Ch + (size_t)r0 * c_stride + col) = h;
                    }
                    if (r1 < M) {
                        __half2 h = __floats2half2_rn(o10, o11);
                        *(__half2*)(Ch + (size_t)r1 * c_stride + col) = h;
                    }
                } else if (col < 198) {
                    int q = col - 192;
                    if (r0 < M) *(float2*)(mu_out + (size_t)r0 * 6 + q) = make_float2(o00, o01);
                    if (r1 < M) *(float2*)(mu_out + (size_t)r1 * 6 + q) = make_float2(o10, o11);
                }
            } else if (c_fp16) {
                __half* Ch = (__half*)C;
                if (r0 < M) {
                    __half2 h = __floats2half2_rn(o00, o01);
                    *(__half2*)(Ch + (size_t)r0 * c_stride + col) = h;
                }
                if (r1 < M) {
                    __half2 h = __floats2half2_rn(o10, o11);
                    *(__half2*)(Ch + (size_t)r1 * c_stride + col) = h;
                }
            } else {
                float* Cf = (float*)C;
                if (r0 < M) *(float2*)(Cf + (size_t)r0 * c_stride + col) = make_float2(o00, o01);
                if (r1 < M) *(float2*)(Cf + (size_t)r1 * c_stride + col) = make_float2(o10, o11);
            }
        }
    }
}

// ---------------- edge GEMM: 64x256, 2 CTAs/SM, warp tile 64x32 ----------------
__global__ void __launch_bounds__(256, 2)
k_edge_mma()
{
    extern __shared__ char dsm[];
    __shared__ int sdst[EM];
    __shared__ float sz[3][EM];

    const uint32_t smem_base = smem_u32(dsm);
    const int tid = threadIdx.x;
    const int wid = tid >> 5;
    const int lane = tid & 31;
    const int e0 = blockIdx.x * EM;

    if (tid < EM) {
        sdst[tid] = g_dsts[e0 + tid];
        sz[0][tid] = g_zs[e0 + tid];
        sz[1][tid] = g_zs[Ee + e0 + tid];
        sz[2][tid] = g_zs[2 * Ee + e0 + tid];
    }
    __syncthreads();

    const int n0w = wid * 32;        // each warp: all 64 rows x 32 cols

    float c[4][4][4];
#pragma unroll
    for (int mi = 0; mi < 4; mi++)
#pragma unroll
        for (int ni = 0; ni < 4; ni++)
#pragma unroll
            for (int r = 0; r < 4; r++) c[mi][ni][r] = 0.f;

    const int arow = tid >> 2;
    const int acol0 = (tid & 3) * 16;
    const int srow = g_srcs[e0 + arow];
    const __half* pd = g_AB16 + (size_t)sdst[arow] * 1536;
    const __half* ps = g_AB16 + (size_t)srow * 1536 + 768;
    const uint32_t a_sw0 = SWZ128((uint32_t)(arow * 128 + acol0 * 2));
    const uint32_t a_sw1 = SWZ128((uint32_t)(arow * 128 + (acol0 + 8) * 2));

    const int a_r = lane & 15;
    const uint32_t a_kb = (uint32_t)((lane >> 4) << 4);
    // B ldm4 lane mapping: tiles {n0..7:k0, n0..7:k1, n8..15:k0, n8..15:k1}
    const int b4_row = (lane & 7) + ((lane >> 4) << 3);
    const uint32_t b4_kb = (uint32_t)(((lane >> 3) & 1) << 4);

    const __half2 hzero = __float2half2_rn(0.f);
    const uint32_t aoff[2] = {SM_A0, SM_A1};
    const uint32_t boff[2] = {SM_B0, SM_B1};

    uint4 ra0, ra1, rb0, rb1;

    auto convStoreA = [&](int chunk, int bi) {
        __half2 zh = __float2half2_rn(sz[chunk >> 2][arow]);
        __half2 r0 = __hmax2(__hmul2(__hadd2(*(__half2*)&ra0.x, *(__half2*)&rb0.x), zh), hzero);
        __half2 r1 = __hmax2(__hmul2(__hadd2(*(__half2*)&ra0.y, *(__half2*)&rb0.y), zh), hzero);
        __half2 r2 = __hmax2(__hmul2(__hadd2(*(__half2*)&ra0.z, *(__half2*)&rb0.z), zh), hzero);
        __half2 r3 = __hmax2(__hmul2(__hadd2(*(__half2*)&ra0.w, *(__half2*)&rb0.w), zh), hzero);
        uint4 v;
        v.x = *(uint32_t*)&r0; v.y = *(uint32_t*)&r1;
        v.z = *(uint32_t*)&r2; v.w = *(uint32_t*)&r3;
        *(uint4*)(dsm + aoff[bi] + a_sw0) = v;
        r0 = __hmax2(__hmul2(__hadd2(*(__half2*)&ra1.x, *(__half2*)&rb1.x), zh), hzero);
        r1 = __hmax2(__hmul2(__hadd2(*(__half2*)&ra1.y, *(__half2*)&rb1.y), zh), hzero);
        r2 = __hmax2(__hmul2(__hadd2(*(__half2*)&ra1.z, *(__half2*)&rb1.z), zh), hzero);
        r3 = __hmax2(__hmul2(__hadd2(*(__half2*)&ra1.w, *(__half2*)&rb1.w), zh), hzero);
        v.x = *(uint32_t*)&r0; v.y = *(uint32_t*)&r1;
        v.z = *(uint32_t*)&r2; v.w = *(uint32_t*)&r3;
        *(uint4*)(dsm + aoff[bi] + a_sw1) = v;
    };
    auto loadA = [&](int chunk) {
        const int kc = chunk * ECH;
        ra0 = *(const uint4*)(pd + kc + acol0);
        ra1 = *(const uint4*)(pd + kc + acol0 + 8);
        rb0 = *(const uint4*)(ps + kc + acol0);
        rb1 = *(const uint4*)(ps + kc + acol0 + 8);
    };
    auto issueB = [&](int chunk, int bi) {
        const char* gB = (const char*)(g_W2h + (size_t)chunk * (EN * ECH));
#pragma unroll
        for (int i = 0; i < 8; i++) {
            int j = (tid + i * 256) * 16;
            cpasync16(smem_base + boff[bi] + (uint32_t)j, gB + j);
        }
        CP_COMMIT();
    };

    loadA(0);
    issueB(0, 0);
    convStoreA(0, 0);
    CP_WAIT0();
    __syncthreads();

    for (int chunk = 0; chunk < NCHUNK; chunk++) {
        const int cur = chunk & 1;
        const int nxt = cur ^ 1;

        if (chunk < NCHUNK - 1) {
            loadA(chunk + 1);
            issueB(chunk + 1, nxt);
        }

#pragma unroll
        for (int ks = 0; ks < 4; ks++) {
            uint32_t a[4][4];
#pragma unroll
            for (int mi = 0; mi < 4; mi++) {
                uint32_t row = (uint32_t)(mi * 16 + a_r);
                ldm4(a[mi], smem_base + aoff[cur] + SWZ128(row * 128 + (uint32_t)(ks * 32) + a_kb));
            }
#pragma unroll
            for (int nig = 0; nig < 2; nig++) {
                uint32_t rr[4];
                uint32_t nrow = (uint32_t)(n0w + nig * 16 + b4_row);
                ldm4(rr, smem_base + boff[cur] + SWZ128(nrow * 128 + (uint32_t)(ks * 32) + b4_kb));
#pragma unroll
                for (int mi = 0; mi < 4; mi++) {
                    mma_f16(c[mi][2 * nig], a[mi], &rr[0]);
                    mma_f16(c[mi][2 * nig + 1], a[mi], &rr[2]);
                }
            }
        }

        if (chunk < NCHUNK - 1) {
            convStoreA(chunk + 1, nxt);
            CP_WAIT0();
        }
        __syncthreads();
    }

    // ---- epilogue: fragments -> SMEM tile -> segmented reduce ----
    float* tile = (float*)dsm;
#pragma unroll
    for (int mi = 0; mi < 4; mi++) {
        int r0 = mi * 16 + (lane >> 2);
        int r1 = r0 + 8;
#pragma unroll
        for (int ni = 0; ni < 4; ni++) {
            int col = n0w + ni * 8 + 2 * (lane & 3);
            float* cc = c[mi][ni];
            *(float2*)&tile[r0 * TSTRIDE + col] = make_float2(cc[0], cc[1]);
            *(float2*)&tile[r1 * TSTRIDE + col] = make_float2(cc[2], cc[3]);
        }
    }
    __syncthreads();

    {
        const int col = tid;
        float acc = 0.f;
        int curn = sdst[0];
#pragma unroll 4
        for (int r = 0; r < EM; r++) {
            int d = sdst[r];
            float v = tile[r * TSTRIDE + col];
            if (d != curn) {
                atomicAdd(g_macc + (size_t)curn * MST + col, acc);
                acc = 0.f;
                curn = d;
            }
            acc += v;
        }
        atomicAdd(g_macc + (size_t)curn * MST + col, acc);
    }
}

// ---------------- mu finalize + inputs staging (runs after fh GEMM) ----------------
__global__ void k_mu(int t, const float* __restrict__ x, float* __restrict__ out) {
    int idx = blockIdx.x * blockDim.x + threadIdx.x;
    if (idx >= Nn * 6) return;
    int n = idx / 6, q = idx % 6;
    float mu = g_in6[idx] + g_fhmu[idx];       // mu(t-1) = inputs(t-1) + relu(h_t@Wo+bo)
    if (t > 0) out[(size_t)n * NFd + (t - 1) * 6 + q] = mu;
    float inp = (t < TTEACH) ? x[(size_t)n * NFd + t * 6 + q] : mu;
    g_in6[idx] = inp;
    g_macc[(size_t)n * MST + 256 + q] = inp * g_cntf[n];
}

// ---------------- GRU gates (pure elementwise) ----------------
__global__ void k_gru() {
    int idx = blockIdx.x * blockDim.x + threadIdx.x;
    if (idx >= Nn * Hh) return;
    int n = idx >> 8, i = idx & 255;
    float m = g_macc[(size_t)n * MST + i] * g_invcnt[n];
    const float* ghp = g_gh + (size_t)n * 1024;
    float gr = ghp[i], gz = ghp[256 + i], gnh = ghp[512 + i], gnx = ghp[768 + i];
    float r  = 1.f / (1.f + __expf(-gr));
    float zg = 1.f / (1.f + __expf(-gz));
    float arg = gnx + r * gnh;
    float nn = 1.f - 2.f / (__expf(2.f * arg) + 1.f);   // tanh
    float h = (1.f - zg) * nn + zg * m;
    g_h[idx] = h;
    g_macc[(size_t)n * MST + i] = g_mbase[idx];
}

// ---------------- launch ----------------
extern "C" void kernel_launch(void* const* d_in, const int* in_sizes, int n_in,
                              void* d_out, int out_size)
{
    const float* x   = (const float*)d_in[0];
    const void*  ei  = d_in[1];
    const float* z   = (const float*)d_in[2];
    const float* Wf  = (const float*)d_in[3];
    const float* bf  = (const float*)d_in[4];
    const float* W1  = (const float*)d_in[5];
    const float* b1  = (const float*)d_in[6];
    const float* W2  = (const float*)d_in[7];
    const float* b2  = (const float*)d_in[8];
    const float* Wih = (const float*)d_in[9];
    const float* bih = (const float*)d_in[10];
    const float* Whh = (const float*)d_in[11];
    const float* bhh = (const float*)d_in[12];
    const float* Wo  = (const float*)d_in[13];
    const float* bo  = (const float*)d_in[14];
    float* out = (float*)d_out;

    float *p_h, *p_macc, *p_gh, *p_W1ab, *p_biasab, *p_ic;
    float *p_WfXF, *p_biasWfX, *p_WhxF, *p_biasWhx, *p_fhmu;
    __half *p_fh16, *p_AB16, *p_WfX16, *p_W1ab16, *p_Whx16;
    cudaGetSymbolAddress((void**)&p_h, g_h);
    cudaGetSymbolAddress((void**)&p_macc, g_macc);
    cudaGetSymbolAddress((void**)&p_gh, g_gh);
    cudaGetSymbolAddress((void**)&p_W1ab, g_W1ab);
    cudaGetSymbolAddress((void**)&p_biasab, g_biasab);
    cudaGetSymbolAddress((void**)&p_ic, g_invcnt);
    cudaGetSymbolAddress((void**)&p_WfXF, g_WfXF);
    cudaGetSymbolAddress((void**)&p_biasWfX, g_biasWfX);
    cudaGetSymbolAddress((void**)&p_WhxF, g_WhxF);
    cudaGetSymbolAddress((void**)&p_biasWhx, g_biasWhx);
    cudaGetSymbolAddress((void**)&p_fhmu, g_fhmu);
    cudaGetSymbolAddress((void**)&p_fh16, g_fh16);
    cudaGetSymbolAddress((void**)&p_AB16, g_AB16);
    cudaGetSymbolAddress((void**)&p_WfX16, g_WfX16);
    cudaGetSymbolAddress((void**)&p_W1ab16, g_W1ab16);
    cudaGetSymbolAddress((void**)&p_Whx16, g_Whx16);

    static int smem_set = 0;
    if (!smem_set) {
        cudaFuncSetAttribute(k_edge_mma, cudaFuncAttributeMaxDynamicSharedMemorySize,
                             SM_EDGE_TOTAL);
        cudaFuncSetAttribute(k_gemm16, cudaFuncAttributeMaxDynamicSharedMemorySize,
                             SM_GEMM_TOTAL);
        smem_set = 1;
    }

    k_init<<<512, 256>>>();
    k_detect<<<512, 256>>>((const int*)ei);
    k_extract<<<(Ee + 255) / 256, 256>>>(ei);
    k_hist<<<(Ee + 255) / 256, 256>>>();
    k_cnt<<<(Nn + 255) / 256, 256>>>();
    k_scan<<<1, 512>>>();
    k_place<<<(Ee + 255) / 256, 256>>>(z);
    k_b2base<<<(Nn * MST + 255) / 256, 256>>>(b2);
    k_pack_w1<<<(192 * 1536 + 255) / 256, 256>>>(W1, b1);
    k_build_wfx<<<(256 * 256 + 255) / 256, 256>>>(Wf, Wo, bf, bo);
    k_build_whx<<<(320 * 1024 + 255) / 256, 256>>>(Whh, Wih, bhh, bih);
    k_pack_w2<<<(NCHUNK * EN * ECH + 255) / 256, 256>>>(W2);
    k_pack_b16<<<(256 * 256 + 255) / 256, 256>>>(p_WfXF, p_WfX16, 256, 256);
    k_pack_b16<<<(192 * 1536 + 255) / 256, 256>>>(p_W1ab, p_W1ab16, 192, 1536);
    k_pack_b16<<<(320 * 1024 + 255) / 256, 256>>>(p_WhxF, p_Whx16, 320, 1024);

    dim3 gfh((Nn + 127) / 128, 4);        // Nd=256
    dim3 gab((Nn + 127) / 128, 24);       // Nd=1536
    dim3 ggh((Nn + 127) / 128, 16);       // Nd=1024
    int  gedge = Ee / EM;                 // 2500
    int  gmu = (Nn * 6 + 255) / 256;
    int  ggru = (Nn * Hh + 255) / 256;

    for (int t = 0; t < Tt; t++) {
        // fhx = relu(h @ [Wf|Wo] + [bf|bo]) -> fh16 (cols<192) + fhmu (192-197)
        k_gemm16<<<gfh, 256, SM_GEMM_TOTAL>>>(p_h, p_WfX16, p_biasWfX, p_fh16,
                               Nn, 256, 256, nullptr, 1, 0, 1, 192, p_fhmu);
        // mu(t-1) finalize + inputs(t) staging
        k_mu<<<gmu, 256>>>(t, x, out);
        // AB16 = fh16 @ W1ab
        k_gemm16<<<gab, 256, SM_GEMM_TOTAL>>>(p_fh16, p_W1ab16, p_biasab, p_AB16,
                               Nn, 192, 1536, nullptr, 0, 1, 1, 1536, nullptr);
        // edge MLP2 + scatter
        k_edge_mma<<<gedge, 256, SM_EDGE_TOTAL>>>();
        // gh = [m | inputs] @ [Whh|Wih] -> [r~|z~|nh|nx]
        k_gemm16<<<ggh, 256, SM_GEMM_TOTAL>>>(p_macc, p_Whx16, p_biasWhx, p_gh,
                               Nn, 320, 1024, p_ic, 0, 0, 0, 1024, nullptr);
        // GRU gates
        k_gru<<<ggru, 256>>>();
    }
    // final mu(31) via one extra fh pass
    k_gemm16<<<gfh, 256, SM_GEMM_TOTAL>>>(p_h, p_WfX16, p_biasWfX, p_fh16,
                           Nn, 256, 256, nullptr, 1, 0, 1, 192, p_fhmu);
    k_mu<<<gmu, 256>>>(Tt, x, out);
}

// round 10
// speedup vs baseline: 5.1235x; 1.0065x over previous
#include <cuda_runtime.h>
#include <cuda_fp16.h>
#include <cstdint>

// ---------------- problem constants ----------------
#define Nn 10000
#define Ee 160000
#define Tt 32
#define Hh 256
#define NFd 192
#define TTEACH 24
#define MST 320            // macc row stride (256 msg + 6 inputs + pad)

// edge-GEMM tiling
#define EM 64
#define EN 256
#define EK 768
#define ECH 64
#define NCHUNK (EK/ECH)

#define SM_A0 0
#define SM_A1 8192
#define SM_B0 16384
#define SM_B1 49152
#define SM_EDGE_TOTAL 81920
#define TSTRIDE 258

// node GEMM smem
#define GM_A0 0
#define GM_A1 16384
#define GM_B0 32768
#define GM_B1 40960
#define SM_GEMM_TOTAL 49152

// ---------------- device scratch ----------------
static __device__ float  g_h[Nn * Hh];
static __device__ __half g_fh16[Nn * NFd];
static __device__ __half g_AB16[Nn * 1536];
static __device__ float  g_macc[Nn * MST];       // [msg 256 | inputs*cnt 6 | pad]
static __device__ float  g_mbase[Nn * Hh];
static __device__ float  g_invcnt[Nn];
static __device__ float  g_cntf[Nn];
static __device__ float  g_zsum[Nn * 3];
static __device__ float  g_in6[Nn * 6];
static __device__ int    g_deg[Nn];
static __device__ int    g_base[Nn + 1];
static __device__ int    g_cur[Nn];
static __device__ int    g_src[Ee];
static __device__ int    g_dst[Ee];
static __device__ int    g_srcs[Ee];
static __device__ int    g_dsts[Ee];
static __device__ float  g_zs[3 * Ee];
static __device__ int    g_is32;
// weight staging + fp16 packs
static __device__ float  g_W1ab[192 * 1536];
static __device__ float  g_biasab[1536];
static __device__ float  g_WfXF[256 * 256];
static __device__ float  g_biasWfX[256];
static __device__ float  g_WhxF[320 * 1024];
static __device__ float  g_biasWhx[1024];
static __device__ __half g_WfX16[256 * 256];
static __device__ __half g_W1ab16[192 * 1536];
static __device__ __half g_Whx16[320 * 1024];
static __device__ __half g_W2h[NCHUNK * EN * ECH];

// ---------------- helpers ----------------
__device__ __forceinline__ uint32_t smem_u32(const void* p) {
    uint32_t a;
    asm("{ .reg .u64 t; cvta.to.shared.u64 t, %1; cvt.u32.u64 %0, t; }" : "=r"(a) : "l"(p));
    return a;
}
#define SWZ128(off) ((off) ^ (((off) >> 3) & 0x70))

__device__ __forceinline__ void ldm4(uint32_t* r, uint32_t addr) {
    asm volatile("ldmatrix.sync.aligned.m8n8.x4.shared.b16 {%0,%1,%2,%3}, [%4];"
                 : "=r"(r[0]), "=r"(r[1]), "=r"(r[2]), "=r"(r[3]) : "r"(addr));
}
__device__ __forceinline__ void ldm2(uint32_t* r, uint32_t addr) {
    asm volatile("ldmatrix.sync.aligned.m8n8.x2.shared.b16 {%0,%1}, [%2];"
                 : "=r"(r[0]), "=r"(r[1]) : "r"(addr));
}
__device__ __forceinline__ void mma_f16(float* c, const uint32_t* a, const uint32_t* b) {
    asm volatile(
        "mma.sync.aligned.m16n8k16.row.col.f32.f16.f16.f32 "
        "{%0,%1,%2,%3}, {%4,%5,%6,%7}, {%8,%9}, {%0,%1,%2,%3};"
        : "+f"(c[0]), "+f"(c[1]), "+f"(c[2]), "+f"(c[3])
        : "r"(a[0]), "r"(a[1]), "r"(a[2]), "r"(a[3]), "r"(b[0]), "r"(b[1]));
}
__device__ __forceinline__ void cpasync16(uint32_t smem_addr, const void* gptr) {
    asm volatile("cp.async.cg.shared.global [%0], [%1], 16;"
                 :: "r"(smem_addr), "l"(gptr) : "memory");
}
#define CP_COMMIT() asm volatile("cp.async.commit_group;" ::: "memory")
#define CP_WAIT0()  asm volatile("cp.async.wait_group 0;" ::: "memory")

// ---------------- setup kernels ----------------
__global__ void k_init() {
    int i = blockIdx.x * blockDim.x + threadIdx.x;
    int st = gridDim.x * blockDim.x;
    for (int j = i; j < Nn * Hh; j += st) g_h[j] = 0.f;
    for (int j = i; j < Nn * 6; j += st) g_in6[j] = 0.f;
    for (int j = i; j < Nn; j += st) g_deg[j] = 0;
    for (int j = i; j < Nn * 3; j += st) g_zsum[j] = 0.f;
    if (i == 0) g_is32 = 0;
}

__global__ void k_detect(const int* __restrict__ w) {
    int i = blockIdx.x * blockDim.x + threadIdx.x;
    int st = gridDim.x * blockDim.x;
    for (int j = i; j < 2 * Ee; j += st) {
        if ((j & 1) && w[j] != 0) g_is32 = 1;
    }
}

__global__ void k_extract(const void* __restrict__ eiraw) {
    int e = blockIdx.x * blockDim.x + threadIdx.x;
    if (e >= Ee) return;
    if (g_is32) {
        const int* p = (const int*)eiraw;
        g_src[e] = p[e];
        g_dst[e] = p[Ee + e];
    } else {
        const long long* p = (const long long*)eiraw;
        g_src[e] = (int)p[e];
        g_dst[e] = (int)p[Ee + e];
    }
}

__global__ void k_hist() {
    int e = blockIdx.x * blockDim.x + threadIdx.x;
    if (e < Ee) atomicAdd(&g_deg[g_dst[e]], 1);
}

__global__ void k_cnt() {
    int n = blockIdx.x * blockDim.x + threadIdx.x;
    if (n < Nn) {
        float c = fmaxf((float)g_deg[n], 1.f);
        g_cntf[n] = c;
        g_invcnt[n] = 1.f / c;
    }
}

__global__ void k_scan() {
    __shared__ int part[512];
    const int tid = threadIdx.x;
    const int per = (Nn + 511) / 512;
    int start = tid * per;
    int s = 0;
    for (int j = 0; j < per; j++) {
        int idx = start + j;
        if (idx < Nn) s += g_deg[idx];
    }
    part[tid] = s;
    __syncthreads();
    if (tid == 0) {
        int acc = 0;
        for (int i = 0; i < 512; i++) { int v = part[i]; part[i] = acc; acc += v; }
    }
    __syncthreads();
    int acc = part[tid];
    for (int j = 0; j < per; j++) {
        int idx = start + j;
        if (idx < Nn) { g_base[idx] = acc; g_cur[idx] = acc; acc += g_deg[idx]; }
    }
    if (tid == 511) g_base[Nn] = acc;
}

__global__ void k_place(const float* __restrict__ z) {
    int e = blockIdx.x * blockDim.x + threadIdx.x;
    if (e >= Ee) return;
    int d = g_dst[e];
    int pos = atomicAdd(&g_cur[d], 1);
    g_srcs[pos] = g_src[e];
    g_dsts[pos] = d;
    float z1 = z[(size_t)e * 4 + 1];
    float z2 = z[(size_t)e * 4 + 2];
    float z3 = z[(size_t)e * 4 + 3];
    g_zs[pos] = z1;
    g_zs[Ee + pos] = z2;
    g_zs[2 * Ee + pos] = z3;
    atomicAdd(&g_zsum[d * 3 + 0], z1);
    atomicAdd(&g_zsum[d * 3 + 1], z2);
    atomicAdd(&g_zsum[d * 3 + 2], z3);
}

__global__ void k_b2base(const float* __restrict__ b2) {
    int idx = blockIdx.x * blockDim.x + threadIdx.x;
    if (idx >= Nn * MST) return;
    int n = idx / MST, c = idx % MST;
    if (c < 256) {
        float v = g_zsum[n * 3 + 0] * b2[c]
                + g_zsum[n * 3 + 1] * b2[256 + c]
                + g_zsum[n * 3 + 2] * b2[512 + c];
        g_mbase[n * 256 + c] = v;
        g_macc[idx] = v;
    } else {
        g_macc[idx] = 0.f;
    }
}

__global__ void k_pack_w1(const float* __restrict__ W1, const float* __restrict__ b1) {
    int idx = blockIdx.x * blockDim.x + threadIdx.x;
    if (idx < 192 * 1536) {
        int row = idx / 1536, c = idx % 1536;
        float v;
        if (c < 768) {
            int k = c >> 8, j = c & 255;
            v = W1[k * 98304 + row * 256 + j];
        } else {
            int c2 = c - 768;
            int k = c2 >> 8, j = c2 & 255;
            v = W1[k * 98304 + (row + 192) * 256 + j];
        }
        g_W1ab[idx] = v;
    }
    if (idx < 1536) g_biasab[idx] = (idx < 768) ? b1[idx] : 0.f;
}

// fh-GEMM B: [256 k][256 n]: n<192 Wf, 192-197 Wo, else 0. bias [bf|bo|0]
__global__ void k_build_wfx(const float* __restrict__ Wf, const float* __restrict__ Wo,
                            const float* __restrict__ bf, const float* __restrict__ bo) {
    int idx = blockIdx.x * blockDim.x + threadIdx.x;
    if (idx >= 256 * 256) return;
    int k = idx >> 8, n = idx & 255;
    float v = 0.f;
    if (n < 192) v = Wf[k * 192 + n];
    else if (n < 198) v = Wo[k * 6 + (n - 192)];
    g_WfXF[idx] = v;
    if (idx < 256) {
        float b = 0.f;
        if (idx < 192) b = bf[idx];
        else if (idx < 198) b = bo[idx - 192];
        g_biasWfX[idx] = b;
    }
}

// gh-GEMM B: [320 k][1024 n], gate-interleaved per 64-col block:
// col j: g=j>>6, rem=j&63, gate=rem>>4, ii=(g<<4)+(rem&15)
// gate 0=r, 1=z, 2=nh, 3=nx. k<256: Whh rows; k 256-261: Wih rows; rest 0.
__global__ void k_build_whx(const float* __restrict__ Whh, const float* __restrict__ Wih,
                            const float* __restrict__ bhh, const float* __restrict__ bih) {
    int idx = blockIdx.x * blockDim.x + threadIdx.x;
    if (idx >= 320 * 1024) return;
    int k = idx >> 10, j = idx & 1023;
    int g = j >> 6, rem = j & 63, gate = rem >> 4;
    int ii = (g << 4) + (rem & 15);
    float v = 0.f;
    if (k < 256) {
        if (gate == 0) v = Whh[ii * 256 + k];
        else if (gate == 1) v = Whh[(256 + ii) * 256 + k];
        else if (gate == 2) v = Whh[(512 + ii) * 256 + k];
    } else if (k < 262) {
        int q = k - 256;
        if (gate == 0) v = Wih[ii * 6 + q];
        else if (gate == 1) v = Wih[(256 + ii) * 6 + q];
        else if (gate == 3) v = Wih[(512 + ii) * 6 + q];
    }
    g_WhxF[idx] = v;
    if (idx < 1024) {
        int gg = idx >> 6, rr = idx & 63, gt = rr >> 4;
        int i2 = (gg << 4) + (rr & 15);
        float b;
        if (gt == 0) b = bhh[i2] + bih[i2];
        else if (gt == 1) b = bhh[256 + i2] + bih[256 + i2];
        else if (gt == 2) b = bhh[512 + i2];
        else b = bih[512 + i2];
        g_biasWhx[idx] = b;
    }
}

__global__ void k_pack_b16(const float* __restrict__ src, __half* __restrict__ dst,
                           int Kd, int Nd) {
    int idx = blockIdx.x * blockDim.x + threadIdx.x;
    if (idx >= Kd * Nd) return;
    int k = idx / Nd, n = idx % Nd;
    int kc = k >> 6, kk = k & 63, nb = n >> 6, nn = n & 63;
    int tile = kc * (Nd >> 6) + nb;
    uint32_t off = SWZ128((uint32_t)(nn * 128 + kk * 2));
    dst[(size_t)tile * 4096 + off / 2] = __float2half_rn(src[idx]);
}

__global__ void k_pack_w2(const float* __restrict__ W2) {
    int idx = blockIdx.x * blockDim.x + threadIdx.x;
    if (idx >= NCHUNK * EN * ECH) return;
    int chunk = idx / (EN * ECH);
    int rem = idx % (EN * ECH);
    int n = rem / ECH, k = rem % ECH;
    float w = W2[(size_t)(chunk * ECH + k) * 256 + n];
    uint32_t off = SWZ128((uint32_t)(n * 128 + k * 2));
    g_W2h[(size_t)chunk * (EN * ECH) + off / 2] = __float2half_rn(w);
}

// ---------------- unified fp16 tensor-core GEMM (pipelined, fused epilogues) ----
// mode 0: plain fp16 C (stride c_stride)
// mode 1: fh fused: cols<192 -> fp16 C; cols 192-197 -> mu finalize + input staging;
//         ALL cols: macc <- mbase reset
// mode 2: gh fused: fragments -> smem tile -> GRU gate math -> g_h (no C write)
__global__ void __launch_bounds__(256) k_gemm16(
    const void* __restrict__ A, const __half* __restrict__ Bpk,
    const float* __restrict__ bias, void* __restrict__ C,
    int M, int Kd, int Nd, const float* __restrict__ rowscale,
    int relu, int a_fp16, int mode, int c_stride,
    int t, const float* __restrict__ x, float* __restrict__ out)
{
    extern __shared__ char gsm[];
    const uint32_t smem_base = smem_u32(gsm);

    const int tid = threadIdx.x;
    const int wid = tid >> 5;
    const int lane = tid & 31;
    const int m0 = blockIdx.x * 128;
    const int nblk = blockIdx.y;
    const int n0 = nblk * 64;
    const int nblocks = Nd >> 6;
    const int niter = Kd >> 6;

    const int m0w = (wid >> 1) * 32;
    const int n0w = (wid & 1) * 32;

    float c[2][4][4];
#pragma unroll
    for (int mi = 0; mi < 2; mi++)
#pragma unroll
        for (int ni = 0; ni < 4; ni++)
#pragma unroll
            for (int r = 0; r < 4; r++) c[mi][ni][r] = 0.f;

    const int arow = tid >> 1;
    const int acol0 = (tid & 1) * 32;
    const int am = m0 + arow;
    const bool av = am < M;
    float rs = 1.f;
    if (rowscale && av) rs = rowscale[am];
    const uint32_t a_sw[4] = {
        SWZ128((uint32_t)(arow * 128 + acol0 * 2)),
        SWZ128((uint32_t)(arow * 128 + (acol0 + 8) * 2)),
        SWZ128((uint32_t)(arow * 128 + (acol0 + 16) * 2)),
        SWZ128((uint32_t)(arow * 128 + (acol0 + 24) * 2))
    };

    const int a_r = lane & 15;
    const uint32_t a_kb = (uint32_t)((lane >> 4) << 4);
    const int b_r = lane & 7;
    const uint32_t b_kb = (uint32_t)(((lane >> 3) & 1) << 4);

    const uint32_t aoff[2] = {GM_A0, GM_A1};
    const uint32_t boff[2] = {GM_B0, GM_B1};

    auto stageA = [&](int kt, int bi) {
        if (a_fp16) {
            const __half* Ah = (const __half*)A + (size_t)am * Kd + kt;
#pragma unroll
            for (int i = 0; i < 4; i++) {
                uint4 v = make_uint4(0u, 0u, 0u, 0u);
                if (av) v = *(const uint4*)(Ah + acol0 + i * 8);
                *(uint4*)(gsm + aoff[bi] + a_sw[i]) = v;
            }
        } else {
            const float* Af = (const float*)A + (size_t)am * Kd + kt;
#pragma unroll
            for (int i = 0; i < 4; i++) {
                uint4 v = make_uint4(0u, 0u, 0u, 0u);
                if (av) {
                    float4 f0 = *(const float4*)(Af + acol0 + i * 8);
                    float4 f1 = *(const float4*)(Af + acol0 + i * 8 + 4);
                    __half2 h0 = __floats2half2_rn(f0.x * rs, f0.y * rs);
                    __half2 h1 = __floats2half2_rn(f0.z * rs, f0.w * rs);
                    __half2 h2 = __floats2half2_rn(f1.x * rs, f1.y * rs);
                    __half2 h3 = __floats2half2_rn(f1.z * rs, f1.w * rs);
                    v.x = *(uint32_t*)&h0; v.y = *(uint32_t*)&h1;
                    v.z = *(uint32_t*)&h2; v.w = *(uint32_t*)&h3;
                }
                *(uint4*)(gsm + aoff[bi] + a_sw[i]) = v;
            }
        }
    };
    auto issueB = [&](int kt, int bi) {
        const char* gB = (const char*)(Bpk + (size_t)((kt >> 6) * nblocks + nblk) * 4096);
        int j0 = tid * 16;
        cpasync16(smem_base + boff[bi] + (uint32_t)j0, gB + j0);
        cpasync16(smem_base + boff[bi] + (uint32_t)(j0 + 4096), gB + j0 + 4096);
        CP_COMMIT();
    };

    issueB(0, 0);
    stageA(0, 0);
    CP_WAIT0();
    __syncthreads();

    for (int it = 0; it < niter; it++) {
        const int cur = it & 1;
        const int nxt = cur ^ 1;
        if (it + 1 < niter) issueB((it + 1) << 6, nxt);

#pragma unroll
        for (int ks = 0; ks < 4; ks++) {
            uint32_t a[2][4];
#pragma unroll
            for (int mi = 0; mi < 2; mi++) {
                uint32_t row = (uint32_t)(m0w + mi * 16 + a_r);
                ldm4(a[mi], smem_base + aoff[cur] + SWZ128(row * 128 + (uint32_t)(ks * 32) + a_kb));
            }
#pragma unroll
            for (int ni = 0; ni < 4; ni++) {
                uint32_t nrow = (uint32_t)(n0w + ni * 8 + b_r);
                uint32_t b[2];
                ldm2(b, smem_base + boff[cur] + SWZ128(nrow * 128 + (uint32_t)(ks * 32) + b_kb));
                mma_f16(c[0][ni], a[0], b);
                mma_f16(c[1][ni], a[1], b);
            }
        }

        if (it + 1 < niter) {
            stageA((it + 1) << 6, nxt);
            CP_WAIT0();
        }
        __syncthreads();
    }

    if (mode == 2) {
        // ---- fused GRU epilogue: fragments+bias -> smem tile -> gate math ----
        float* tile = (float*)gsm;   // 128 x 68
#pragma unroll
        for (int mi = 0; mi < 2; mi++) {
            int lr0 = m0w + mi * 16 + (lane >> 2);
            int lr1 = lr0 + 8;
#pragma unroll
            for (int ni = 0; ni < 4; ni++) {
                int col = n0w + ni * 8 + 2 * (lane & 3);
                float bv0 = bias[n0 + col], bv1 = bias[n0 + col + 1];
                float* cc = c[mi][ni];
                tile[lr0 * 68 + col] = cc[0] + bv0;
                tile[lr0 * 68 + col + 1] = cc[1] + bv1;
                tile[lr1 * 68 + col] = cc[2] + bv0;
                tile[lr1 * 68 + col + 1] = cc[3] + bv1;
            }
        }
        __syncthreads();
#pragma unroll
        for (int u = 0; u < 8; u++) {
            int unit = tid + u * 256;
            int row = unit >> 4, iloc = unit & 15;
            int gn = m0 + row;
            if (gn < M) {
                float gr  = tile[row * 68 + iloc];
                float gz  = tile[row * 68 + 16 + iloc];
                float gnh = tile[row * 68 + 32 + iloc];
                float gnx = tile[row * 68 + 48 + iloc];
                int hcol = nblk * 16 + iloc;
                float ic = rowscale[gn];
                float m = g_macc[(size_t)gn * MST + hcol] * ic;
                float r  = 1.f / (1.f + __expf(-gr));
                float zg = 1.f / (1.f + __expf(-gz));
                float arg = gnx + r * gnh;
                float nn = 1.f - 2.f / (__expf(2.f * arg) + 1.f);
                g_h[(size_t)gn * 256 + hcol] = (1.f - zg) * nn + zg * m;
            }
        }
        return;
    }

#pragma unroll
    for (int mi = 0; mi < 2; mi++) {
        int r0 = m0 + m0w + mi * 16 + (lane >> 2);
        int r1 = r0 + 8;
#pragma unroll
        for (int ni = 0; ni < 4; ni++) {
            int col = n0 + n0w + ni * 8 + 2 * (lane & 3);
            float bv0 = bias[col], bv1 = bias[col + 1];
            float* cc = c[mi][ni];
            float o00 = cc[0] + bv0, o01 = cc[1] + bv1;
            float o10 = cc[2] + bv0, o11 = cc[3] + bv1;
            if (relu) {
                o00 = fmaxf(o00, 0.f); o01 = fmaxf(o01, 0.f);
                o10 = fmaxf(o10, 0.f); o11 = fmaxf(o11, 0.f);
            }
            if (mode == 1) {
                // macc <- mbase reset (cols all < 256)
                if (r0 < M)
                    *(float2*)(g_macc + (size_t)r0 * MST + col) =
                        *(const float2*)(g_mbase + (size_t)r0 * 256 + col);
                if (r1 < M)
                    *(float2*)(g_macc + (size_t)r1 * MST + col) =
                        *(const float2*)(g_mbase + (size_t)r1 * 256 + col);
                if (col < 192) {
                    __half* Ch = (__half*)C;
                    if (r0 < M) {
                        __half2 h = __floats2half2_rn(o00, o01);
                        *(__half2*)(Ch + (size_t)r0 * c_stride + col) = h;
                    }
                    if (r1 < M) {
                        __half2 h = __floats2half2_rn(o10, o11);
                        *(__half2*)(Ch + (size_t)r1 * c_stride + col) = h;
                    }
                } else if (col < 198) {
                    int q = col - 192;
#pragma unroll
                    for (int half = 0; half < 2; half++) {
                        int rr = half ? r1 : r0;
                        float v0 = half ? o10 : o00;
                        float v1 = half ? o11 : o01;
                        if (rr < M) {
                            float mu0 = g_in6[rr * 6 + q] + v0;
                            float mu1 = g_in6[rr * 6 + q + 1] + v1;
                            if (t > 0) {
                                out[(size_t)rr * NFd + (t - 1) * 6 + q] = mu0;
                                out[(size_t)rr * NFd + (t - 1) * 6 + q + 1] = mu1;
                            }
                            float i0 = (t < TTEACH) ? x[(size_t)rr * NFd + t * 6 + q] : mu0;
                            float i1 = (t < TTEACH) ? x[(size_t)rr * NFd + t * 6 + q + 1] : mu1;
                            g_in6[rr * 6 + q] = i0;
                            g_in6[rr * 6 + q + 1] = i1;
                            float cf = g_cntf[rr];
                            g_macc[(size_t)rr * MST + 256 + q] = i0 * cf;
                            g_macc[(size_t)rr * MST + 256 + q + 1] = i1 * cf;
                        }
                    }
                }
            } else {
                __half* Ch = (__half*)C;
                if (r0 < M) {
                    __half2 h = __floats2half2_rn(o00, o01);
                    *(__half2*)(Ch + (size_t)r0 * c_stride + col) = h;
                }
                if (r1 < M) {
                    __half2 h = __floats2half2_rn(o10, o11);
                    *(__half2*)(Ch + (size_t)r1 * c_stride + col) = h;
                }
            }
        }
    }
}

// ---------------- edge GEMM: 64x256, 2 CTAs/SM, warp tile 64x32 ----------------
__global__ void __launch_bounds__(256, 2)
k_edge_mma()
{
    extern __shared__ char dsm[];
    __shared__ int sdst[EM];
    __shared__ float sz[3][EM];

    const uint32_t smem_base = smem_u32(dsm);
    const int tid = threadIdx.x;
    const int wid = tid >> 5;
    const int lane = tid & 31;
    const int e0 = blockIdx.x * EM;

    if (tid < EM) {
        sdst[tid] = g_dsts[e0 + tid];
        sz[0][tid] = g_zs[e0 + tid];
        sz[1][tid] = g_zs[Ee + e0 + tid];
        sz[2][tid] = g_zs[2 * Ee + e0 + tid];
    }
    __syncthreads();

    const int n0w = wid * 32;

    float c[4][4][4];
#pragma unroll
    for (int mi = 0; mi < 4; mi++)
#pragma unroll
        for (int ni = 0; ni < 4; ni++)
#pragma unroll
            for (int r = 0; r < 4; r++) c[mi][ni][r] = 0.f;

    const int arow = tid >> 2;
    const int acol0 = (tid & 3) * 16;
    const int srow = g_srcs[e0 + arow];
    const __half* pd = g_AB16 + (size_t)sdst[arow] * 1536;
    const __half* ps = g_AB16 + (size_t)srow * 1536 + 768;
    const uint32_t a_sw0 = SWZ128((uint32_t)(arow * 128 + acol0 * 2));
    const uint32_t a_sw1 = SWZ128((uint32_t)(arow * 128 + (acol0 + 8) * 2));

    const int a_r = lane & 15;
    const uint32_t a_kb = (uint32_t)((lane >> 4) << 4);
    const int b4_row = (lane & 7) + ((lane >> 4) << 3);
    const uint32_t b4_kb = (uint32_t)(((lane >> 3) & 1) << 4);

    const __half2 hzero = __float2half2_rn(0.f);
    const uint32_t aoff[2] = {SM_A0, SM_A1};
    const uint32_t boff[2] = {SM_B0, SM_B1};

    uint4 ra0, ra1, rb0, rb1;

    auto convStoreA = [&](int chunk, int bi) {
        __half2 zh = __float2half2_rn(sz[chunk >> 2][arow]);
        __half2 r0 = __hmax2(__hmul2(__hadd2(*(__half2*)&ra0.x, *(__half2*)&rb0.x), zh), hzero);
        __half2 r1 = __hmax2(__hmul2(__hadd2(*(__half2*)&ra0.y, *(__half2*)&rb0.y), zh), hzero);
        __half2 r2 = __hmax2(__hmul2(__hadd2(*(__half2*)&ra0.z, *(__half2*)&rb0.z), zh), hzero);
        __half2 r3 = __hmax2(__hmul2(__hadd2(*(__half2*)&ra0.w, *(__half2*)&rb0.w), zh), hzero);
        uint4 v;
        v.x = *(uint32_t*)&r0; v.y = *(uint32_t*)&r1;
        v.z = *(uint32_t*)&r2; v.w = *(uint32_t*)&r3;
        *(uint4*)(dsm + aoff[bi] + a_sw0) = v;
        r0 = __hmax2(__hmul2(__hadd2(*(__half2*)&ra1.x, *(__half2*)&rb1.x), zh), hzero);
        r1 = __hmax2(__hmul2(__hadd2(*(__half2*)&ra1.y, *(__half2*)&rb1.y), zh), hzero);
        r2 = __hmax2(__hmul2(__hadd2(*(__half2*)&ra1.z, *(__half2*)&rb1.z), zh), hzero);
        r3 = __hmax2(__hmul2(__hadd2(*(__half2*)&ra1.w, *(__half2*)&rb1.w), zh), hzero);
        v.x = *(uint32_t*)&r0; v.y = *(uint32_t*)&r1;
        v.z = *(uint32_t*)&r2; v.w = *(uint32_t*)&r3;
        *(uint4*)(dsm + aoff[bi] + a_sw1) = v;
    };
    auto loadA = [&](int chunk) {
        const int kc = chunk * ECH;
        ra0 = *(const uint4*)(pd + kc + acol0);
        ra1 = *(const uint4*)(pd + kc + acol0 + 8);
        rb0 = *(const uint4*)(ps + kc + acol0);
        rb1 = *(const uint4*)(ps + kc + acol0 + 8);
    };
    auto issueB = [&](int chunk, int bi) {
        const char* gB = (const char*)(g_W2h + (size_t)chunk * (EN * ECH));
#pragma unroll
        for (int i = 0; i < 8; i++) {
            int j = (tid + i * 256) * 16;
            cpasync16(smem_base + boff[bi] + (uint32_t)j, gB + j);
        }
        CP_COMMIT();
    };

    loadA(0);
    issueB(0, 0);
    convStoreA(0, 0);
    CP_WAIT0();
    __syncthreads();

    for (int chunk = 0; chunk < NCHUNK; chunk++) {
        const int cur = chunk & 1;
        const int nxt = cur ^ 1;

        if (chunk < NCHUNK - 1) {
            loadA(chunk + 1);
            issueB(chunk + 1, nxt);
        }

#pragma unroll
        for (int ks = 0; ks < 4; ks++) {
            uint32_t a[4][4];
#pragma unroll
            for (int mi = 0; mi < 4; mi++) {
                uint32_t row = (uint32_t)(mi * 16 + a_r);
                ldm4(a[mi], smem_base + aoff[cur] + SWZ128(row * 128 + (uint32_t)(ks * 32) + a_kb));
            }
#pragma unroll
            for (int nig = 0; nig < 2; nig++) {
                uint32_t rr[4];
                uint32_t nrow = (uint32_t)(n0w + nig * 16 + b4_row);
                ldm4(rr, smem_base + boff[cur] + SWZ128(nrow * 128 + (uint32_t)(ks * 32) + b4_kb));
#pragma unroll
                for (int mi = 0; mi < 4; mi++) {
                    mma_f16(c[mi][2 * nig], a[mi], &rr[0]);
                    mma_f16(c[mi][2 * nig + 1], a[mi], &rr[2]);
                }
            }
        }

        if (chunk < NCHUNK - 1) {
            convStoreA(chunk + 1, nxt);
            CP_WAIT0();
        }
        __syncthreads();
    }

    // ---- epilogue: fragments -> SMEM tile -> segmented reduce ----
    float* tile = (float*)dsm;
#pragma unroll
    for (int mi = 0; mi < 4; mi++) {
        int r0 = mi * 16 + (lane >> 2);
        int r1 = r0 + 8;
#pragma unroll
        for (int ni = 0; ni < 4; ni++) {
            int col = n0w + ni * 8 + 2 * (lane & 3);
            float* cc = c[mi][ni];
            *(float2*)&tile[r0 * TSTRIDE + col] = make_float2(cc[0], cc[1]);
            *(float2*)&tile[r1 * TSTRIDE + col] = make_float2(cc[2], cc[3]);
        }
    }
    __syncthreads();

    {
        const int col = tid;
        float acc = 0.f;
        int curn = sdst[0];
#pragma unroll 4
        for (int r = 0; r < EM; r++) {
            int d = sdst[r];
            float v = tile[r * TSTRIDE + col];
            if (d != curn) {
                atomicAdd(g_macc + (size_t)curn * MST + col, acc);
                acc = 0.f;
                curn = d;
            }
            acc += v;
        }
        atomicAdd(g_macc + (size_t)curn * MST + col, acc);
    }
}

// ---------------- launch ----------------
extern "C" void kernel_launch(void* const* d_in, const int* in_sizes, int n_in,
                              void* d_out, int out_size)
{
    const float* x   = (const float*)d_in[0];
    const void*  ei  = d_in[1];
    const float* z   = (const float*)d_in[2];
    const float* Wf  = (const float*)d_in[3];
    const float* bf  = (const float*)d_in[4];
    const float* W1  = (const float*)d_in[5];
    const float* b1  = (const float*)d_in[6];
    const float* W2  = (const float*)d_in[7];
    const float* b2  = (const float*)d_in[8];
    const float* Wih = (const float*)d_in[9];
    const float* bih = (const float*)d_in[10];
    const float* Whh = (const float*)d_in[11];
    const float* bhh = (const float*)d_in[12];
    const float* Wo  = (const float*)d_in[13];
    const float* bo  = (const float*)d_in[14];
    float* out = (float*)d_out;

    float *p_h, *p_macc, *p_W1ab, *p_biasab, *p_ic;
    float *p_WfXF, *p_biasWfX, *p_WhxF, *p_biasWhx;
    __half *p_fh16, *p_AB16, *p_WfX16, *p_W1ab16, *p_Whx16;
    cudaGetSymbolAddress((void**)&p_h, g_h);
    cudaGetSymbolAddress((void**)&p_macc, g_macc);
    cudaGetSymbolAddress((void**)&p_W1ab, g_W1ab);
    cudaGetSymbolAddress((void**)&p_biasab, g_biasab);
    cudaGetSymbolAddress((void**)&p_ic, g_invcnt);
    cudaGetSymbolAddress((void**)&p_WfXF, g_WfXF);
    cudaGetSymbolAddress((void**)&p_biasWfX, g_biasWfX);
    cudaGetSymbolAddress((void**)&p_WhxF, g_WhxF);
    cudaGetSymbolAddress((void**)&p_biasWhx, g_biasWhx);
    cudaGetSymbolAddress((void**)&p_fh16, g_fh16);
    cudaGetSymbolAddress((void**)&p_AB16, g_AB16);
    cudaGetSymbolAddress((void**)&p_WfX16, g_WfX16);
    cudaGetSymbolAddress((void**)&p_W1ab16, g_W1ab16);
    cudaGetSymbolAddress((void**)&p_Whx16, g_Whx16);

    static int smem_set = 0;
    if (!smem_set) {
        cudaFuncSetAttribute(k_edge_mma, cudaFuncAttributeMaxDynamicSharedMemorySize,
                             SM_EDGE_TOTAL);
        cudaFuncSetAttribute(k_gemm16, cudaFuncAttributeMaxDynamicSharedMemorySize,
                             SM_GEMM_TOTAL);
        smem_set = 1;
    }

    k_init<<<512, 256>>>();
    k_detect<<<512, 256>>>((const int*)ei);
    k_extract<<<(Ee + 255) / 256, 256>>>(ei);
    k_hist<<<(Ee + 255) / 256, 256>>>();
    k_cnt<<<(Nn + 255) / 256, 256>>>();
    k_scan<<<1, 512>>>();
    k_place<<<(Ee + 255) / 256, 256>>>(z);
    k_b2base<<<(Nn * MST + 255) / 256, 256>>>(b2);
    k_pack_w1<<<(192 * 1536 + 255) / 256, 256>>>(W1, b1);
    k_build_wfx<<<(256 * 256 + 255) / 256, 256>>>(Wf, Wo, bf, bo);
    k_build_whx<<<(320 * 1024 + 255) / 256, 256>>>(Whh, Wih, bhh, bih);
    k_pack_w2<<<(NCHUNK * EN * ECH + 255) / 256, 256>>>(W2);
    k_pack_b16<<<(256 * 256 + 255) / 256, 256>>>(p_WfXF, p_WfX16, 256, 256);
    k_pack_b16<<<(192 * 1536 + 255) / 256, 256>>>(p_W1ab, p_W1ab16, 192, 1536);
    k_pack_b16<<<(320 * 1024 + 255) / 256, 256>>>(p_WhxF, p_Whx16, 320, 1024);

    dim3 gfh((Nn + 127) / 128, 4);        // Nd=256
    dim3 gab((Nn + 127) / 128, 24);       // Nd=1536
    dim3 ggh((Nn + 127) / 128, 16);       // Nd=1024
    int  gedge = Ee / EM;                 // 2500

    for (int t = 0; t < Tt; t++) {
        // fh fused: fh16 + mu(t-1) + inputs(t) staging + macc<-mbase reset
        k_gemm16<<<gfh, 256, SM_GEMM_TOTAL>>>(p_h, p_WfX16, p_biasWfX, p_fh16,
                               Nn, 256, 256, nullptr, 1, 0, 1, 192, t, x, out);
        // AB16 = fh16 @ W1ab
        k_gemm16<<<gab, 256, SM_GEMM_TOTAL>>>(p_fh16, p_W1ab16, p_biasab, p_AB16,
                               Nn, 192, 1536, nullptr, 0, 1, 0, 1536, 0, nullptr, nullptr);
        // edge MLP2 + scatter (adds into macc)
        k_edge_mma<<<gedge, 256, SM_EDGE_TOTAL>>>();
        // gh fused: [m|inputs] @ [Whh|Wih] -> GRU gates -> g_h
        k_gemm16<<<ggh, 256, SM_GEMM_TOTAL>>>(p_macc, p_Whx16, p_biasWhx, nullptr,
                               Nn, 320, 1024, p_ic, 0, 0, 2, 0, 0, nullptr, nullptr);
    }
    // tail: emit mu(31)
    k_gemm16<<<gfh, 256, SM_GEMM_TOTAL>>>(p_h, p_WfX16, p_biasWfX, p_fh16,
                           Nn, 256, 256, nullptr, 1, 0, 1, 192, Tt, x, out);
}